// round 5
// baseline (speedup 1.0000x reference)
#include <cuda_runtime.h>
#include <cstdint>
#include <math.h>

#define BB 8
#define TT 2048
#define EE 512
#define CC 128
#define NCH 16
#define EPS_D 1e-3f
#define QSCALE 0.044194173824159216f   // 512^-0.5

// ---------------- device scratch ----------------
__device__ float g_Q[BB * TT * EE];
__device__ float g_K[BB * TT * EE];
__device__ float g_V[BB * TT * EE];
__device__ float g_A[BB * TT * EE];
__device__ float g_P[BB * NCH * CC * CC];
__device__ float g_RS[BB * TT];
__device__ float g_DI[BB * TT];
__device__ float g_ZC[BB * NCH * EE];
__device__ float g_SP[(size_t)BB * NCH * EE * EE];  // per-chunk K^T V partials
__device__ float g_SC[(size_t)BB * NCH * EE * EE];  // exclusive prefix of g_SP

// ---------------- tf32 helpers ----------------
__device__ __forceinline__ float tf32r(float v) {
    uint32_t u;
    asm("cvt.rna.tf32.f32 %0, %1;" : "=r"(u) : "f"(v));
    return __uint_as_float(u);
}

__device__ __forceinline__ void mma8(float* c, const uint32_t* a, const uint32_t* b) {
    asm("mma.sync.aligned.m16n8k8.row.col.f32.tf32.tf32.f32 "
        "{%0,%1,%2,%3}, {%4,%5,%6,%7}, {%8,%9}, {%0,%1,%2,%3};"
        : "+f"(c[0]), "+f"(c[1]), "+f"(c[2]), "+f"(c[3])
        : "r"(a[0]), "r"(a[1]), "r"(a[2]), "r"(a[3]), "r"(b[0]), "r"(b[1]));
}

// swizzled smem word address for tile [k(16)][t(128)]
__device__ __forceinline__ int swz(int k, int t) {
    return (k << 7) + (t ^ ((((k & 3) ^ ((k >> 2) & 3))) << 3));
}

// ---- staging: element (t, k) = g[k*ld + t]  (lanes along t -> coalesced) ----
__device__ __forceinline__ void stage_T(const float* __restrict__ g, int ld,
                                        float* __restrict__ hi, float* __restrict__ lo,
                                        int tid) {
#pragma unroll
    for (int i = 0; i < 8; i++) {
        int li = tid + i * 256;
        int t = li & 127, k = li >> 7;
        float v = g[(size_t)k * ld + t];
        float h = tf32r(v);
        int a = swz(k, t);
        hi[a] = h;
        lo[a] = v - h;
    }
}

// ---- staging: element (n, k) = g[n*ld + k]  (float4 along k) ----
__device__ __forceinline__ void stage_N(const float* __restrict__ g, int ld,
                                        float* __restrict__ hi, float* __restrict__ lo,
                                        int tid) {
    int q = tid & 3, n = tid >> 2;
#pragma unroll
    for (int i = 0; i < 2; i++) {
        int nn = n + i * 64;
        const float4 v4 = *(const float4*)(g + (size_t)nn * ld + q * 4);
        float vv[4] = {v4.x, v4.y, v4.z, v4.w};
#pragma unroll
        for (int j = 0; j < 4; j++) {
            int k = q * 4 + j;
            float v = vv[j];
            float h = tf32r(v);
            int a = swz(k, nn);
            hi[a] = h;
            lo[a] = v - h;
        }
    }
}

// ---- per-ktile compute: 3xTF32 (hh + hl + lh) ----
__device__ __forceinline__ void compute_ktile(
    float (&acc)[4][4][4],
    const float* __restrict__ Ah, const float* __restrict__ Al,
    const float* __restrict__ Bh, const float* __restrict__ Bl,
    const int* rm, const int* rb, const int (&off)[2][2], const int (&xr)[2][2])
{
#pragma unroll
    for (int ks = 0; ks < 2; ks++) {
        uint32_t bh[4][2], bl[4][2];
#pragma unroll
        for (int in = 0; in < 4; in++) {
            int a0 = off[ks][0] + (rb[in] ^ xr[ks][0]);
            int a1 = off[ks][1] + (rb[in] ^ xr[ks][1]);
            bh[in][0] = __float_as_uint(Bh[a0]);
            bh[in][1] = __float_as_uint(Bh[a1]);
            bl[in][0] = __float_as_uint(Bl[a0]);
            bl[in][1] = __float_as_uint(Bl[a1]);
        }
        uint32_t af[4][4];
#pragma unroll
        for (int im = 0; im < 4; im++)
#pragma unroll
            for (int r = 0; r < 4; r++) {
                int d = r & 1, gg = r >> 1;
                af[im][r] = __float_as_uint(Ah[off[ks][gg] + (rm[im * 2 + d] ^ xr[ks][gg])]);
            }
#pragma unroll
        for (int im = 0; im < 4; im++)
#pragma unroll
            for (int in = 0; in < 4; in++) mma8(acc[im][in], af[im], bh[in]);
#pragma unroll
        for (int im = 0; im < 4; im++)
#pragma unroll
            for (int in = 0; in < 4; in++) mma8(acc[im][in], af[im], bl[in]);
#pragma unroll
        for (int im = 0; im < 4; im++)
#pragma unroll
            for (int r = 0; r < 4; r++) {
                int d = r & 1, gg = r >> 1;
                af[im][r] = __float_as_uint(Al[off[ks][gg] + (rm[im * 2 + d] ^ xr[ks][gg])]);
            }
#pragma unroll
        for (int im = 0; im < 4; im++)
#pragma unroll
            for (int in = 0; in < 4; in++) mma8(acc[im][in], af[im], bh[in]);
    }
}

#define GEMM_PRE()                                                        \
    const int tid = threadIdx.x;                                          \
    const int lane = tid & 31, wid = tid >> 5;                            \
    const int warpM = (wid & 1) * 64, warpN = (wid >> 1) * 32;            \
    const int lq = lane & 3, lr = lane >> 2;                              \
    int rm[8], rb[4], off[2][2], xr[2][2];                                \
    _Pragma("unroll") for (int im = 0; im < 4; im++)                      \
        _Pragma("unroll") for (int d = 0; d < 2; d++)                     \
            rm[im * 2 + d] = warpM + im * 16 + d * 8 + lr;                \
    _Pragma("unroll") for (int in = 0; in < 4; in++)                      \
        rb[in] = warpN + in * 8 + lr;                                     \
    _Pragma("unroll") for (int ks = 0; ks < 2; ks++)                      \
        _Pragma("unroll") for (int gg = 0; gg < 2; gg++) {                \
            off[ks][gg] = (ks * 8 + gg * 4 + lq) << 7;                    \
            xr[ks][gg] = ((lq ^ (ks * 2 + gg)) & 3) << 3;                 \
        }                                                                 \
    float acc[4][4][4];                                                   \
    _Pragma("unroll") for (int im = 0; im < 4; im++)                      \
        _Pragma("unroll") for (int in = 0; in < 4; in++)                  \
            _Pragma("unroll") for (int r = 0; r < 4; r++)                 \
                acc[im][in][r] = 0.f;                                     \
    __shared__ float sAh[2048], sAl[2048], sBh[2048], sBl[2048];

// ---------------------------------------------------------------------------
// Projections: out[b,t,o] = xt @ w^T + b;  mode 0:Q raw  1:K exp  2:V*toep
// ---------------------------------------------------------------------------
__global__ __launch_bounds__(256, 2) void proj_mma(
    const float* __restrict__ x, const float* __restrict__ w,
    const float* __restrict__ bias, const float* __restrict__ toep, int mode)
{
    float* out = (mode == 0) ? g_Q : (mode == 1) ? g_K : g_V;
    const int b = blockIdx.z, t0 = blockIdx.x * 128, o0 = blockIdx.y * 128;
    GEMM_PRE();
    const float* xb = x + (size_t)b * EE * TT + t0;
    const float* wb = w + (size_t)o0 * EE;
    for (int k0 = 0; k0 < EE; k0 += 16) {
        stage_T(xb + (size_t)k0 * TT, TT, sAh, sAl, tid);
        stage_N(wb + k0, EE, sBh, sBl, tid);
        __syncthreads();
        compute_ktile(acc, sAh, sAl, sBh, sBl, rm, rb, off, xr);
        __syncthreads();
    }
#pragma unroll
    for (int im = 0; im < 4; im++)
#pragma unroll
        for (int d = 0; d < 2; d++) {
            int r = rm[im * 2 + d];
            int t = t0 + r;
            float tw = (mode == 2) ? toep[t] : 1.f;
            float* orow = out + ((size_t)b * TT + t) * EE + o0;
#pragma unroll
            for (int in = 0; in < 4; in++) {
                int cc = warpN + in * 8 + lq * 2;
                float v0 = acc[im][in][d * 2 + 0] + bias[o0 + cc];
                float v1 = acc[im][in][d * 2 + 1] + bias[o0 + cc + 1];
                if (mode == 1) { v0 = expf(v0); v1 = expf(v1); }
                else if (mode == 2) { v0 *= tw; v1 *= tw; }
                *(float2*)&orow[cc] = make_float2(v0, v1);
            }
        }
}

// ---------------------------------------------------------------------------
// Row softmax over E for Q (* E^-0.5)
// ---------------------------------------------------------------------------
__global__ __launch_bounds__(256) void softmax_q()
{
    size_t row = blockIdx.x;
    float* r = g_Q + row * EE;
    int tid = threadIdx.x;
    float v0 = r[tid], v1 = r[tid + 256];
    __shared__ float red[256];
    red[tid] = fmaxf(v0, v1);
    __syncthreads();
    for (int s = 128; s > 0; s >>= 1) {
        if (tid < s) red[tid] = fmaxf(red[tid], red[tid + s]);
        __syncthreads();
    }
    float m = red[0];
    __syncthreads();
    float e0 = expf(v0 - m), e1 = expf(v1 - m);
    red[tid] = e0 + e1;
    __syncthreads();
    for (int s = 128; s > 0; s >>= 1) {
        if (tid < s) red[tid] += red[tid + s];
        __syncthreads();
    }
    float scale = QSCALE / red[0];
    r[tid] = e0 * scale;
    r[tid + 256] = e1 * scale;
}

// ---------------------------------------------------------------------------
// P = mask(Q_c K_c^T) + row sums.  one CTA per (chunk, batch)
// ---------------------------------------------------------------------------
__global__ __launch_bounds__(256, 2) void p_mma()
{
    const int cI = blockIdx.x, b = blockIdx.y;
    GEMM_PRE();
    __shared__ float srs[CC];
    if (tid < CC) srs[tid] = 0.f;
    const float* Qc = g_Q + ((size_t)b * TT + (size_t)cI * CC) * EE;
    const float* Kc = g_K + ((size_t)b * TT + (size_t)cI * CC) * EE;
    for (int k0 = 0; k0 < EE; k0 += 16) {
        stage_N(Qc + k0, EE, sAh, sAl, tid);
        stage_N(Kc + k0, EE, sBh, sBl, tid);
        __syncthreads();
        compute_ktile(acc, sAh, sAl, sBh, sBl, rm, rb, off, xr);
        __syncthreads();
    }
    float* Pc = g_P + (size_t)(b * NCH + cI) * CC * CC;
#pragma unroll
    for (int im = 0; im < 4; im++)
#pragma unroll
        for (int d = 0; d < 2; d++) {
            int r = rm[im * 2 + d];
            float rsum = 0.f;
#pragma unroll
            for (int in = 0; in < 4; in++) {
                int cc = warpN + in * 8 + lq * 2;
                float v0 = (cc <= r)     ? acc[im][in][d * 2 + 0] : 0.f;
                float v1 = (cc + 1 <= r) ? acc[im][in][d * 2 + 1] : 0.f;
                rsum += v0 + v1;
                *(float2*)&Pc[(size_t)r * CC + cc] = make_float2(v0, v1);
            }
            atomicAdd(&srs[r], rsum);
        }
    __syncthreads();
    if (tid < CC) g_RS[(size_t)b * TT + (size_t)cI * CC + tid] = srs[tid];
}

// ---------------------------------------------------------------------------
// Per-chunk K^T V partials:  g_SP[b,c] = K_c^T V_c   (512x512, K=128)
// ---------------------------------------------------------------------------
__global__ __launch_bounds__(256, 2) void ktv_mma()
{
    const int tile = blockIdx.x, cI = blockIdx.y, b = blockIdx.z;
    const int tm = (tile & 3) * 128, tn = (tile >> 2) * 128;
    GEMM_PRE();
    const float* Kc = g_K + ((size_t)b * TT + (size_t)cI * CC) * EE + tm;
    const float* Vc = g_V + ((size_t)b * TT + (size_t)cI * CC) * EE + tn;
    for (int k0 = 0; k0 < CC; k0 += 16) {
        stage_T(Kc + (size_t)k0 * EE, EE, sAh, sAl, tid);
        stage_T(Vc + (size_t)k0 * EE, EE, sBh, sBl, tid);
        __syncthreads();
        compute_ktile(acc, sAh, sAl, sBh, sBl, rm, rb, off, xr);
        __syncthreads();
    }
    float* Sp = g_SP + ((size_t)(b * NCH + cI) * EE) * EE;
#pragma unroll
    for (int im = 0; im < 4; im++)
#pragma unroll
        for (int d = 0; d < 2; d++) {
            int r = tm + rm[im * 2 + d];
#pragma unroll
            for (int in = 0; in < 4; in++) {
                int cc = tn + warpN + in * 8 + lq * 2;
                *(float2*)&Sp[(size_t)r * EE + cc] =
                    make_float2(acc[im][in][d * 2 + 0], acc[im][in][d * 2 + 1]);
            }
        }
}

// ---------------------------------------------------------------------------
// Exclusive prefix over chunks:  g_SC[b,c] = sum_{c'<c} g_SP[b,c']
// ---------------------------------------------------------------------------
__global__ __launch_bounds__(256) void prefix_S()
{
    int gid = blockIdx.x * 256 + threadIdx.x;     // 524288 threads
    int b = gid >> 16;
    int p4 = gid & 65535;
    size_t base = ((size_t)b * NCH) * EE * EE + (size_t)p4 * 4;
    float4 run = make_float4(0.f, 0.f, 0.f, 0.f);
    for (int c = 0; c < NCH; c++) {
        size_t o = base + (size_t)c * EE * EE;
        *(float4*)(g_SC + o) = run;
        float4 s = *(const float4*)(g_SP + o);
        run.x += s.x; run.y += s.y; run.z += s.z; run.w += s.w;
    }
}

// ---------------------------------------------------------------------------
// z exclusive prefix:  g_ZC[b,c,e] = sum_{c'<c} colsum(K_{c'})[e]
// ---------------------------------------------------------------------------
__global__ __launch_bounds__(512) void z_prefix()
{
    int b = blockIdx.x, e = threadIdx.x;
    float run = 0.f;
    for (int c = 0; c < NCH; c++) {
        g_ZC[((size_t)b * NCH + c) * EE + e] = run;
        const float* kb = g_K + ((size_t)b * TT + (size_t)c * CC) * EE + e;
#pragma unroll 8
        for (int s = 0; s < CC; s++) run += kb[(size_t)s * EE];
    }
}

// ---------------------------------------------------------------------------
// Denominator:  g_DI[row] = 1 / max(q . z_prev + rowsum(P), eps)
// ---------------------------------------------------------------------------
__global__ __launch_bounds__(256) void dinv_kernel()
{
    int w = blockIdx.x * 8 + (threadIdx.x >> 5);   // global row
    int lane = threadIdx.x & 31;
    int b = w >> 11, t = w & 2047, c = t >> 7;
    const float* q = g_Q + (size_t)w * EE;
    const float* z = g_ZC + ((size_t)b * NCH + c) * EE;
    float s = 0.f;
#pragma unroll
    for (int i = 0; i < 16; i++) s += q[lane + 32 * i] * z[lane + 32 * i];
#pragma unroll
    for (int o = 16; o > 0; o >>= 1) s += __shfl_xor_sync(0xffffffffu, s, o);
    if (lane == 0) {
        float d = fmaxf(s + g_RS[w], EPS_D);
        g_DI[w] = 1.f / d;
    }
}

// ---------------------------------------------------------------------------
// O = (Q_c @ S_cum + P_c @ V_c) * dinv    one CTA per (ntile, chunk, batch)
// ---------------------------------------------------------------------------
__global__ __launch_bounds__(256, 2) void qspv_mma()
{
    const int n0 = blockIdx.x * 128, cI = blockIdx.y, b = blockIdx.z;
    GEMM_PRE();
    if (cI > 0) {
        const float* Qc = g_Q + ((size_t)b * TT + (size_t)cI * CC) * EE;
        const float* Sc = g_SC + ((size_t)(b * NCH + cI) * EE) * EE + n0;
        for (int k0 = 0; k0 < EE; k0 += 16) {
            stage_N(Qc + k0, EE, sAh, sAl, tid);
            stage_T(Sc + (size_t)k0 * EE, EE, sBh, sBl, tid);
            __syncthreads();
            compute_ktile(acc, sAh, sAl, sBh, sBl, rm, rb, off, xr);
            __syncthreads();
        }
    }
    const float* Pc = g_P + (size_t)(b * NCH + cI) * CC * CC;
    const float* Vc = g_V + ((size_t)b * TT + (size_t)cI * CC) * EE + n0;
    for (int k0 = 0; k0 < CC; k0 += 16) {
        stage_N(Pc + k0, CC, sAh, sAl, tid);
        stage_T(Vc + (size_t)k0 * EE, EE, sBh, sBl, tid);
        __syncthreads();
        compute_ktile(acc, sAh, sAl, sBh, sBl, rm, rb, off, xr);
        __syncthreads();
    }
#pragma unroll
    for (int im = 0; im < 4; im++)
#pragma unroll
        for (int d = 0; d < 2; d++) {
            int r = rm[im * 2 + d];
            size_t row = (size_t)b * TT + (size_t)cI * CC + r;
            float di = g_DI[row];
            float* arow = g_A + row * EE + n0;
#pragma unroll
            for (int in = 0; in < 4; in++) {
                int cc = warpN + in * 8 + lq * 2;
                *(float2*)&arow[cc] = make_float2(acc[im][in][d * 2 + 0] * di,
                                                  acc[im][in][d * 2 + 1] * di);
            }
        }
}

// ---------------------------------------------------------------------------
// Output projection:  out = A @ o_w^T + o_b
// ---------------------------------------------------------------------------
__global__ __launch_bounds__(256, 2) void out_mma(
    const float* __restrict__ ow, const float* __restrict__ ob,
    float* __restrict__ out)
{
    const int b = blockIdx.z, t0 = blockIdx.x * 128, o0 = blockIdx.y * 128;
    GEMM_PRE();
    const float* Ab = g_A + ((size_t)b * TT + t0) * EE;
    const float* wb = ow + (size_t)o0 * EE;
    for (int k0 = 0; k0 < EE; k0 += 16) {
        stage_N(Ab + k0, EE, sAh, sAl, tid);
        stage_N(wb + k0, EE, sBh, sBl, tid);
        __syncthreads();
        compute_ktile(acc, sAh, sAl, sBh, sBl, rm, rb, off, xr);
        __syncthreads();
    }
#pragma unroll
    for (int im = 0; im < 4; im++)
#pragma unroll
        for (int d = 0; d < 2; d++) {
            int t = t0 + rm[im * 2 + d];
            float* orow = out + ((size_t)b * TT + t) * EE + o0;
#pragma unroll
            for (int in = 0; in < 4; in++) {
                int cc = warpN + in * 8 + lq * 2;
                *(float2*)&orow[cc] = make_float2(acc[im][in][d * 2 + 0] + ob[o0 + cc],
                                                  acc[im][in][d * 2 + 1] + ob[o0 + cc + 1]);
            }
        }
}

// ---------------------------------------------------------------------------
extern "C" void kernel_launch(void* const* d_in, const int* in_sizes, int n_in,
                              void* d_out, int out_size)
{
    (void)in_sizes; (void)n_in; (void)out_size;
    const float* x    = (const float*)d_in[0];
    const float* toep = (const float*)d_in[1];
    const float* q_w  = (const float*)d_in[2];
    const float* q_b  = (const float*)d_in[3];
    const float* k_w  = (const float*)d_in[4];
    const float* k_b  = (const float*)d_in[5];
    const float* v_w  = (const float*)d_in[6];
    const float* v_b  = (const float*)d_in[7];
    const float* o_w  = (const float*)d_in[8];
    const float* o_b  = (const float*)d_in[9];
    float* out = (float*)d_out;

    dim3 gProj(TT / 128, EE / 128, BB);            // (16,4,8)
    proj_mma<<<gProj, 256>>>(x, q_w, q_b, toep, 0);
    proj_mma<<<gProj, 256>>>(x, k_w, k_b, toep, 1);
    proj_mma<<<gProj, 256>>>(x, v_w, v_b, toep, 2);
    softmax_q<<<BB * TT, 256>>>();
    p_mma<<<dim3(NCH, BB), 256>>>();
    z_prefix<<<BB, 512>>>();
    ktv_mma<<<dim3(16, NCH, BB), 256>>>();
    prefix_S<<<2048, 256>>>();
    dinv_kernel<<<BB * TT / 8, 256>>>();
    qspv_mma<<<dim3(EE / 128, NCH, BB), 256>>>();
    out_mma<<<gProj, 256>>>(o_w, o_b, out);
}

// round 7
// speedup vs baseline: 1.8922x; 1.8922x over previous
#include <cuda_runtime.h>
#include <cuda_fp16.h>
#include <cstdint>
#include <math.h>

// ===========================================================================
// LinearAttentionToeplitz — fp16x2 error-compensated mma.sync pipeline.
// All GEMMs: C[m,n] = sum_k A[m,k]*B[n,k]; 128x128 CTA tiles, K-tile 64,
// pre-split fp16 (hi,lo) operands in GMEM, cp.async -> swizzled smem,
// ldmatrix.x4 fragments, mma.sync.m16n8k16.f32.f16.f16.f32, 3 passes
// (hh + hl + lh) giving ~22-bit effective mantissa.
// ===========================================================================

#define BB 8
#define TT 2048
#define EE 512
#define CC 128
#define NCH 16
#define NT (BB*TT)
#define NTE (NT*EE)
#define EPS_D 1e-3f
#define QSCALE 0.044194173824159216f
#define QUP 1024.0f            // 2^10 scale for Q splits (subnormal guard)
#define QDN (1.0f/1024.0f)
#define SPN ((size_t)BB*NCH*EE*EE)
#define SMEM_BYTES (1024 + 2*4*16384)   // ctrl + 2 stages x 4 tiles(16KB)

typedef __half hf;

// ---------------- device scratch ----------------
__device__ __align__(16) float g_Q[NTE];    // fp32 q (true scale, post softmax)
__device__ __align__(16) float g_K[NTE];    // fp32 exp(k)
__device__ __align__(16) float g_V[NTE];    // fp32 v*toep
__device__ __align__(16) float g_SP[SPN];   // per-chunk S partial [f][e]
__device__ float g_RS[NT];
__device__ float g_DI[NT];
__device__ float g_ZC[BB*NCH*EE];

__device__ __align__(16) hf g_xT1[NTE], g_xT2[NTE];   // x^T [t][e]
__device__ __align__(16) hf g_Q1[NTE],  g_Q2[NTE];    // 1024*q rows [t][e]
__device__ __align__(16) hf g_K1[NTE],  g_K2[NTE];    // expk rows [t][e]
__device__ __align__(16) hf g_KT1[NTE], g_KT2[NTE];   // expk^T [e][t]
__device__ __align__(16) hf g_VT1[NTE], g_VT2[NTE];   // v^T    [f][t]
__device__ __align__(16) hf g_A1[NTE],  g_A2[NTE];    // attn   [t][e]
__device__ __align__(16) hf g_P1[BB*NCH*CC*CC], g_P2[BB*NCH*CC*CC]; // 1024*P
__device__ __align__(16) hf g_SC1[SPN], g_SC2[SPN];   // S prefix [f][e]
__device__ __align__(16) hf g_W1[4*EE*EE], g_W2[4*EE*EE];  // q,k,v,o weights

// ---------------- helpers ----------------
__device__ __forceinline__ uint32_t sm_u32(const void* p) {
    uint32_t a;
    asm("{ .reg .u64 t; cvta.to.shared.u64 t, %1; cvt.u32.u64 %0, t; }"
        : "=r"(a) : "l"(p));
    return a;
}
__device__ __forceinline__ void h2split(float v, hf& h, hf& l) {
    h = __float2half_rn(v);
    l = __float2half_rn(v - __half2float(h));
}
// swizzled byte offset in a [128 row][128B] tile: chunk' = chunk ^ (row&7)
__device__ __forceinline__ uint32_t swz(int row, int seg) {
    return (uint32_t)(row * 128 + ((seg ^ (row & 7)) << 4));
}

#define LDSM4(r0, r1, r2, r3, addr)                                            \
    asm volatile("ldmatrix.sync.aligned.m8n8.x4.shared.b16 {%0,%1,%2,%3}, [%4];" \
                 : "=r"(r0), "=r"(r1), "=r"(r2), "=r"(r3) : "r"(addr))

#define MMA16816(d, a, b)                                                      \
    asm volatile("mma.sync.aligned.m16n8k16.row.col.f32.f16.f16.f32 "          \
                 "{%0,%1,%2,%3}, {%4,%5,%6,%7}, {%8,%9}, {%0,%1,%2,%3};"       \
                 : "+f"((d)[0]), "+f"((d)[1]), "+f"((d)[2]), "+f"((d)[3])      \
                 : "r"((a)[0]), "r"((a)[1]), "r"((a)[2]), "r"((a)[3]),         \
                   "r"((b)[0]), "r"((b)[1]))

// ---------------- cp.async staging: 4 tiles (Ah,Al,Bh,Bl) of [128][64] hf ----
__device__ __forceinline__ void ld_stage(
    uint32_t st,
    const hf* __restrict__ A1, const hf* __restrict__ A2, size_t ldA,
    const hf* __restrict__ B1, const hf* __restrict__ B2, size_t ldB,
    int kc, int tid)
{
    const hf* gp[4] = {A1, A2, B1, B2};
    const size_t ldb[4] = {ldA * 2, ldA * 2, ldB * 2, ldB * 2};
#pragma unroll
    for (int t = 0; t < 4; t++) {
        const char* g0 = (const char*)gp[t] + (size_t)kc * 128;
#pragma unroll
        for (int i = 0; i < 4; i++) {
            int c = tid + i * 256;
            int row = c >> 3, seg = c & 7;
            uint32_t d = st + t * 16384 + swz(row, seg);
            const void* s = g0 + (size_t)row * ldb[t] + seg * 16;
            asm volatile("cp.async.cg.shared.global [%0], [%1], 16;"
                         :: "r"(d), "l"(s) : "memory");
        }
    }
    asm volatile("cp.async.commit_group;" ::: "memory");
}

// ---------------- per-ktile compute: 3 fp16 passes, ldmatrix + mma ----------
__device__ __forceinline__ void compute_tile(
    float (&acc)[4][4][4], uint32_t stage, int warpM, int warpN, int lane)
{
    const int l7 = lane & 7;
    const int aR = warpM + ((lane >> 3) & 1) * 8 + l7;
    const int aSel = lane >> 4;          // k-chunk half for A
    const int aR7 = aR & 7;
    const int bR = warpN + (lane >> 4) * 8 + l7;
    const int bSel = (lane >> 3) & 1;    // k-chunk half for B
    const int bR7 = bR & 7;
    uint32_t aRow[4];
#pragma unroll
    for (int mi = 0; mi < 4; mi++) aRow[mi] = (uint32_t)((aR + mi * 16) * 128);
    const uint32_t bRow0 = (uint32_t)(bR * 128);
    const uint32_t bRow1 = (uint32_t)((bR + 16) * 128);

    const uint32_t aBase[3] = {stage, stage, stage + 16384u};           // Ah,Ah,Al
    const uint32_t bBase[3] = {stage + 32768u, stage + 49152u, stage + 32768u}; // Bh,Bl,Bh
#pragma unroll
    for (int p = 0; p < 3; p++) {
#pragma unroll
        for (int ks = 0; ks < 4; ks++) {
            const uint32_t ax = (uint32_t)(((ks * 2 + aSel) ^ aR7) << 4);
            const uint32_t bx = (uint32_t)(((ks * 2 + bSel) ^ bR7) << 4);
            uint32_t a[4][4], b0[4], b1[4];
#pragma unroll
            for (int mi = 0; mi < 4; mi++)
                LDSM4(a[mi][0], a[mi][1], a[mi][2], a[mi][3],
                      aBase[p] + aRow[mi] + ax);
            LDSM4(b0[0], b0[1], b0[2], b0[3], bBase[p] + bRow0 + bx);
            LDSM4(b1[0], b1[1], b1[2], b1[3], bBase[p] + bRow1 + bx);
#pragma unroll
            for (int mi = 0; mi < 4; mi++) {
                MMA16816(acc[mi][0], a[mi], b0 + 0);
                MMA16816(acc[mi][1], a[mi], b0 + 2);
                MMA16816(acc[mi][2], a[mi], b1 + 0);
                MMA16816(acc[mi][3], a[mi], b1 + 2);
            }
        }
    }
}

// ---------------- double-buffered GEMM core (accumulating) ------------------
__device__ void gemm_core(const hf* A1, const hf* A2, size_t ldA,
                          const hf* B1, const hf* B2, size_t ldB,
                          int nK, uint32_t sb, float (&acc)[4][4][4])
{
    const int tid = threadIdx.x;
    const int lane = tid & 31, wid = tid >> 5;
    const int warpM = (wid & 1) * 64, warpN = (wid >> 1) * 32;
    ld_stage(sb, A1, A2, ldA, B1, B2, ldB, 0, tid);
    for (int kc = 0; kc < nK; kc++) {
        if (kc + 1 < nK) {
            ld_stage(sb + ((kc + 1) & 1) * 65536, A1, A2, ldA, B1, B2, ldB,
                     kc + 1, tid);
            asm volatile("cp.async.wait_group 1;" ::: "memory");
        } else {
            asm volatile("cp.async.wait_group 0;" ::: "memory");
        }
        __syncthreads();
        compute_tile(acc, sb + (kc & 1) * 65536, warpM, warpN, lane);
        __syncthreads();
    }
}

#define ACC_DECL()                                                             \
    float acc[4][4][4];                                                        \
    _Pragma("unroll") for (int _i = 0; _i < 4; _i++)                           \
        _Pragma("unroll") for (int _j = 0; _j < 4; _j++)                       \
            _Pragma("unroll") for (int _r = 0; _r < 4; _r++)                   \
                acc[_i][_j][_r] = 0.f;

#define EPI_SETUP()                                                            \
    const int lane = threadIdx.x & 31, wid = threadIdx.x >> 5;                 \
    const int warpM = (wid & 1) * 64, warpN = (wid >> 1) * 32;                 \
    const int er = warpM + (lane >> 2);                                        \
    const int ec = warpN + (lane & 3) * 2;

// ===========================================================================
// aux kernels
// ===========================================================================

__global__ __launch_bounds__(256) void prep_w(
    const float* __restrict__ qw, const float* __restrict__ kw,
    const float* __restrict__ vw, const float* __restrict__ ow)
{
    int i = blockIdx.x * 256 + threadIdx.x;
    int m = i >> 18;
    const float* src = (m == 0) ? qw : (m == 1) ? kw : (m == 2) ? vw : ow;
    float v = src[i & (EE * EE - 1)];
    h2split(v, g_W1[i], g_W2[i]);
}

__global__ __launch_bounds__(256) void trans_x(const float* __restrict__ x)
{
    __shared__ float tile[32][33];
    const int b = blockIdx.z, t0 = blockIdx.x * 32, e0 = blockIdx.y * 32;
    const int tx = threadIdx.x, ty = threadIdx.y;
#pragma unroll
    for (int j = 0; j < 4; j++) {
        int e = e0 + ty + j * 8;
        tile[tx][ty + j * 8] = x[((size_t)(b * EE + e)) * TT + t0 + tx];
    }
    __syncthreads();
#pragma unroll
    for (int j = 0; j < 4; j++) {
        int r = ty + j * 8;
        float v = tile[r][tx];   // (t = t0+r, e = e0+tx)
        size_t o = ((size_t)(b * TT + t0 + r)) * EE + e0 + tx;
        h2split(v, g_xT1[o], g_xT2[o]);
    }
}

// row softmax on g_Q (*E^-0.5); fp32 true + 1024x-scaled fp16 splits
__global__ __launch_bounds__(256) void softmax_split()
{
    size_t row = blockIdx.x;
    float* r = g_Q + row * EE;
    int tid = threadIdx.x;
    float v0 = r[tid], v1 = r[tid + 256];
    __shared__ float red[256];
    red[tid] = fmaxf(v0, v1);
    __syncthreads();
    for (int s = 128; s > 0; s >>= 1) {
        if (tid < s) red[tid] = fmaxf(red[tid], red[tid + s]);
        __syncthreads();
    }
    float m = red[0];
    __syncthreads();
    float e0 = expf(v0 - m), e1 = expf(v1 - m);
    red[tid] = e0 + e1;
    __syncthreads();
    for (int s = 128; s > 0; s >>= 1) {
        if (tid < s) red[tid] += red[tid + s];
        __syncthreads();
    }
    float sc = QSCALE / red[0];
    float q0 = e0 * sc, q1 = e1 * sc;
    r[tid] = q0; r[tid + 256] = q1;
    size_t o0 = row * EE + tid, o1 = o0 + 256;
    h2split(q0 * QUP, g_Q1[o0], g_Q2[o0]);
    h2split(q1 * QUP, g_Q1[o1], g_Q2[o1]);
}

// exp(k): row splits + transposed splits
__global__ __launch_bounds__(256) void trans_split_K()
{
    __shared__ float tile[32][33];
    const int b = blockIdx.z, t0 = blockIdx.x * 32, e0 = blockIdx.y * 32;
    const int tx = threadIdx.x, ty = threadIdx.y;
#pragma unroll
    for (int j = 0; j < 4; j++) {
        int t = t0 + ty + j * 8;
        size_t o = ((size_t)(b * TT + t)) * EE + e0 + tx;
        float v = g_K[o];
        tile[ty + j * 8][tx] = v;
        h2split(v, g_K1[o], g_K2[o]);
    }
    __syncthreads();
#pragma unroll
    for (int j = 0; j < 4; j++) {
        int r = ty + j * 8;
        float v = tile[tx][r];   // K[t0+tx][e0+r]
        size_t o = ((size_t)(b * EE + e0 + r)) * TT + t0 + tx;
        h2split(v, g_KT1[o], g_KT2[o]);
    }
}

__global__ __launch_bounds__(256) void trans_split_V()
{
    __shared__ float tile[32][33];
    const int b = blockIdx.z, t0 = blockIdx.x * 32, e0 = blockIdx.y * 32;
    const int tx = threadIdx.x, ty = threadIdx.y;
#pragma unroll
    for (int j = 0; j < 4; j++) {
        int t = t0 + ty + j * 8;
        tile[ty + j * 8][tx] = g_V[((size_t)(b * TT + t)) * EE + e0 + tx];
    }
    __syncthreads();
#pragma unroll
    for (int j = 0; j < 4; j++) {
        int r = ty + j * 8;
        float v = tile[tx][r];
        size_t o = ((size_t)(b * EE + e0 + r)) * TT + t0 + tx;
        h2split(v, g_VT1[o], g_VT2[o]);
    }
}

__global__ __launch_bounds__(512) void z_prefix()
{
    int b = blockIdx.x, e = threadIdx.x;
    float run = 0.f;
    for (int c = 0; c < NCH; c++) {
        g_ZC[((size_t)b * NCH + c) * EE + e] = run;
        const float* kb = g_K + ((size_t)b * TT + (size_t)c * CC) * EE + e;
#pragma unroll 8
        for (int s = 0; s < CC; s++) run += kb[(size_t)s * EE];
    }
}

// exclusive chunk prefix of S partials -> fp16 splits
__global__ __launch_bounds__(256) void prefix_S()
{
    int gid = blockIdx.x * 256 + threadIdx.x;
    int b = gid >> 16;
    int p4 = gid & 65535;
    size_t base = ((size_t)b * NCH) * EE * EE + (size_t)p4 * 4;
    float4 run = make_float4(0.f, 0.f, 0.f, 0.f);
    for (int c = 0; c < NCH; c++) {
        size_t o = base + (size_t)c * EE * EE;
        float rv[4] = {run.x, run.y, run.z, run.w};
        hf h[4], l[4];
#pragma unroll
        for (int j = 0; j < 4; j++) h2split(rv[j], h[j], l[j]);
        *(__half2*)(g_SC1 + o)     = __halves2half2(h[0], h[1]);
        *(__half2*)(g_SC1 + o + 2) = __halves2half2(h[2], h[3]);
        *(__half2*)(g_SC2 + o)     = __halves2half2(l[0], l[1]);
        *(__half2*)(g_SC2 + o + 2) = __halves2half2(l[2], l[3]);
        float4 s = *(const float4*)(g_SP + o);
        run.x += s.x; run.y += s.y; run.z += s.z; run.w += s.w;
    }
}

__global__ __launch_bounds__(256) void dinv_kernel()
{
    int w = blockIdx.x * 8 + (threadIdx.x >> 5);
    int lane = threadIdx.x & 31;
    int b = w >> 11, t = w & 2047, c = t >> 7;
    const float* q = g_Q + (size_t)w * EE;
    const float* z = g_ZC + ((size_t)b * NCH + c) * EE;
    float s = 0.f;
#pragma unroll
    for (int i = 0; i < 16; i++) s += q[lane + 32 * i] * z[lane + 32 * i];
#pragma unroll
    for (int o = 16; o > 0; o >>= 1) s += __shfl_xor_sync(0xffffffffu, s, o);
    if (lane == 0) g_DI[w] = 1.f / fmaxf(s + g_RS[w], EPS_D);
}

// ===========================================================================
// GEMM kernels
// ===========================================================================

// projections: C[t,o] = x^T @ W^T + b; mode 0:Q 1:K(exp) 2:V(*toep) -> fp32
__global__ __launch_bounds__(256, 1) void proj_tc(
    const float* __restrict__ bias, const float* __restrict__ toep, int mode)
{
    extern __shared__ char smdyn[];
    uint32_t sb = sm_u32(smdyn) + 1024;
    const int b = blockIdx.z, t0 = blockIdx.x * 128, o0 = blockIdx.y * 128;
    ACC_DECL();
    const size_t aoff = ((size_t)(b * TT + t0)) * EE;
    const size_t woff = (size_t)mode * EE * EE + (size_t)o0 * EE;
    gemm_core(g_xT1 + aoff, g_xT2 + aoff, EE, g_W1 + woff, g_W2 + woff, EE,
              8, sb, acc);
    EPI_SETUP();
    float* out = (mode == 0) ? g_Q : (mode == 1) ? g_K : g_V;
#pragma unroll
    for (int mi = 0; mi < 4; mi++)
#pragma unroll
        for (int h = 0; h < 2; h++) {
            int t = t0 + er + mi * 16 + h * 8;
            float tw = (mode == 2) ? toep[t] : 1.f;
            float* orow = out + ((size_t)b * TT + t) * EE + o0;
#pragma unroll
            for (int nf = 0; nf < 4; nf++) {
                int cc = ec + nf * 8;
                float v0 = acc[mi][nf][h * 2 + 0] + bias[o0 + cc];
                float v1 = acc[mi][nf][h * 2 + 1] + bias[o0 + cc + 1];
                if (mode == 1) { v0 = expf(v0); v1 = expf(v1); }
                else if (mode == 2) { v0 *= tw; v1 *= tw; }
                *(float2*)&orow[cc] = make_float2(v0, v1);
            }
        }
}

// P' = mask(Q' K^T) (1024x scale kept), fp16 splits + true rowsums
__global__ __launch_bounds__(256, 1) void p_tc()
{
    extern __shared__ char smdyn[];
    uint32_t sb = sm_u32(smdyn) + 1024;
    float* srs = (float*)smdyn;
    const int c = blockIdx.x, b = blockIdx.y;
    const int tid = threadIdx.x;
    if (tid < CC) srs[tid] = 0.f;
    ACC_DECL();
    const size_t off = ((size_t)(b * TT + c * CC)) * EE;
    gemm_core(g_Q1 + off, g_Q2 + off, EE, g_K1 + off, g_K2 + off, EE,
              8, sb, acc);
    EPI_SETUP();
    hf* P1 = g_P1 + (size_t)(b * NCH + c) * CC * CC;
    hf* P2 = g_P2 + (size_t)(b * NCH + c) * CC * CC;
#pragma unroll
    for (int mi = 0; mi < 4; mi++)
#pragma unroll
        for (int h = 0; h < 2; h++) {
            int m = er + mi * 16 + h * 8;
            float rsum = 0.f;
#pragma unroll
            for (int nf = 0; nf < 4; nf++) {
                int cc = ec + nf * 8;
                float v0 = (cc     <= m) ? acc[mi][nf][h * 2 + 0] : 0.f;
                float v1 = (cc + 1 <= m) ? acc[mi][nf][h * 2 + 1] : 0.f;
                rsum += v0 + v1;
                hf h0, l0, h1, l1;
                h2split(v0, h0, l0);
                h2split(v1, h1, l1);
                *(__half2*)(P1 + (size_t)m * CC + cc) = __halves2half2(h0, h1);
                *(__half2*)(P2 + (size_t)m * CC + cc) = __halves2half2(l0, l1);
            }
            atomicAdd(&srs[m], rsum);
        }
    __syncthreads();
    if (tid < CC) g_RS[(size_t)b * TT + (size_t)c * CC + tid] = srs[tid] * QDN;
}

// per-chunk S[f,e] = V_c^T K_c  (fp32 partials)
__global__ __launch_bounds__(256, 1) void ktv_tc()
{
    extern __shared__ char smdyn[];
    uint32_t sb = sm_u32(smdyn) + 1024;
    const int fi = blockIdx.x & 3, ei = blockIdx.x >> 2;
    const int c = blockIdx.y, b = blockIdx.z;
    ACC_DECL();
    const size_t aoff = ((size_t)(b * EE + fi * 128)) * TT + (size_t)c * CC;
    const size_t boff = ((size_t)(b * EE + ei * 128)) * TT + (size_t)c * CC;
    gemm_core(g_VT1 + aoff, g_VT2 + aoff, TT, g_KT1 + boff, g_KT2 + boff, TT,
              2, sb, acc);
    EPI_SETUP();
#pragma unroll
    for (int mi = 0; mi < 4; mi++)
#pragma unroll
        for (int h = 0; h < 2; h++) {
            int m = er + mi * 16 + h * 8;
            float* sp = g_SP + ((size_t)(b * NCH + c) * EE + fi * 128 + m) * EE
                             + ei * 128;
#pragma unroll
            for (int nf = 0; nf < 4; nf++) {
                int cc = ec + nf * 8;
                *(float2*)&sp[cc] = make_float2(acc[mi][nf][h * 2 + 0],
                                                acc[mi][nf][h * 2 + 1]);
            }
        }
}

// O = (Q'@S_prev + P'@V) * dinv / 1024 -> attn fp16 splits
__global__ __launch_bounds__(256, 1) void qspv_tc()
{
    extern __shared__ char smdyn[];
    uint32_t sb = sm_u32(smdyn) + 1024;
    const int n0 = blockIdx.x * 128, c = blockIdx.y, b = blockIdx.z;
    ACC_DECL();
    const size_t qoff = ((size_t)(b * TT + c * CC)) * EE;
    if (c > 0) {
        const size_t soff = ((size_t)(b * NCH + c) * EE + n0) * EE;
        gemm_core(g_Q1 + qoff, g_Q2 + qoff, EE, g_SC1 + soff, g_SC2 + soff, EE,
                  8, sb, acc);
    }
    const size_t poff = (size_t)(b * NCH + c) * CC * CC;
    const size_t voff = ((size_t)(b * EE + n0)) * TT + (size_t)c * CC;
    gemm_core(g_P1 + poff, g_P2 + poff, CC, g_VT1 + voff, g_VT2 + voff, TT,
              2, sb, acc);
    EPI_SETUP();
#pragma unroll
    for (int mi = 0; mi < 4; mi++)
#pragma unroll
        for (int h = 0; h < 2; h++) {
            int m = er + mi * 16 + h * 8;
            size_t row = (size_t)b * TT + (size_t)c * CC + m;
            float di = g_DI[row] * QDN;
            hf* A1 = g_A1 + row * EE + n0;
            hf* A2 = g_A2 + row * EE + n0;
#pragma unroll
            for (int nf = 0; nf < 4; nf++) {
                int cc = ec + nf * 8;
                float v0 = acc[mi][nf][h * 2 + 0] * di;
                float v1 = acc[mi][nf][h * 2 + 1] * di;
                hf h0, l0, h1, l1;
                h2split(v0, h0, l0);
                h2split(v1, h1, l1);
                *(__half2*)(A1 + cc) = __halves2half2(h0, h1);
                *(__half2*)(A2 + cc) = __halves2half2(l0, l1);
            }
        }
}

// out = A @ o_w^T + o_b (fp32)
__global__ __launch_bounds__(256, 1) void out_tc(
    const float* __restrict__ ob, float* __restrict__ out)
{
    extern __shared__ char smdyn[];
    uint32_t sb = sm_u32(smdyn) + 1024;
    const int b = blockIdx.z, t0 = blockIdx.x * 128, o0 = blockIdx.y * 128;
    ACC_DECL();
    const size_t aoff = ((size_t)(b * TT + t0)) * EE;
    const size_t woff = (size_t)3 * EE * EE + (size_t)o0 * EE;
    gemm_core(g_A1 + aoff, g_A2 + aoff, EE, g_W1 + woff, g_W2 + woff, EE,
              8, sb, acc);
    EPI_SETUP();
#pragma unroll
    for (int mi = 0; mi < 4; mi++)
#pragma unroll
        for (int h = 0; h < 2; h++) {
            int t = t0 + er + mi * 16 + h * 8;
            float* orow = out + ((size_t)b * TT + t) * EE + o0;
#pragma unroll
            for (int nf = 0; nf < 4; nf++) {
                int cc = ec + nf * 8;
                *(float2*)&orow[cc] = make_float2(
                    acc[mi][nf][h * 2 + 0] + ob[o0 + cc],
                    acc[mi][nf][h * 2 + 1] + ob[o0 + cc + 1]);
            }
        }
}

// ===========================================================================
extern "C" void kernel_launch(void* const* d_in, const int* in_sizes, int n_in,
                              void* d_out, int out_size)
{
    (void)in_sizes; (void)n_in; (void)out_size;
    const float* x    = (const float*)d_in[0];
    const float* toep = (const float*)d_in[1];
    const float* q_w  = (const float*)d_in[2];
    const float* q_b  = (const float*)d_in[3];
    const float* k_w  = (const float*)d_in[4];
    const float* k_b  = (const float*)d_in[5];
    const float* v_w  = (const float*)d_in[6];
    const float* v_b  = (const float*)d_in[7];
    const float* o_w  = (const float*)d_in[8];
    const float* o_b  = (const float*)d_in[9];
    float* out = (float*)d_out;

    cudaFuncSetAttribute(proj_tc, cudaFuncAttributeMaxDynamicSharedMemorySize, SMEM_BYTES);
    cudaFuncSetAttribute(p_tc,    cudaFuncAttributeMaxDynamicSharedMemorySize, SMEM_BYTES);
    cudaFuncSetAttribute(ktv_tc,  cudaFuncAttributeMaxDynamicSharedMemorySize, SMEM_BYTES);
    cudaFuncSetAttribute(qspv_tc, cudaFuncAttributeMaxDynamicSharedMemorySize, SMEM_BYTES);
    cudaFuncSetAttribute(out_tc,  cudaFuncAttributeMaxDynamicSharedMemorySize, SMEM_BYTES);

    prep_w<<<4096, 256>>>(q_w, k_w, v_w, o_w);
    trans_x<<<dim3(TT / 32, EE / 32, BB), dim3(32, 8)>>>(x);

    dim3 gProj(TT / 128, EE / 128, BB);
    proj_tc<<<gProj, 256, SMEM_BYTES>>>(q_b, toep, 0);
    proj_tc<<<gProj, 256, SMEM_BYTES>>>(k_b, toep, 1);
    proj_tc<<<gProj, 256, SMEM_BYTES>>>(v_b, toep, 2);

    softmax_split<<<NT, 256>>>();
    trans_split_K<<<dim3(TT / 32, EE / 32, BB), dim3(32, 8)>>>();
    trans_split_V<<<dim3(TT / 32, EE / 32, BB), dim3(32, 8)>>>();
    z_prefix<<<BB, 512>>>();

    p_tc<<<dim3(NCH, BB), 256, SMEM_BYTES>>>();
    ktv_tc<<<dim3(16, NCH, BB), 256, SMEM_BYTES>>>();
    prefix_S<<<2048, 256>>>();
    dinv_kernel<<<NT / 8, 256>>>();
    qspv_tc<<<dim3(EE / 128, NCH, BB), 256, SMEM_BYTES>>>();
    out_tc<<<gProj, 256, SMEM_BYTES>>>(o_b, out);
}

// round 8
// speedup vs baseline: 2.1274x; 1.1243x over previous
#include <cuda_runtime.h>
#include <cuda_fp16.h>
#include <cstdint>
#include <math.h>

// ===========================================================================
// LinearAttentionToeplitz — fp16x2 error-compensated mma.sync pipeline, v2.
// 512 threads/CTA (16 warps, 32x32 warp tiles), 3-stage cp.async ring,
// single barrier per k-tile. 3 passes (hh+hl+lh) ~22-bit effective mantissa.
// ===========================================================================

#define BB 8
#define TT 2048
#define EE 512
#define CC 128
#define NCH 16
#define NT (BB*TT)
#define NTE (NT*EE)
#define EPS_D 1e-3f
#define QSCALE 0.044194173824159216f
#define QUP 1024.0f
#define QDN (1.0f/1024.0f)
#define SPN ((size_t)BB*NCH*EE*EE)
#define STAGE_BYTES 65536              // 4 tiles x [128][64] fp16
#define SMEM_BYTES (1024 + 3*STAGE_BYTES)

typedef __half hf;

// ---------------- device scratch ----------------
__device__ __align__(16) float g_Q[NTE];    // fp32 q (true scale)
__device__ __align__(16) float g_K[NTE];    // fp32 exp(k)
__device__ __align__(16) float g_V[NTE];    // fp32 v*toep
__device__ __align__(16) float g_SP[SPN];   // per-chunk S partial [f][e]
__device__ float g_RS[NT];
__device__ float g_DI[NT];
__device__ float g_ZC[BB*NCH*EE];
__device__ float g_ZS[BB*NCH*EE];

__device__ __align__(16) hf g_xT1[NTE], g_xT2[NTE];   // x^T [t][e]
__device__ __align__(16) hf g_Q1[NTE],  g_Q2[NTE];    // 1024*q rows
__device__ __align__(16) hf g_K1[NTE],  g_K2[NTE];    // expk rows
__device__ __align__(16) hf g_KT1[NTE], g_KT2[NTE];   // expk^T [e][t]
__device__ __align__(16) hf g_VT1[NTE], g_VT2[NTE];   // v^T    [f][t]
__device__ __align__(16) hf g_A1[NTE],  g_A2[NTE];    // attn   [t][e]
__device__ __align__(16) hf g_P1[BB*NCH*CC*CC], g_P2[BB*NCH*CC*CC]; // 1024*P
__device__ __align__(16) hf g_SC1[SPN], g_SC2[SPN];   // S prefix [f][e]
__device__ __align__(16) hf g_W1[4*EE*EE], g_W2[4*EE*EE];

// ---------------- helpers ----------------
__device__ __forceinline__ uint32_t sm_u32(const void* p) {
    uint32_t a;
    asm("{ .reg .u64 t; cvta.to.shared.u64 t, %1; cvt.u32.u64 %0, t; }"
        : "=r"(a) : "l"(p));
    return a;
}
__device__ __forceinline__ void h2split(float v, hf& h, hf& l) {
    h = __float2half_rn(v);
    l = __float2half_rn(v - __half2float(h));
}
__device__ __forceinline__ uint32_t swz(int row, int seg) {
    return (uint32_t)(row * 128 + ((seg ^ (row & 7)) << 4));
}

#define LDSM4(r0, r1, r2, r3, addr)                                            \
    asm volatile("ldmatrix.sync.aligned.m8n8.x4.shared.b16 {%0,%1,%2,%3}, [%4];" \
                 : "=r"(r0), "=r"(r1), "=r"(r2), "=r"(r3) : "r"(addr))

#define MMA16816(d, a, b)                                                      \
    asm volatile("mma.sync.aligned.m16n8k16.row.col.f32.f16.f16.f32 "          \
                 "{%0,%1,%2,%3}, {%4,%5,%6,%7}, {%8,%9}, {%0,%1,%2,%3};"       \
                 : "+f"((d)[0]), "+f"((d)[1]), "+f"((d)[2]), "+f"((d)[3])      \
                 : "r"((a)[0]), "r"((a)[1]), "r"((a)[2]), "r"((a)[3]),         \
                   "r"((b)[0]), "r"((b)[1]))

// ---------------- cp.async staging: 4 tiles (Ah,Al,Bh,Bl) [128][64] hf ------
__device__ __forceinline__ void ld_stage(
    uint32_t st,
    const hf* __restrict__ A1, const hf* __restrict__ A2, size_t ldA,
    const hf* __restrict__ B1, const hf* __restrict__ B2, size_t ldB,
    int kc, int tid)
{
    const hf* gp[4] = {A1, A2, B1, B2};
    const size_t ldb[4] = {ldA * 2, ldA * 2, ldB * 2, ldB * 2};
#pragma unroll
    for (int t = 0; t < 4; t++) {
        const char* g0 = (const char*)gp[t] + (size_t)kc * 128;
#pragma unroll
        for (int i = 0; i < 2; i++) {
            int c = tid + i * 512;
            int row = c >> 3, seg = c & 7;
            uint32_t d = st + t * 16384 + swz(row, seg);
            const void* s = g0 + (size_t)row * ldb[t] + seg * 16;
            asm volatile("cp.async.cg.shared.global [%0], [%1], 16;"
                         :: "r"(d), "l"(s) : "memory");
        }
    }
    asm volatile("cp.async.commit_group;" ::: "memory");
}

// ---------------- per-ktile compute: 32x32 warp tile, 3 passes --------------
__device__ __forceinline__ void compute_tile(
    float (&acc)[2][4][4], uint32_t stage, int warpM, int warpN, int lane)
{
    const int l7 = lane & 7;
    const int aSel = lane >> 4;
    const int bSel = (lane >> 3) & 1;
    const int aR = ((lane >> 3) & 1) * 8 + l7;
    const int bR = (lane >> 4) * 8 + l7;
    const uint32_t aRow0 = (uint32_t)((warpM + aR) * 128);
    const uint32_t aRow1 = (uint32_t)((warpM + 16 + aR) * 128);
    const uint32_t bRow0 = (uint32_t)((warpN + bR) * 128);
    const uint32_t bRow1 = (uint32_t)((warpN + 16 + bR) * 128);
    const uint32_t aBase[3] = {stage, stage, stage + 16384u};            // Ah,Ah,Al
    const uint32_t bBase[3] = {stage + 32768u, stage + 49152u, stage + 32768u}; // Bh,Bl,Bh
#pragma unroll
    for (int p = 0; p < 3; p++) {
#pragma unroll
        for (int ks = 0; ks < 4; ks++) {
            const uint32_t ax = (uint32_t)(((ks * 2 + aSel) ^ l7) << 4);
            const uint32_t bx = (uint32_t)(((ks * 2 + bSel) ^ l7) << 4);
            uint32_t a0[4], a1[4], b0[4], b1[4];
            LDSM4(a0[0], a0[1], a0[2], a0[3], aBase[p] + aRow0 + ax);
            LDSM4(a1[0], a1[1], a1[2], a1[3], aBase[p] + aRow1 + ax);
            LDSM4(b0[0], b0[1], b0[2], b0[3], bBase[p] + bRow0 + bx);
            LDSM4(b1[0], b1[1], b1[2], b1[3], bBase[p] + bRow1 + bx);
            MMA16816(acc[0][0], a0, b0 + 0);
            MMA16816(acc[0][1], a0, b0 + 2);
            MMA16816(acc[0][2], a0, b1 + 0);
            MMA16816(acc[0][3], a0, b1 + 2);
            MMA16816(acc[1][0], a1, b0 + 0);
            MMA16816(acc[1][1], a1, b0 + 2);
            MMA16816(acc[1][2], a1, b1 + 0);
            MMA16816(acc[1][3], a1, b1 + 2);
        }
    }
}

// ---------------- 3-stage ring GEMM core (accumulating) ---------------------
__device__ void gemm_core(const hf* A1, const hf* A2, size_t ldA,
                          const hf* B1, const hf* B2, size_t ldB,
                          int nK, uint32_t sb, float (&acc)[2][4][4])
{
    const int tid = threadIdx.x;
    const int lane = tid & 31, wid = tid >> 5;
    const int warpM = (wid & 3) * 32, warpN = (wid >> 2) * 32;
    ld_stage(sb, A1, A2, ldA, B1, B2, ldB, 0, tid);
    if (nK > 1) ld_stage(sb + STAGE_BYTES, A1, A2, ldA, B1, B2, ldB, 1, tid);
    for (int kc = 0; kc < nK; kc++) {
        if (kc + 1 < nK) asm volatile("cp.async.wait_group 1;" ::: "memory");
        else             asm volatile("cp.async.wait_group 0;" ::: "memory");
        __syncthreads();
        if (kc + 2 < nK)
            ld_stage(sb + ((kc + 2) % 3) * STAGE_BYTES,
                     A1, A2, ldA, B1, B2, ldB, kc + 2, tid);
        compute_tile(acc, sb + (kc % 3) * STAGE_BYTES, warpM, warpN, lane);
    }
    __syncthreads();   // buffers reusable by caller / next gemm_core
}

#define ACC_DECL()                                                             \
    float acc[2][4][4];                                                        \
    _Pragma("unroll") for (int _i = 0; _i < 2; _i++)                           \
        _Pragma("unroll") for (int _j = 0; _j < 4; _j++)                       \
            _Pragma("unroll") for (int _r = 0; _r < 4; _r++)                   \
                acc[_i][_j][_r] = 0.f;

#define EPI_SETUP()                                                            \
    const int lane = threadIdx.x & 31, wid = threadIdx.x >> 5;                 \
    const int warpM = (wid & 3) * 32, warpN = (wid >> 2) * 32;                 \
    const int er = warpM + (lane >> 2);                                        \
    const int ec = warpN + (lane & 3) * 2;

// ===========================================================================
// aux kernels
// ===========================================================================

__global__ __launch_bounds__(256) void prep_w(
    const float* __restrict__ qw, const float* __restrict__ kw,
    const float* __restrict__ vw, const float* __restrict__ ow)
{
    int i = blockIdx.x * 256 + threadIdx.x;
    int m = i >> 18;
    const float* src = (m == 0) ? qw : (m == 1) ? kw : (m == 2) ? vw : ow;
    float v = src[i & (EE * EE - 1)];
    h2split(v, g_W1[i], g_W2[i]);
}

__global__ __launch_bounds__(256) void trans_x(const float* __restrict__ x)
{
    __shared__ float tile[32][33];
    const int b = blockIdx.z, t0 = blockIdx.x * 32, e0 = blockIdx.y * 32;
    const int tx = threadIdx.x, ty = threadIdx.y;
#pragma unroll
    for (int j = 0; j < 4; j++) {
        int e = e0 + ty + j * 8;
        tile[tx][ty + j * 8] = x[((size_t)(b * EE + e)) * TT + t0 + tx];
    }
    __syncthreads();
#pragma unroll
    for (int j = 0; j < 4; j++) {
        int r = ty + j * 8;
        float v = tile[r][tx];
        size_t o = ((size_t)(b * TT + t0 + r)) * EE + e0 + tx;
        h2split(v, g_xT1[o], g_xT2[o]);
    }
}

__global__ __launch_bounds__(256) void softmax_split()
{
    size_t row = blockIdx.x;
    float* r = g_Q + row * EE;
    int tid = threadIdx.x;
    float v0 = r[tid], v1 = r[tid + 256];
    __shared__ float red[256];
    red[tid] = fmaxf(v0, v1);
    __syncthreads();
    for (int s = 128; s > 0; s >>= 1) {
        if (tid < s) red[tid] = fmaxf(red[tid], red[tid + s]);
        __syncthreads();
    }
    float m = red[0];
    __syncthreads();
    float e0 = expf(v0 - m), e1 = expf(v1 - m);
    red[tid] = e0 + e1;
    __syncthreads();
    for (int s = 128; s > 0; s >>= 1) {
        if (tid < s) red[tid] += red[tid + s];
        __syncthreads();
    }
    float sc = QSCALE / red[0];
    float q0 = e0 * sc, q1 = e1 * sc;
    r[tid] = q0; r[tid + 256] = q1;
    size_t o0 = row * EE + tid, o1 = o0 + 256;
    h2split(q0 * QUP, g_Q1[o0], g_Q2[o0]);
    h2split(q1 * QUP, g_Q1[o1], g_Q2[o1]);
}

__global__ __launch_bounds__(256) void trans_split_K()
{
    __shared__ float tile[32][33];
    const int b = blockIdx.z, t0 = blockIdx.x * 32, e0 = blockIdx.y * 32;
    const int tx = threadIdx.x, ty = threadIdx.y;
#pragma unroll
    for (int j = 0; j < 4; j++) {
        int t = t0 + ty + j * 8;
        size_t o = ((size_t)(b * TT + t)) * EE + e0 + tx;
        float v = g_K[o];
        tile[ty + j * 8][tx] = v;
        h2split(v, g_K1[o], g_K2[o]);
    }
    __syncthreads();
#pragma unroll
    for (int j = 0; j < 4; j++) {
        int r = ty + j * 8;
        float v = tile[tx][r];
        size_t o = ((size_t)(b * EE + e0 + r)) * TT + t0 + tx;
        h2split(v, g_KT1[o], g_KT2[o]);
    }
}

__global__ __launch_bounds__(256) void trans_split_V()
{
    __shared__ float tile[32][33];
    const int b = blockIdx.z, t0 = blockIdx.x * 32, e0 = blockIdx.y * 32;
    const int tx = threadIdx.x, ty = threadIdx.y;
#pragma unroll
    for (int j = 0; j < 4; j++) {
        int t = t0 + ty + j * 8;
        tile[ty + j * 8][tx] = g_V[((size_t)(b * TT + t)) * EE + e0 + tx];
    }
    __syncthreads();
#pragma unroll
    for (int j = 0; j < 4; j++) {
        int r = ty + j * 8;
        float v = tile[tx][r];
        size_t o = ((size_t)(b * EE + e0 + r)) * TT + t0 + tx;
        h2split(v, g_VT1[o], g_VT2[o]);
    }
}

// phase 1: per-chunk colsum of exp(k)
__global__ __launch_bounds__(512) void z_colsum()
{
    int c = blockIdx.x, b = blockIdx.y, e = threadIdx.x;
    const float* kb = g_K + ((size_t)b * TT + (size_t)c * CC) * EE + e;
    float s = 0.f;
#pragma unroll 8
    for (int t = 0; t < CC; t++) s += kb[(size_t)t * EE];
    g_ZS[((size_t)b * NCH + c) * EE + e] = s;
}

// phase 2: exclusive scan over chunks
__global__ __launch_bounds__(512) void z_scan()
{
    int b = blockIdx.x, e = threadIdx.x;
    float run = 0.f;
    for (int c = 0; c < NCH; c++) {
        size_t o = ((size_t)b * NCH + c) * EE + e;
        g_ZC[o] = run;
        run += g_ZS[o];
    }
}

__global__ __launch_bounds__(256) void prefix_S()
{
    int gid = blockIdx.x * 256 + threadIdx.x;
    int b = gid >> 16;
    int p4 = gid & 65535;
    size_t base = ((size_t)b * NCH) * EE * EE + (size_t)p4 * 4;
    float4 run = make_float4(0.f, 0.f, 0.f, 0.f);
    for (int c = 0; c < NCH; c++) {
        size_t o = base + (size_t)c * EE * EE;
        float rv[4] = {run.x, run.y, run.z, run.w};
        hf h[4], l[4];
#pragma unroll
        for (int j = 0; j < 4; j++) h2split(rv[j], h[j], l[j]);
        *(__half2*)(g_SC1 + o)     = __halves2half2(h[0], h[1]);
        *(__half2*)(g_SC1 + o + 2) = __halves2half2(h[2], h[3]);
        *(__half2*)(g_SC2 + o)     = __halves2half2(l[0], l[1]);
        *(__half2*)(g_SC2 + o + 2) = __halves2half2(l[2], l[3]);
        float4 s = *(const float4*)(g_SP + o);
        run.x += s.x; run.y += s.y; run.z += s.z; run.w += s.w;
    }
}

__global__ __launch_bounds__(256) void dinv_kernel()
{
    int w = blockIdx.x * 8 + (threadIdx.x >> 5);
    int lane = threadIdx.x & 31;
    int b = w >> 11, t = w & 2047, c = t >> 7;
    const float* q = g_Q + (size_t)w * EE;
    const float* z = g_ZC + ((size_t)b * NCH + c) * EE;
    float s = 0.f;
#pragma unroll
    for (int i = 0; i < 16; i++) s += q[lane + 32 * i] * z[lane + 32 * i];
#pragma unroll
    for (int o = 16; o > 0; o >>= 1) s += __shfl_xor_sync(0xffffffffu, s, o);
    if (lane == 0) g_DI[w] = 1.f / fmaxf(s + g_RS[w], EPS_D);
}

// ===========================================================================
// GEMM kernels (512 threads)
// ===========================================================================

// merged projections: z = mode*BB + b; C[t,o] = x^T @ W^T + b
__global__ __launch_bounds__(512, 1) void proj_tc(
    const float* __restrict__ qb, const float* __restrict__ kb,
    const float* __restrict__ vb, const float* __restrict__ toep)
{
    extern __shared__ char smdyn[];
    uint32_t sb = sm_u32(smdyn) + 1024;
    const int mode = blockIdx.z >> 3, b = blockIdx.z & 7;
    const int t0 = blockIdx.x * 128, o0 = blockIdx.y * 128;
    ACC_DECL();
    const size_t aoff = ((size_t)(b * TT + t0)) * EE;
    const size_t woff = (size_t)mode * EE * EE + (size_t)o0 * EE;
    gemm_core(g_xT1 + aoff, g_xT2 + aoff, EE, g_W1 + woff, g_W2 + woff, EE,
              8, sb, acc);
    EPI_SETUP();
    const float* bias = (mode == 0) ? qb : (mode == 1) ? kb : vb;
    float* out = (mode == 0) ? g_Q : (mode == 1) ? g_K : g_V;
#pragma unroll
    for (int mi = 0; mi < 2; mi++)
#pragma unroll
        for (int h = 0; h < 2; h++) {
            int t = t0 + er + mi * 16 + h * 8;
            float tw = (mode == 2) ? toep[t] : 1.f;
            float* orow = out + ((size_t)b * TT + t) * EE + o0;
#pragma unroll
            for (int nf = 0; nf < 4; nf++) {
                int cc = ec + nf * 8;
                float v0 = acc[mi][nf][h * 2 + 0] + bias[o0 + cc];
                float v1 = acc[mi][nf][h * 2 + 1] + bias[o0 + cc + 1];
                if (mode == 1) { v0 = expf(v0); v1 = expf(v1); }
                else if (mode == 2) { v0 *= tw; v1 *= tw; }
                *(float2*)&orow[cc] = make_float2(v0, v1);
            }
        }
}

// P' = mask(Q' K^T): fp16 splits + true rowsums
__global__ __launch_bounds__(512, 1) void p_tc()
{
    extern __shared__ char smdyn[];
    uint32_t sb = sm_u32(smdyn) + 1024;
    float* srs = (float*)smdyn;
    const int c = blockIdx.x, b = blockIdx.y;
    const int tid = threadIdx.x;
    if (tid < CC) srs[tid] = 0.f;
    ACC_DECL();
    const size_t off = ((size_t)(b * TT + c * CC)) * EE;
    gemm_core(g_Q1 + off, g_Q2 + off, EE, g_K1 + off, g_K2 + off, EE,
              8, sb, acc);
    EPI_SETUP();
    hf* P1 = g_P1 + (size_t)(b * NCH + c) * CC * CC;
    hf* P2 = g_P2 + (size_t)(b * NCH + c) * CC * CC;
#pragma unroll
    for (int mi = 0; mi < 2; mi++)
#pragma unroll
        for (int h = 0; h < 2; h++) {
            int m = er + mi * 16 + h * 8;
            float rsum = 0.f;
#pragma unroll
            for (int nf = 0; nf < 4; nf++) {
                int cc = ec + nf * 8;
                float v0 = (cc     <= m) ? acc[mi][nf][h * 2 + 0] : 0.f;
                float v1 = (cc + 1 <= m) ? acc[mi][nf][h * 2 + 1] : 0.f;
                rsum += v0 + v1;
                hf h0, l0, h1, l1;
                h2split(v0, h0, l0);
                h2split(v1, h1, l1);
                *(__half2*)(P1 + (size_t)m * CC + cc) = __halves2half2(h0, h1);
                *(__half2*)(P2 + (size_t)m * CC + cc) = __halves2half2(l0, l1);
            }
            atomicAdd(&srs[m], rsum);
        }
    __syncthreads();
    if (tid < CC) g_RS[(size_t)b * TT + (size_t)c * CC + tid] = srs[tid] * QDN;
}

// per-chunk S[f,e] = V_c^T K_c (fp32 partials)
__global__ __launch_bounds__(512, 1) void ktv_tc()
{
    extern __shared__ char smdyn[];
    uint32_t sb = sm_u32(smdyn) + 1024;
    const int fi = blockIdx.x & 3, ei = blockIdx.x >> 2;
    const int c = blockIdx.y, b = blockIdx.z;
    ACC_DECL();
    const size_t aoff = ((size_t)(b * EE + fi * 128)) * TT + (size_t)c * CC;
    const size_t boff = ((size_t)(b * EE + ei * 128)) * TT + (size_t)c * CC;
    gemm_core(g_VT1 + aoff, g_VT2 + aoff, TT, g_KT1 + boff, g_KT2 + boff, TT,
              2, sb, acc);
    EPI_SETUP();
#pragma unroll
    for (int mi = 0; mi < 2; mi++)
#pragma unroll
        for (int h = 0; h < 2; h++) {
            int m = er + mi * 16 + h * 8;
            float* sp = g_SP + ((size_t)(b * NCH + c) * EE + fi * 128 + m) * EE
                             + ei * 128;
#pragma unroll
            for (int nf = 0; nf < 4; nf++) {
                int cc = ec + nf * 8;
                *(float2*)&sp[cc] = make_float2(acc[mi][nf][h * 2 + 0],
                                                acc[mi][nf][h * 2 + 1]);
            }
        }
}

// O = (Q'@S_prev + P'@V) * dinv/1024 -> attn fp16 splits
__global__ __launch_bounds__(512, 1) void qspv_tc()
{
    extern __shared__ char smdyn[];
    uint32_t sb = sm_u32(smdyn) + 1024;
    const int n0 = blockIdx.x * 128, c = blockIdx.y, b = blockIdx.z;
    ACC_DECL();
    const size_t qoff = ((size_t)(b * TT + c * CC)) * EE;
    if (c > 0) {
        const size_t soff = ((size_t)(b * NCH + c) * EE + n0) * EE;
        gemm_core(g_Q1 + qoff, g_Q2 + qoff, EE, g_SC1 + soff, g_SC2 + soff, EE,
                  8, sb, acc);
    }
    const size_t poff = (size_t)(b * NCH + c) * CC * CC;
    const size_t voff = ((size_t)(b * EE + n0)) * TT + (size_t)c * CC;
    gemm_core(g_P1 + poff, g_P2 + poff, CC, g_VT1 + voff, g_VT2 + voff, TT,
              2, sb, acc);
    EPI_SETUP();
#pragma unroll
    for (int mi = 0; mi < 2; mi++)
#pragma unroll
        for (int h = 0; h < 2; h++) {
            int m = er + mi * 16 + h * 8;
            size_t row = (size_t)b * TT + (size_t)c * CC + m;
            float di = g_DI[row] * QDN;
            hf* A1 = g_A1 + row * EE + n0;
            hf* A2 = g_A2 + row * EE + n0;
#pragma unroll
            for (int nf = 0; nf < 4; nf++) {
                int cc = ec + nf * 8;
                float v0 = acc[mi][nf][h * 2 + 0] * di;
                float v1 = acc[mi][nf][h * 2 + 1] * di;
                hf h0, l0, h1, l1;
                h2split(v0, h0, l0);
                h2split(v1, h1, l1);
                *(__half2*)(A1 + cc) = __halves2half2(h0, h1);
                *(__half2*)(A2 + cc) = __halves2half2(l0, l1);
            }
        }
}

// out = A @ o_w^T + o_b (fp32)
__global__ __launch_bounds__(512, 1) void out_tc(
    const float* __restrict__ ob, float* __restrict__ out)
{
    extern __shared__ char smdyn[];
    uint32_t sb = sm_u32(smdyn) + 1024;
    const int b = blockIdx.z, t0 = blockIdx.x * 128, o0 = blockIdx.y * 128;
    ACC_DECL();
    const size_t aoff = ((size_t)(b * TT + t0)) * EE;
    const size_t woff = (size_t)3 * EE * EE + (size_t)o0 * EE;
    gemm_core(g_A1 + aoff, g_A2 + aoff, EE, g_W1 + woff, g_W2 + woff, EE,
              8, sb, acc);
    EPI_SETUP();
#pragma unroll
    for (int mi = 0; mi < 2; mi++)
#pragma unroll
        for (int h = 0; h < 2; h++) {
            int t = t0 + er + mi * 16 + h * 8;
            float* orow = out + ((size_t)b * TT + t) * EE + o0;
#pragma unroll
            for (int nf = 0; nf < 4; nf++) {
                int cc = ec + nf * 8;
                *(float2*)&orow[cc] = make_float2(
                    acc[mi][nf][h * 2 + 0] + ob[o0 + cc],
                    acc[mi][nf][h * 2 + 1] + ob[o0 + cc + 1]);
            }
        }
}

// ===========================================================================
extern "C" void kernel_launch(void* const* d_in, const int* in_sizes, int n_in,
                              void* d_out, int out_size)
{
    (void)in_sizes; (void)n_in; (void)out_size;
    const float* x    = (const float*)d_in[0];
    const float* toep = (const float*)d_in[1];
    const float* q_w  = (const float*)d_in[2];
    const float* q_b  = (const float*)d_in[3];
    const float* k_w  = (const float*)d_in[4];
    const float* k_b  = (const float*)d_in[5];
    const float* v_w  = (const float*)d_in[6];
    const float* v_b  = (const float*)d_in[7];
    const float* o_w  = (const float*)d_in[8];
    const float* o_b  = (const float*)d_in[9];
    float* out = (float*)d_out;

    cudaFuncSetAttribute(proj_tc, cudaFuncAttributeMaxDynamicSharedMemorySize, SMEM_BYTES);
    cudaFuncSetAttribute(p_tc,    cudaFuncAttributeMaxDynamicSharedMemorySize, SMEM_BYTES);
    cudaFuncSetAttribute(ktv_tc,  cudaFuncAttributeMaxDynamicSharedMemorySize, SMEM_BYTES);
    cudaFuncSetAttribute(qspv_tc, cudaFuncAttributeMaxDynamicSharedMemorySize, SMEM_BYTES);
    cudaFuncSetAttribute(out_tc,  cudaFuncAttributeMaxDynamicSharedMemorySize, SMEM_BYTES);

    prep_w<<<4096, 256>>>(q_w, k_w, v_w, o_w);
    trans_x<<<dim3(TT / 32, EE / 32, BB), dim3(32, 8)>>>(x);

    proj_tc<<<dim3(TT / 128, EE / 128, 3 * BB), 512, SMEM_BYTES>>>(q_b, k_b, v_b, toep);

    softmax_split<<<NT, 256>>>();
    trans_split_K<<<dim3(TT / 32, EE / 32, BB), dim3(32, 8)>>>();
    trans_split_V<<<dim3(TT / 32, EE / 32, BB), dim3(32, 8)>>>();
    z_colsum<<<dim3(NCH, BB), 512>>>();
    z_scan<<<BB, 512>>>();

    p_tc<<<dim3(NCH, BB), 512, SMEM_BYTES>>>();
    ktv_tc<<<dim3(16, NCH, BB), 512, SMEM_BYTES>>>();
    prefix_S<<<2048, 256>>>();
    dinv_kernel<<<NT / 8, 256>>>();
    qspv_tc<<<dim3(EE / 128, NCH, BB), 512, SMEM_BYTES>>>();
    out_tc<<<dim3(TT / 128, EE / 128, BB), 512, SMEM_BYTES>>>(o_b, out);
}

// round 9
// speedup vs baseline: 2.4852x; 1.1682x over previous
#include <cuda_runtime.h>
#include <cuda_fp16.h>
#include <cstdint>
#include <math.h>

// ===========================================================================
// LinearAttentionToeplitz — fp16x2 error-compensated mma.sync pipeline, v3.
// 512 threads/CTA, 32x32 warp tiles, 3-stage cp.async ring, shared-fragment
// 3-pass compute (8 LDSM4 : 24 MMA per ks), K/V split+transpose+colsum fused
// into the projection epilogue.
// ===========================================================================

#define BB 8
#define TT 2048
#define EE 512
#define CC 128
#define NCH 16
#define NT (BB*TT)
#define NTE (NT*EE)
#define EPS_D 1e-3f
#define QSCALE 0.044194173824159216f
#define QUP 1024.0f
#define QDN (1.0f/1024.0f)
#define SPN ((size_t)BB*NCH*EE*EE)
#define STAGE_BYTES 65536
#define SMEM_BYTES (1024 + 3*STAGE_BYTES)

typedef __half hf;

// ---------------- device scratch ----------------
__device__ __align__(16) float g_Q[NTE];    // fp32 q (true scale)
__device__ __align__(16) float g_SP[SPN];   // per-chunk S partial [f][e]
__device__ float g_RS[NT];
__device__ float g_DI[NT];
__device__ float g_ZC[BB*NCH*EE];
__device__ float g_ZS[BB*NCH*EE];

__device__ __align__(16) hf g_xT1[NTE], g_xT2[NTE];   // x^T [t][e]
__device__ __align__(16) hf g_Q1[NTE],  g_Q2[NTE];    // 1024*q rows
__device__ __align__(16) hf g_K1[NTE],  g_K2[NTE];    // expk rows
__device__ __align__(16) hf g_KT1[NTE], g_KT2[NTE];   // expk^T [e][t]
__device__ __align__(16) hf g_VT1[NTE], g_VT2[NTE];   // v^T    [f][t]
__device__ __align__(16) hf g_A1[NTE],  g_A2[NTE];    // attn   [t][e]
__device__ __align__(16) hf g_P1[BB*NCH*CC*CC], g_P2[BB*NCH*CC*CC]; // 1024*P
__device__ __align__(16) hf g_SC1[SPN], g_SC2[SPN];   // S prefix [f][e]
__device__ __align__(16) hf g_W1[4*EE*EE], g_W2[4*EE*EE];

// ---------------- helpers ----------------
__device__ __forceinline__ uint32_t sm_u32(const void* p) {
    uint32_t a;
    asm("{ .reg .u64 t; cvta.to.shared.u64 t, %1; cvt.u32.u64 %0, t; }"
        : "=r"(a) : "l"(p));
    return a;
}
__device__ __forceinline__ void h2split(float v, hf& h, hf& l) {
    h = __float2half_rn(v);
    l = __float2half_rn(v - __half2float(h));
}
__device__ __forceinline__ uint32_t swz(int row, int seg) {
    return (uint32_t)(row * 128 + ((seg ^ (row & 7)) << 4));
}

#define LDSM4(r, addr)                                                         \
    asm volatile("ldmatrix.sync.aligned.m8n8.x4.shared.b16 {%0,%1,%2,%3}, [%4];" \
                 : "=r"((r)[0]), "=r"((r)[1]), "=r"((r)[2]), "=r"((r)[3])      \
                 : "r"(addr))

#define MMA16816(d, a, b)                                                      \
    asm volatile("mma.sync.aligned.m16n8k16.row.col.f32.f16.f16.f32 "          \
                 "{%0,%1,%2,%3}, {%4,%5,%6,%7}, {%8,%9}, {%0,%1,%2,%3};"       \
                 : "+f"((d)[0]), "+f"((d)[1]), "+f"((d)[2]), "+f"((d)[3])      \
                 : "r"((a)[0]), "r"((a)[1]), "r"((a)[2]), "r"((a)[3]),         \
                   "r"((b)[0]), "r"((b)[1]))

// ---------------- cp.async staging: 4 tiles (Ah,Al,Bh,Bl) [128][64] hf ------
__device__ __forceinline__ void ld_stage(
    uint32_t st,
    const hf* __restrict__ A1, const hf* __restrict__ A2, size_t ldA,
    const hf* __restrict__ B1, const hf* __restrict__ B2, size_t ldB,
    int kc, int tid)
{
    const hf* gp[4] = {A1, A2, B1, B2};
    const size_t ldb[4] = {ldA * 2, ldA * 2, ldB * 2, ldB * 2};
#pragma unroll
    for (int t = 0; t < 4; t++) {
        const char* g0 = (const char*)gp[t] + (size_t)kc * 128;
#pragma unroll
        for (int i = 0; i < 2; i++) {
            int c = tid + i * 512;
            int row = c >> 3, seg = c & 7;
            uint32_t d = st + t * 16384 + swz(row, seg);
            const void* s = g0 + (size_t)row * ldb[t] + seg * 16;
            asm volatile("cp.async.cg.shared.global [%0], [%1], 16;"
                         :: "r"(d), "l"(s) : "memory");
        }
    }
    asm volatile("cp.async.commit_group;" ::: "memory");
}

// ---------------- per-ktile compute: shared fragments, 3 passes -------------
__device__ __forceinline__ void compute_tile(
    float (&acc)[2][4][4], uint32_t stage, int warpM, int warpN, int lane)
{
    const int l7 = lane & 7;
    const int aSel = lane >> 4;
    const int bSel = (lane >> 3) & 1;
    const int aR = ((lane >> 3) & 1) * 8 + l7;
    const int bR = (lane >> 4) * 8 + l7;
    const uint32_t aRow0 = (uint32_t)((warpM + aR) * 128);
    const uint32_t aRow1 = (uint32_t)((warpM + 16 + aR) * 128);
    const uint32_t bRow0 = (uint32_t)((warpN + bR) * 128);
    const uint32_t bRow1 = (uint32_t)((warpN + 16 + bR) * 128);
#pragma unroll
    for (int ks = 0; ks < 4; ks++) {
        const uint32_t ax = (uint32_t)(((ks * 2 + aSel) ^ l7) << 4);
        const uint32_t bx = (uint32_t)(((ks * 2 + bSel) ^ l7) << 4);
        uint32_t a0h[4], a1h[4], a0l[4], a1l[4];
        uint32_t b0h[4], b1h[4], b0l[4], b1l[4];
        LDSM4(a0h, stage + aRow0 + ax);
        LDSM4(a1h, stage + aRow1 + ax);
        LDSM4(a0l, stage + 16384u + aRow0 + ax);
        LDSM4(a1l, stage + 16384u + aRow1 + ax);
        LDSM4(b0h, stage + 32768u + bRow0 + bx);
        LDSM4(b1h, stage + 32768u + bRow1 + bx);
        LDSM4(b0l, stage + 49152u + bRow0 + bx);
        LDSM4(b1l, stage + 49152u + bRow1 + bx);
        // pass hh
        MMA16816(acc[0][0], a0h, b0h + 0); MMA16816(acc[0][1], a0h, b0h + 2);
        MMA16816(acc[0][2], a0h, b1h + 0); MMA16816(acc[0][3], a0h, b1h + 2);
        MMA16816(acc[1][0], a1h, b0h + 0); MMA16816(acc[1][1], a1h, b0h + 2);
        MMA16816(acc[1][2], a1h, b1h + 0); MMA16816(acc[1][3], a1h, b1h + 2);
        // pass hl
        MMA16816(acc[0][0], a0h, b0l + 0); MMA16816(acc[0][1], a0h, b0l + 2);
        MMA16816(acc[0][2], a0h, b1l + 0); MMA16816(acc[0][3], a0h, b1l + 2);
        MMA16816(acc[1][0], a1h, b0l + 0); MMA16816(acc[1][1], a1h, b0l + 2);
        MMA16816(acc[1][2], a1h, b1l + 0); MMA16816(acc[1][3], a1h, b1l + 2);
        // pass lh
        MMA16816(acc[0][0], a0l, b0h + 0); MMA16816(acc[0][1], a0l, b0h + 2);
        MMA16816(acc[0][2], a0l, b1h + 0); MMA16816(acc[0][3], a0l, b1h + 2);
        MMA16816(acc[1][0], a1l, b0h + 0); MMA16816(acc[1][1], a1l, b0h + 2);
        MMA16816(acc[1][2], a1l, b1h + 0); MMA16816(acc[1][3], a1l, b1h + 2);
    }
}

// ---------------- 3-stage ring GEMM core (accumulating) ---------------------
__device__ void gemm_core(const hf* A1, const hf* A2, size_t ldA,
                          const hf* B1, const hf* B2, size_t ldB,
                          int nK, uint32_t sb, float (&acc)[2][4][4])
{
    const int tid = threadIdx.x;
    const int lane = tid & 31, wid = tid >> 5;
    const int warpM = (wid & 3) * 32, warpN = (wid >> 2) * 32;
    ld_stage(sb, A1, A2, ldA, B1, B2, ldB, 0, tid);
    if (nK > 1) ld_stage(sb + STAGE_BYTES, A1, A2, ldA, B1, B2, ldB, 1, tid);
    for (int kc = 0; kc < nK; kc++) {
        if (kc + 1 < nK) asm volatile("cp.async.wait_group 1;" ::: "memory");
        else             asm volatile("cp.async.wait_group 0;" ::: "memory");
        __syncthreads();
        if (kc + 2 < nK)
            ld_stage(sb + ((kc + 2) % 3) * STAGE_BYTES,
                     A1, A2, ldA, B1, B2, ldB, kc + 2, tid);
        compute_tile(acc, sb + (kc % 3) * STAGE_BYTES, warpM, warpN, lane);
    }
    __syncthreads();
}

#define ACC_DECL()                                                             \
    float acc[2][4][4];                                                        \
    _Pragma("unroll") for (int _i = 0; _i < 2; _i++)                           \
        _Pragma("unroll") for (int _j = 0; _j < 4; _j++)                       \
            _Pragma("unroll") for (int _r = 0; _r < 4; _r++)                   \
                acc[_i][_j][_r] = 0.f;

#define EPI_SETUP()                                                            \
    const int lane = threadIdx.x & 31, wid = threadIdx.x >> 5;                 \
    const int warpM = (wid & 3) * 32, warpN = (wid >> 2) * 32;                 \
    const int er = warpM + (lane >> 2);                                        \
    const int ec = warpN + (lane & 3) * 2;

// ===========================================================================
// aux kernels
// ===========================================================================

__global__ __launch_bounds__(512) void zero_zs()
{
    int i = blockIdx.x * 512 + threadIdx.x;     // 65536 total
    g_ZS[i] = 0.f;
}

__global__ __launch_bounds__(256) void prep_w(
    const float* __restrict__ qw, const float* __restrict__ kw,
    const float* __restrict__ vw, const float* __restrict__ ow)
{
    int i = blockIdx.x * 256 + threadIdx.x;
    int m = i >> 18;
    const float* src = (m == 0) ? qw : (m == 1) ? kw : (m == 2) ? vw : ow;
    float v = src[i & (EE * EE - 1)];
    h2split(v, g_W1[i], g_W2[i]);
}

__global__ __launch_bounds__(256) void trans_x(const float* __restrict__ x)
{
    __shared__ float tile[32][33];
    const int b = blockIdx.z, t0 = blockIdx.x * 32, e0 = blockIdx.y * 32;
    const int tx = threadIdx.x, ty = threadIdx.y;
#pragma unroll
    for (int j = 0; j < 4; j++) {
        int e = e0 + ty + j * 8;
        tile[tx][ty + j * 8] = x[((size_t)(b * EE + e)) * TT + t0 + tx];
    }
    __syncthreads();
#pragma unroll
    for (int j = 0; j < 4; j++) {
        int r = ty + j * 8;
        float v = tile[r][tx];
        size_t o = ((size_t)(b * TT + t0 + r)) * EE + e0 + tx;
        h2split(v, g_xT1[o], g_xT2[o]);
    }
}

__global__ __launch_bounds__(256) void softmax_split()
{
    size_t row = blockIdx.x;
    float* r = g_Q + row * EE;
    int tid = threadIdx.x;
    float v0 = r[tid], v1 = r[tid + 256];
    __shared__ float red[256];
    red[tid] = fmaxf(v0, v1);
    __syncthreads();
    for (int s = 128; s > 0; s >>= 1) {
        if (tid < s) red[tid] = fmaxf(red[tid], red[tid + s]);
        __syncthreads();
    }
    float m = red[0];
    __syncthreads();
    float e0 = expf(v0 - m), e1 = expf(v1 - m);
    red[tid] = e0 + e1;
    __syncthreads();
    for (int s = 128; s > 0; s >>= 1) {
        if (tid < s) red[tid] += red[tid + s];
        __syncthreads();
    }
    float sc = QSCALE / red[0];
    float q0 = e0 * sc, q1 = e1 * sc;
    r[tid] = q0; r[tid + 256] = q1;
    size_t o0 = row * EE + tid, o1 = o0 + 256;
    h2split(q0 * QUP, g_Q1[o0], g_Q2[o0]);
    h2split(q1 * QUP, g_Q1[o1], g_Q2[o1]);
}

// exclusive scan over chunk colsums (g_ZS filled by proj epilogue atomics)
__global__ __launch_bounds__(512) void z_scan()
{
    int b = blockIdx.x, e = threadIdx.x;
    float run = 0.f;
    for (int c = 0; c < NCH; c++) {
        size_t o = ((size_t)b * NCH + c) * EE + e;
        g_ZC[o] = run;
        run += g_ZS[o];
    }
}

__global__ __launch_bounds__(256) void prefix_S()
{
    int gid = blockIdx.x * 256 + threadIdx.x;
    int b = gid >> 16;
    int p4 = gid & 65535;
    size_t base = ((size_t)b * NCH) * EE * EE + (size_t)p4 * 4;
    float4 run = make_float4(0.f, 0.f, 0.f, 0.f);
    for (int c = 0; c < NCH; c++) {
        size_t o = base + (size_t)c * EE * EE;
        float rv[4] = {run.x, run.y, run.z, run.w};
        hf h[4], l[4];
#pragma unroll
        for (int j = 0; j < 4; j++) h2split(rv[j], h[j], l[j]);
        *(__half2*)(g_SC1 + o)     = __halves2half2(h[0], h[1]);
        *(__half2*)(g_SC1 + o + 2) = __halves2half2(h[2], h[3]);
        *(__half2*)(g_SC2 + o)     = __halves2half2(l[0], l[1]);
        *(__half2*)(g_SC2 + o + 2) = __halves2half2(l[2], l[3]);
        float4 s = *(const float4*)(g_SP + o);
        run.x += s.x; run.y += s.y; run.z += s.z; run.w += s.w;
    }
}

__global__ __launch_bounds__(256) void dinv_kernel()
{
    int w = blockIdx.x * 8 + (threadIdx.x >> 5);
    int lane = threadIdx.x & 31;
    int b = w >> 11, t = w & 2047, c = t >> 7;
    const float* q = g_Q + (size_t)w * EE;
    const float* z = g_ZC + ((size_t)b * NCH + c) * EE;
    float s = 0.f;
#pragma unroll
    for (int i = 0; i < 16; i++) s += q[lane + 32 * i] * z[lane + 32 * i];
#pragma unroll
    for (int o = 16; o > 0; o >>= 1) s += __shfl_xor_sync(0xffffffffu, s, o);
    if (lane == 0) g_DI[w] = 1.f / fmaxf(s + g_RS[w], EPS_D);
}

// ===========================================================================
// GEMM kernels (512 threads)
// ===========================================================================

// merged projections; fused epilogues:
//   mode 0 (Q): fp32 g_Q rows (softmax later)
//   mode 1 (K): exp -> row splits K1/K2, transposed splits KT1/KT2, colsums
//   mode 2 (V): *toep -> transposed splits VT1/VT2
__global__ __launch_bounds__(512, 1) void proj_tc(
    const float* __restrict__ qb, const float* __restrict__ kb,
    const float* __restrict__ vb, const float* __restrict__ toep)
{
    extern __shared__ char smdyn[];
    uint32_t sb = sm_u32(smdyn) + 1024;
    const int mode = blockIdx.z >> 3, b = blockIdx.z & 7;
    const int t0 = blockIdx.x * 128, o0 = blockIdx.y * 128;
    ACC_DECL();
    const size_t aoff = ((size_t)(b * TT + t0)) * EE;
    const size_t woff = (size_t)mode * EE * EE + (size_t)o0 * EE;
    gemm_core(g_xT1 + aoff, g_xT2 + aoff, EE, g_W1 + woff, g_W2 + woff, EE,
              8, sb, acc);
    EPI_SETUP();
    const float* bias = (mode == 0) ? qb : (mode == 1) ? kb : vb;
    float* smf = (float*)(smdyn + 1024);          // [128 o][132] fp32 stage

    if (mode == 0) {
#pragma unroll
        for (int mi = 0; mi < 2; mi++)
#pragma unroll
            for (int h = 0; h < 2; h++) {
                int t = t0 + er + mi * 16 + h * 8;
                float* orow = g_Q + ((size_t)b * TT + t) * EE + o0;
#pragma unroll
                for (int nf = 0; nf < 4; nf++) {
                    int cc = ec + nf * 8;
                    *(float2*)&orow[cc] = make_float2(
                        acc[mi][nf][h * 2 + 0] + bias[o0 + cc],
                        acc[mi][nf][h * 2 + 1] + bias[o0 + cc + 1]);
                }
            }
        return;
    }

    // modes 1/2: compute values, stage transposed, (K: rows + colsum)
    float csum[4][2] = {{0.f,0.f},{0.f,0.f},{0.f,0.f},{0.f,0.f}};
#pragma unroll
    for (int mi = 0; mi < 2; mi++)
#pragma unroll
        for (int h = 0; h < 2; h++) {
            int m = er + mi * 16 + h * 8;
            int t = t0 + m;
            float tw = (mode == 2) ? toep[t] : 1.f;
            hf* K1r = g_K1 + ((size_t)b * TT + t) * EE + o0;
            hf* K2r = g_K2 + ((size_t)b * TT + t) * EE + o0;
#pragma unroll
            for (int nf = 0; nf < 4; nf++) {
                int cc = ec + nf * 8;
                float v0 = acc[mi][nf][h * 2 + 0] + bias[o0 + cc];
                float v1 = acc[mi][nf][h * 2 + 1] + bias[o0 + cc + 1];
                if (mode == 1) {
                    v0 = expf(v0); v1 = expf(v1);
                    csum[nf][0] += v0; csum[nf][1] += v1;
                    hf h0, l0, h1, l1;
                    h2split(v0, h0, l0);
                    h2split(v1, h1, l1);
                    *(__half2*)(K1r + cc) = __halves2half2(h0, h1);
                    *(__half2*)(K2r + cc) = __halves2half2(l0, l1);
                } else {
                    v0 *= tw; v1 *= tw;
                }
                smf[cc * 132 + m] = v0;
                smf[(cc + 1) * 132 + m] = v1;
            }
        }
    if (mode == 1) {
        const int chunk = t0 >> 7;
        float* zrow = g_ZS + ((size_t)b * NCH + chunk) * EE + o0;
#pragma unroll
        for (int nf = 0; nf < 4; nf++) {
            atomicAdd(&zrow[ec + nf * 8],     csum[nf][0]);
            atomicAdd(&zrow[ec + nf * 8 + 1], csum[nf][1]);
        }
    }
    __syncthreads();
    // transposed writes: warp w handles e-rows [w*8, w*8+8), lane covers 4 t's
    hf* T1 = (mode == 1) ? g_KT1 : g_VT1;
    hf* T2 = (mode == 1) ? g_KT2 : g_VT2;
#pragma unroll
    for (int i = 0; i < 8; i++) {
        int e = wid * 8 + i;
        float4 vv = *(float4*)&smf[e * 132 + 4 * lane];
        hf h0, l0, h1, l1, h2, l2, h3, l3;
        h2split(vv.x, h0, l0); h2split(vv.y, h1, l1);
        h2split(vv.z, h2, l2); h2split(vv.w, h3, l3);
        size_t o = ((size_t)(b * EE + o0 + e)) * TT + t0 + 4 * lane;
        *(__half2*)(T1 + o)     = __halves2half2(h0, h1);
        *(__half2*)(T1 + o + 2) = __halves2half2(h2, h3);
        *(__half2*)(T2 + o)     = __halves2half2(l0, l1);
        *(__half2*)(T2 + o + 2) = __halves2half2(l2, l3);
    }
}

// P' = mask(Q' K^T): fp16 splits + true rowsums
__global__ __launch_bounds__(512, 1) void p_tc()
{
    extern __shared__ char smdyn[];
    uint32_t sb = sm_u32(smdyn) + 1024;
    float* srs = (float*)smdyn;
    const int c = blockIdx.x, b = blockIdx.y;
    const int tid = threadIdx.x;
    if (tid < CC) srs[tid] = 0.f;
    ACC_DECL();
    const size_t off = ((size_t)(b * TT + c * CC)) * EE;
    gemm_core(g_Q1 + off, g_Q2 + off, EE, g_K1 + off, g_K2 + off, EE,
              8, sb, acc);
    EPI_SETUP();
    hf* P1 = g_P1 + (size_t)(b * NCH + c) * CC * CC;
    hf* P2 = g_P2 + (size_t)(b * NCH + c) * CC * CC;
#pragma unroll
    for (int mi = 0; mi < 2; mi++)
#pragma unroll
        for (int h = 0; h < 2; h++) {
            int m = er + mi * 16 + h * 8;
            float rsum = 0.f;
#pragma unroll
            for (int nf = 0; nf < 4; nf++) {
                int cc = ec + nf * 8;
                float v0 = (cc     <= m) ? acc[mi][nf][h * 2 + 0] : 0.f;
                float v1 = (cc + 1 <= m) ? acc[mi][nf][h * 2 + 1] : 0.f;
                rsum += v0 + v1;
                hf h0, l0, h1, l1;
                h2split(v0, h0, l0);
                h2split(v1, h1, l1);
                *(__half2*)(P1 + (size_t)m * CC + cc) = __halves2half2(h0, h1);
                *(__half2*)(P2 + (size_t)m * CC + cc) = __halves2half2(l0, l1);
            }
            atomicAdd(&srs[m], rsum);
        }
    __syncthreads();
    if (tid < CC) g_RS[(size_t)b * TT + (size_t)c * CC + tid] = srs[tid] * QDN;
}

// per-chunk S[f,e] = V_c^T K_c (fp32 partials)
__global__ __launch_bounds__(512, 1) void ktv_tc()
{
    extern __shared__ char smdyn[];
    uint32_t sb = sm_u32(smdyn) + 1024;
    const int fi = blockIdx.x & 3, ei = blockIdx.x >> 2;
    const int c = blockIdx.y, b = blockIdx.z;
    ACC_DECL();
    const size_t aoff = ((size_t)(b * EE + fi * 128)) * TT + (size_t)c * CC;
    const size_t boff = ((size_t)(b * EE + ei * 128)) * TT + (size_t)c * CC;
    gemm_core(g_VT1 + aoff, g_VT2 + aoff, TT, g_KT1 + boff, g_KT2 + boff, TT,
              2, sb, acc);
    EPI_SETUP();
#pragma unroll
    for (int mi = 0; mi < 2; mi++)
#pragma unroll
        for (int h = 0; h < 2; h++) {
            int m = er + mi * 16 + h * 8;
            float* sp = g_SP + ((size_t)(b * NCH + c) * EE + fi * 128 + m) * EE
                             + ei * 128;
#pragma unroll
            for (int nf = 0; nf < 4; nf++) {
                int cc = ec + nf * 8;
                *(float2*)&sp[cc] = make_float2(acc[mi][nf][h * 2 + 0],
                                                acc[mi][nf][h * 2 + 1]);
            }
        }
}

// O = (Q'@S_prev + P'@V) * dinv/1024 -> attn fp16 splits
__global__ __launch_bounds__(512, 1) void qspv_tc()
{
    extern __shared__ char smdyn[];
    uint32_t sb = sm_u32(smdyn) + 1024;
    const int n0 = blockIdx.x * 128, c = blockIdx.y, b = blockIdx.z;
    ACC_DECL();
    const size_t qoff = ((size_t)(b * TT + c * CC)) * EE;
    if (c > 0) {
        const size_t soff = ((size_t)(b * NCH + c) * EE + n0) * EE;
        gemm_core(g_Q1 + qoff, g_Q2 + qoff, EE, g_SC1 + soff, g_SC2 + soff, EE,
                  8, sb, acc);
    }
    const size_t poff = (size_t)(b * NCH + c) * CC * CC;
    const size_t voff = ((size_t)(b * EE + n0)) * TT + (size_t)c * CC;
    gemm_core(g_P1 + poff, g_P2 + poff, CC, g_VT1 + voff, g_VT2 + voff, TT,
              2, sb, acc);
    EPI_SETUP();
#pragma unroll
    for (int mi = 0; mi < 2; mi++)
#pragma unroll
        for (int h = 0; h < 2; h++) {
            int m = er + mi * 16 + h * 8;
            size_t row = (size_t)b * TT + (size_t)c * CC + m;
            float di = g_DI[row] * QDN;
            hf* A1 = g_A1 + row * EE + n0;
            hf* A2 = g_A2 + row * EE + n0;
#pragma unroll
            for (int nf = 0; nf < 4; nf++) {
                int cc = ec + nf * 8;
                float v0 = acc[mi][nf][h * 2 + 0] * di;
                float v1 = acc[mi][nf][h * 2 + 1] * di;
                hf h0, l0, h1, l1;
                h2split(v0, h0, l0);
                h2split(v1, h1, l1);
                *(__half2*)(A1 + cc) = __halves2half2(h0, h1);
                *(__half2*)(A2 + cc) = __halves2half2(l0, l1);
            }
        }
}

// out = A @ o_w^T + o_b (fp32)
__global__ __launch_bounds__(512, 1) void out_tc(
    const float* __restrict__ ob, float* __restrict__ out)
{
    extern __shared__ char smdyn[];
    uint32_t sb = sm_u32(smdyn) + 1024;
    const int b = blockIdx.z, t0 = blockIdx.x * 128, o0 = blockIdx.y * 128;
    ACC_DECL();
    const size_t aoff = ((size_t)(b * TT + t0)) * EE;
    const size_t woff = (size_t)3 * EE * EE + (size_t)o0 * EE;
    gemm_core(g_A1 + aoff, g_A2 + aoff, EE, g_W1 + woff, g_W2 + woff, EE,
              8, sb, acc);
    EPI_SETUP();
#pragma unroll
    for (int mi = 0; mi < 2; mi++)
#pragma unroll
        for (int h = 0; h < 2; h++) {
            int t = t0 + er + mi * 16 + h * 8;
            float* orow = out + ((size_t)b * TT + t) * EE + o0;
#pragma unroll
            for (int nf = 0; nf < 4; nf++) {
                int cc = ec + nf * 8;
                *(float2*)&orow[cc] = make_float2(
                    acc[mi][nf][h * 2 + 0] + ob[o0 + cc],
                    acc[mi][nf][h * 2 + 1] + ob[o0 + cc + 1]);
            }
        }
}

// ===========================================================================
extern "C" void kernel_launch(void* const* d_in, const int* in_sizes, int n_in,
                              void* d_out, int out_size)
{
    (void)in_sizes; (void)n_in; (void)out_size;
    const float* x    = (const float*)d_in[0];
    const float* toep = (const float*)d_in[1];
    const float* q_w  = (const float*)d_in[2];
    const float* q_b  = (const float*)d_in[3];
    const float* k_w  = (const float*)d_in[4];
    const float* k_b  = (const float*)d_in[5];
    const float* v_w  = (const float*)d_in[6];
    const float* v_b  = (const float*)d_in[7];
    const float* o_w  = (const float*)d_in[8];
    const float* o_b  = (const float*)d_in[9];
    float* out = (float*)d_out;

    cudaFuncSetAttribute(proj_tc, cudaFuncAttributeMaxDynamicSharedMemorySize, SMEM_BYTES);
    cudaFuncSetAttribute(p_tc,    cudaFuncAttributeMaxDynamicSharedMemorySize, SMEM_BYTES);
    cudaFuncSetAttribute(ktv_tc,  cudaFuncAttributeMaxDynamicSharedMemorySize, SMEM_BYTES);
    cudaFuncSetAttribute(qspv_tc, cudaFuncAttributeMaxDynamicSharedMemorySize, SMEM_BYTES);
    cudaFuncSetAttribute(out_tc,  cudaFuncAttributeMaxDynamicSharedMemorySize, SMEM_BYTES);

    zero_zs<<<128, 512>>>();
    prep_w<<<4096, 256>>>(q_w, k_w, v_w, o_w);
    trans_x<<<dim3(TT / 32, EE / 32, BB), dim3(32, 8)>>>(x);

    proj_tc<<<dim3(TT / 128, EE / 128, 3 * BB), 512, SMEM_BYTES>>>(q_b, k_b, v_b, toep);

    softmax_split<<<NT, 256>>>();
    z_scan<<<BB, 512>>>();

    p_tc<<<dim3(NCH, BB), 512, SMEM_BYTES>>>();
    ktv_tc<<<dim3(16, NCH, BB), 512, SMEM_BYTES>>>();
    prefix_S<<<2048, 256>>>();
    dinv_kernel<<<NT / 8, 256>>>();
    qspv_tc<<<dim3(EE / 128, NCH, BB), 512, SMEM_BYTES>>>();
    out_tc<<<dim3(TT / 128, EE / 128, BB), 512, SMEM_BYTES>>>(o_b, out);
}

// round 10
// speedup vs baseline: 2.7080x; 1.0896x over previous
#include <cuda_runtime.h>
#include <cuda_fp16.h>
#include <cstdint>
#include <math.h>

// ===========================================================================
// LinearAttentionToeplitz — fp16x2 error-compensated mma.sync pipeline, v4.
// 256-thread CTAs (2 CTAs/SM, overlapping barrier domains), 64x32 warp tiles
// (4:1 MMA:LDSM), k-tile 32 with 3-stage cp.async ring, 2-bit 64B-row swizzle.
// 3 passes (hh+hl+lh) ~22-bit effective mantissa.
// ===========================================================================

#define BB 8
#define TT 2048
#define EE 512
#define CC 128
#define NCH 16
#define NT (BB*TT)
#define NTE (NT*EE)
#define EPS_D 1e-3f
#define QSCALE 0.044194173824159216f
#define QUP 1024.0f
#define QDN (1.0f/1024.0f)
#define SPN ((size_t)BB*NCH*EE*EE)
#define STAGE_BYTES 32768              // 4 tiles x [128][32] fp16
#define SMEM_BYTES (1024 + 3*STAGE_BYTES)

typedef __half hf;

// ---------------- device scratch ----------------
__device__ __align__(16) float g_Q[NTE];    // fp32 q (true scale)
__device__ __align__(16) float g_SP[SPN];   // per-chunk S partial [f][e]
__device__ float g_RS[NT];
__device__ float g_DI[NT];
__device__ float g_ZC[BB*NCH*EE];
__device__ float g_ZS[BB*NCH*EE];

__device__ __align__(16) hf g_xT1[NTE], g_xT2[NTE];   // x^T [t][e]
__device__ __align__(16) hf g_Q1[NTE],  g_Q2[NTE];    // 1024*q rows
__device__ __align__(16) hf g_K1[NTE],  g_K2[NTE];    // expk rows
__device__ __align__(16) hf g_KT1[NTE], g_KT2[NTE];   // expk^T [e][t]
__device__ __align__(16) hf g_VT1[NTE], g_VT2[NTE];   // v^T    [f][t]
__device__ __align__(16) hf g_A1[NTE],  g_A2[NTE];    // attn   [t][e]
__device__ __align__(16) hf g_P1[BB*NCH*CC*CC], g_P2[BB*NCH*CC*CC]; // 1024*P
__device__ __align__(16) hf g_SC1[SPN], g_SC2[SPN];   // S prefix [f][e]
__device__ __align__(16) hf g_W1[4*EE*EE], g_W2[4*EE*EE];

// ---------------- helpers ----------------
__device__ __forceinline__ uint32_t sm_u32(const void* p) {
    uint32_t a;
    asm("{ .reg .u64 t; cvta.to.shared.u64 t, %1; cvt.u32.u64 %0, t; }"
        : "=r"(a) : "l"(p));
    return a;
}
__device__ __forceinline__ void h2split(float v, hf& h, hf& l) {
    h = __float2half_rn(v);
    l = __float2half_rn(v - __half2float(h));
}
// swizzle for [row][64B] tiles: 4 segs of 16B, seg' = seg ^ ((row>>1)&3)
__device__ __forceinline__ uint32_t swz(int row, int seg) {
    return (uint32_t)(row * 64 + ((seg ^ ((row >> 1) & 3)) << 4));
}

#define LDSM4(r, addr)                                                         \
    asm volatile("ldmatrix.sync.aligned.m8n8.x4.shared.b16 {%0,%1,%2,%3}, [%4];" \
                 : "=r"((r)[0]), "=r"((r)[1]), "=r"((r)[2]), "=r"((r)[3])      \
                 : "r"(addr))

#define MMA16816(d, a, b)                                                      \
    asm volatile("mma.sync.aligned.m16n8k16.row.col.f32.f16.f16.f32 "          \
                 "{%0,%1,%2,%3}, {%4,%5,%6,%7}, {%8,%9}, {%0,%1,%2,%3};"       \
                 : "+f"((d)[0]), "+f"((d)[1]), "+f"((d)[2]), "+f"((d)[3])      \
                 : "r"((a)[0]), "r"((a)[1]), "r"((a)[2]), "r"((a)[3]),         \
                   "r"((b)[0]), "r"((b)[1]))

// ---------------- cp.async staging: 4 tiles (Ah,Al,Bh,Bl) [128][32] hf ------
__device__ __forceinline__ void ld_stage(
    uint32_t st,
    const hf* __restrict__ A1, const hf* __restrict__ A2, size_t ldA,
    const hf* __restrict__ B1, const hf* __restrict__ B2, size_t ldB,
    int kc, int tid)
{
    const hf* gp[4] = {A1, A2, B1, B2};
    const size_t ldb[4] = {ldA * 2, ldA * 2, ldB * 2, ldB * 2};
#pragma unroll
    for (int t = 0; t < 4; t++) {
        const char* g0 = (const char*)gp[t] + (size_t)kc * 64;
#pragma unroll
        for (int i = 0; i < 2; i++) {
            int c = tid + i * 256;
            int row = c >> 2, seg = c & 3;
            uint32_t d = st + t * 8192u + swz(row, seg);
            const void* s = g0 + (size_t)row * ldb[t] + seg * 16;
            asm volatile("cp.async.cg.shared.global [%0], [%1], 16;"
                         :: "r"(d), "l"(s) : "memory");
        }
    }
    asm volatile("cp.async.commit_group;" ::: "memory");
}

// ---------------- per-ktile compute: 64x32 warp tile, 3 passes --------------
__device__ __forceinline__ void compute_tile(
    float (&acc)[4][4][4], uint32_t stage, int warpM, int warpN, int lane)
{
    const int l7 = lane & 7;
    const int aSel = lane >> 4;
    const int bSel = (lane >> 3) & 1;
    const int aR = ((lane >> 3) & 1) * 8 + l7;
    const int bR = (lane >> 4) * 8 + l7;
#pragma unroll
    for (int ks = 0; ks < 2; ks++) {
        uint32_t ah[4][4], al[4][4], bh[2][4], bl[2][4];
#pragma unroll
        for (int mi = 0; mi < 4; mi++) {
            int row = warpM + mi * 16 + aR;
            uint32_t off = swz(row, (ks * 2 + aSel) & 3) ^ 0u;
            // swz takes unswizzled seg: recompute properly
            off = (uint32_t)(row * 64 + (((ks * 2 + aSel) ^ ((row >> 1) & 3)) << 4));
            LDSM4(ah[mi], stage + off);
            LDSM4(al[mi], stage + 8192u + off);
        }
#pragma unroll
        for (int ni = 0; ni < 2; ni++) {
            int row = warpN + ni * 16 + bR;
            uint32_t off = (uint32_t)(row * 64 + (((ks * 2 + bSel) ^ ((row >> 1) & 3)) << 4));
            LDSM4(bh[ni], stage + 16384u + off);
            LDSM4(bl[ni], stage + 24576u + off);
        }
        // pass hh
#pragma unroll
        for (int mi = 0; mi < 4; mi++) {
            MMA16816(acc[mi][0], ah[mi], bh[0] + 0);
            MMA16816(acc[mi][1], ah[mi], bh[0] + 2);
            MMA16816(acc[mi][2], ah[mi], bh[1] + 0);
            MMA16816(acc[mi][3], ah[mi], bh[1] + 2);
        }
        // pass hl
#pragma unroll
        for (int mi = 0; mi < 4; mi++) {
            MMA16816(acc[mi][0], ah[mi], bl[0] + 0);
            MMA16816(acc[mi][1], ah[mi], bl[0] + 2);
            MMA16816(acc[mi][2], ah[mi], bl[1] + 0);
            MMA16816(acc[mi][3], ah[mi], bl[1] + 2);
        }
        // pass lh
#pragma unroll
        for (int mi = 0; mi < 4; mi++) {
            MMA16816(acc[mi][0], al[mi], bh[0] + 0);
            MMA16816(acc[mi][1], al[mi], bh[0] + 2);
            MMA16816(acc[mi][2], al[mi], bh[1] + 0);
            MMA16816(acc[mi][3], al[mi], bh[1] + 2);
        }
    }
}

// ---------------- 3-stage ring GEMM core (accumulating) ---------------------
__device__ void gemm_core(const hf* A1, const hf* A2, size_t ldA,
                          const hf* B1, const hf* B2, size_t ldB,
                          int nK, uint32_t sb, float (&acc)[4][4][4])
{
    const int tid = threadIdx.x;
    const int lane = tid & 31, wid = tid >> 5;
    const int warpM = (wid & 1) * 64, warpN = (wid >> 1) * 32;
    ld_stage(sb, A1, A2, ldA, B1, B2, ldB, 0, tid);
    if (nK > 1) ld_stage(sb + STAGE_BYTES, A1, A2, ldA, B1, B2, ldB, 1, tid);
    for (int kc = 0; kc < nK; kc++) {
        if (kc + 1 < nK) asm volatile("cp.async.wait_group 1;" ::: "memory");
        else             asm volatile("cp.async.wait_group 0;" ::: "memory");
        __syncthreads();
        if (kc + 2 < nK)
            ld_stage(sb + ((kc + 2) % 3) * STAGE_BYTES,
                     A1, A2, ldA, B1, B2, ldB, kc + 2, tid);
        compute_tile(acc, sb + (kc % 3) * STAGE_BYTES, warpM, warpN, lane);
    }
    __syncthreads();
}

#define ACC_DECL()                                                             \
    float acc[4][4][4];                                                        \
    _Pragma("unroll") for (int _i = 0; _i < 4; _i++)                           \
        _Pragma("unroll") for (int _j = 0; _j < 4; _j++)                       \
            _Pragma("unroll") for (int _r = 0; _r < 4; _r++)                   \
                acc[_i][_j][_r] = 0.f;

#define EPI_SETUP()                                                            \
    const int lane = threadIdx.x & 31, wid = threadIdx.x >> 5;                 \
    const int warpM = (wid & 1) * 64, warpN = (wid >> 1) * 32;                 \
    const int er = warpM + (lane >> 2);                                        \
    const int ec = warpN + (lane & 3) * 2;

// ===========================================================================
// aux kernels
// ===========================================================================

__global__ __launch_bounds__(512) void zero_zs()
{
    int i = blockIdx.x * 512 + threadIdx.x;
    g_ZS[i] = 0.f;
}

__global__ __launch_bounds__(256) void prep_w(
    const float* __restrict__ qw, const float* __restrict__ kw,
    const float* __restrict__ vw, const float* __restrict__ ow)
{
    int i = blockIdx.x * 256 + threadIdx.x;
    int m = i >> 18;
    const float* src = (m == 0) ? qw : (m == 1) ? kw : (m == 2) ? vw : ow;
    float v = src[i & (EE * EE - 1)];
    h2split(v, g_W1[i], g_W2[i]);
}

__global__ __launch_bounds__(256) void trans_x(const float* __restrict__ x)
{
    __shared__ float tile[32][33];
    const int b = blockIdx.z, t0 = blockIdx.x * 32, e0 = blockIdx.y * 32;
    const int tx = threadIdx.x, ty = threadIdx.y;
#pragma unroll
    for (int j = 0; j < 4; j++) {
        int e = e0 + ty + j * 8;
        tile[tx][ty + j * 8] = x[((size_t)(b * EE + e)) * TT + t0 + tx];
    }
    __syncthreads();
#pragma unroll
    for (int j = 0; j < 4; j++) {
        int r = ty + j * 8;
        float v = tile[r][tx];
        size_t o = ((size_t)(b * TT + t0 + r)) * EE + e0 + tx;
        h2split(v, g_xT1[o], g_xT2[o]);
    }
}

__global__ __launch_bounds__(256) void softmax_split()
{
    size_t row = blockIdx.x;
    float* r = g_Q + row * EE;
    int tid = threadIdx.x;
    float v0 = r[tid], v1 = r[tid + 256];
    __shared__ float red[256];
    red[tid] = fmaxf(v0, v1);
    __syncthreads();
    for (int s = 128; s > 0; s >>= 1) {
        if (tid < s) red[tid] = fmaxf(red[tid], red[tid + s]);
        __syncthreads();
    }
    float m = red[0];
    __syncthreads();
    float e0 = expf(v0 - m), e1 = expf(v1 - m);
    red[tid] = e0 + e1;
    __syncthreads();
    for (int s = 128; s > 0; s >>= 1) {
        if (tid < s) red[tid] += red[tid + s];
        __syncthreads();
    }
    float sc = QSCALE / red[0];
    float q0 = e0 * sc, q1 = e1 * sc;
    r[tid] = q0; r[tid + 256] = q1;
    size_t o0 = row * EE + tid, o1 = o0 + 256;
    h2split(q0 * QUP, g_Q1[o0], g_Q2[o0]);
    h2split(q1 * QUP, g_Q1[o1], g_Q2[o1]);
}

__global__ __launch_bounds__(512) void z_scan()
{
    int b = blockIdx.x, e = threadIdx.x;
    float run = 0.f;
    for (int c = 0; c < NCH; c++) {
        size_t o = ((size_t)b * NCH + c) * EE + e;
        g_ZC[o] = run;
        run += g_ZS[o];
    }
}

__global__ __launch_bounds__(256) void prefix_S()
{
    int gid = blockIdx.x * 256 + threadIdx.x;
    int b = gid >> 16;
    int p4 = gid & 65535;
    size_t base = ((size_t)b * NCH) * EE * EE + (size_t)p4 * 4;
    float4 run = make_float4(0.f, 0.f, 0.f, 0.f);
    for (int c = 0; c < NCH; c++) {
        size_t o = base + (size_t)c * EE * EE;
        float rv[4] = {run.x, run.y, run.z, run.w};
        hf h[4], l[4];
#pragma unroll
        for (int j = 0; j < 4; j++) h2split(rv[j], h[j], l[j]);
        *(__half2*)(g_SC1 + o)     = __halves2half2(h[0], h[1]);
        *(__half2*)(g_SC1 + o + 2) = __halves2half2(h[2], h[3]);
        *(__half2*)(g_SC2 + o)     = __halves2half2(l[0], l[1]);
        *(__half2*)(g_SC2 + o + 2) = __halves2half2(l[2], l[3]);
        float4 s = *(const float4*)(g_SP + o);
        run.x += s.x; run.y += s.y; run.z += s.z; run.w += s.w;
    }
}

__global__ __launch_bounds__(256) void dinv_kernel()
{
    int w = blockIdx.x * 8 + (threadIdx.x >> 5);
    int lane = threadIdx.x & 31;
    int b = w >> 11, t = w & 2047, c = t >> 7;
    const float* q = g_Q + (size_t)w * EE;
    const float* z = g_ZC + ((size_t)b * NCH + c) * EE;
    float s = 0.f;
#pragma unroll
    for (int i = 0; i < 16; i++) s += q[lane + 32 * i] * z[lane + 32 * i];
#pragma unroll
    for (int o = 16; o > 0; o >>= 1) s += __shfl_xor_sync(0xffffffffu, s, o);
    if (lane == 0) g_DI[w] = 1.f / fmaxf(s + g_RS[w], EPS_D);
}

// ===========================================================================
// GEMM kernels (256 threads, 2 CTAs/SM)
// ===========================================================================

// merged projections; fused epilogues (Q raw fp32 / K exp+splits+T+colsum /
// V *toep +T splits)
__global__ __launch_bounds__(256, 2) void proj_tc(
    const float* __restrict__ qb, const float* __restrict__ kb,
    const float* __restrict__ vb, const float* __restrict__ toep)
{
    extern __shared__ char smdyn[];
    uint32_t sb = sm_u32(smdyn) + 1024;
    const int mode = blockIdx.z >> 3, b = blockIdx.z & 7;
    const int t0 = blockIdx.x * 128, o0 = blockIdx.y * 128;
    ACC_DECL();
    const size_t aoff = ((size_t)(b * TT + t0)) * EE;
    const size_t woff = (size_t)mode * EE * EE + (size_t)o0 * EE;
    gemm_core(g_xT1 + aoff, g_xT2 + aoff, EE, g_W1 + woff, g_W2 + woff, EE,
              16, sb, acc);
    EPI_SETUP();
    const float* bias = (mode == 0) ? qb : (mode == 1) ? kb : vb;
    float* smf = (float*)(smdyn + 1024);          // [128 o][132] fp32 stage

    if (mode == 0) {
#pragma unroll
        for (int mi = 0; mi < 4; mi++)
#pragma unroll
            for (int h = 0; h < 2; h++) {
                int t = t0 + er + mi * 16 + h * 8;
                float* orow = g_Q + ((size_t)b * TT + t) * EE + o0;
#pragma unroll
                for (int nf = 0; nf < 4; nf++) {
                    int cc = ec + nf * 8;
                    *(float2*)&orow[cc] = make_float2(
                        acc[mi][nf][h * 2 + 0] + bias[o0 + cc],
                        acc[mi][nf][h * 2 + 1] + bias[o0 + cc + 1]);
                }
            }
        return;
    }

    float csum[4][2] = {{0.f,0.f},{0.f,0.f},{0.f,0.f},{0.f,0.f}};
#pragma unroll
    for (int mi = 0; mi < 4; mi++)
#pragma unroll
        for (int h = 0; h < 2; h++) {
            int m = er + mi * 16 + h * 8;
            int t = t0 + m;
            float tw = (mode == 2) ? toep[t] : 1.f;
            hf* K1r = g_K1 + ((size_t)b * TT + t) * EE + o0;
            hf* K2r = g_K2 + ((size_t)b * TT + t) * EE + o0;
#pragma unroll
            for (int nf = 0; nf < 4; nf++) {
                int cc = ec + nf * 8;
                float v0 = acc[mi][nf][h * 2 + 0] + bias[o0 + cc];
                float v1 = acc[mi][nf][h * 2 + 1] + bias[o0 + cc + 1];
                if (mode == 1) {
                    v0 = expf(v0); v1 = expf(v1);
                    csum[nf][0] += v0; csum[nf][1] += v1;
                    hf h0, l0, h1, l1;
                    h2split(v0, h0, l0);
                    h2split(v1, h1, l1);
                    *(__half2*)(K1r + cc) = __halves2half2(h0, h1);
                    *(__half2*)(K2r + cc) = __halves2half2(l0, l1);
                } else {
                    v0 *= tw; v1 *= tw;
                }
                smf[cc * 132 + m] = v0;
                smf[(cc + 1) * 132 + m] = v1;
            }
        }
    if (mode == 1) {
        const int chunk = t0 >> 7;
        float* zrow = g_ZS + ((size_t)b * NCH + chunk) * EE + o0;
#pragma unroll
        for (int nf = 0; nf < 4; nf++) {
            atomicAdd(&zrow[ec + nf * 8],     csum[nf][0]);
            atomicAdd(&zrow[ec + nf * 8 + 1], csum[nf][1]);
        }
    }
    __syncthreads();
    hf* T1 = (mode == 1) ? g_KT1 : g_VT1;
    hf* T2 = (mode == 1) ? g_KT2 : g_VT2;
#pragma unroll
    for (int i = 0; i < 16; i++) {
        int e = wid * 16 + i;
        float4 vv = *(float4*)&smf[e * 132 + 4 * lane];
        hf h0, l0, h1, l1, h2, l2, h3, l3;
        h2split(vv.x, h0, l0); h2split(vv.y, h1, l1);
        h2split(vv.z, h2, l2); h2split(vv.w, h3, l3);
        size_t o = ((size_t)(b * EE + o0 + e)) * TT + t0 + 4 * lane;
        *(__half2*)(T1 + o)     = __halves2half2(h0, h1);
        *(__half2*)(T1 + o + 2) = __halves2half2(h2, h3);
        *(__half2*)(T2 + o)     = __halves2half2(l0, l1);
        *(__half2*)(T2 + o + 2) = __halves2half2(l2, l3);
    }
}

// P' = mask(Q' K^T): fp16 splits + true rowsums
__global__ __launch_bounds__(256, 2) void p_tc()
{
    extern __shared__ char smdyn[];
    uint32_t sb = sm_u32(smdyn) + 1024;
    float* srs = (float*)smdyn;
    const int c = blockIdx.x, b = blockIdx.y;
    const int tid = threadIdx.x;
    if (tid < CC) srs[tid] = 0.f;
    ACC_DECL();
    const size_t off = ((size_t)(b * TT + c * CC)) * EE;
    gemm_core(g_Q1 + off, g_Q2 + off, EE, g_K1 + off, g_K2 + off, EE,
              16, sb, acc);
    EPI_SETUP();
    hf* P1 = g_P1 + (size_t)(b * NCH + c) * CC * CC;
    hf* P2 = g_P2 + (size_t)(b * NCH + c) * CC * CC;
#pragma unroll
    for (int mi = 0; mi < 4; mi++)
#pragma unroll
        for (int h = 0; h < 2; h++) {
            int m = er + mi * 16 + h * 8;
            float rsum = 0.f;
#pragma unroll
            for (int nf = 0; nf < 4; nf++) {
                int cc = ec + nf * 8;
                float v0 = (cc     <= m) ? acc[mi][nf][h * 2 + 0] : 0.f;
                float v1 = (cc + 1 <= m) ? acc[mi][nf][h * 2 + 1] : 0.f;
                rsum += v0 + v1;
                hf h0, l0, h1, l1;
                h2split(v0, h0, l0);
                h2split(v1, h1, l1);
                *(__half2*)(P1 + (size_t)m * CC + cc) = __halves2half2(h0, h1);
                *(__half2*)(P2 + (size_t)m * CC + cc) = __halves2half2(l0, l1);
            }
            atomicAdd(&srs[m], rsum);
        }
    __syncthreads();
    if (tid < CC) g_RS[(size_t)b * TT + (size_t)c * CC + tid] = srs[tid] * QDN;
}

// per-chunk S[f,e] = V_c^T K_c (fp32 partials)
__global__ __launch_bounds__(256, 2) void ktv_tc()
{
    extern __shared__ char smdyn[];
    uint32_t sb = sm_u32(smdyn) + 1024;
    const int fi = blockIdx.x & 3, ei = blockIdx.x >> 2;
    const int c = blockIdx.y, b = blockIdx.z;
    ACC_DECL();
    const size_t aoff = ((size_t)(b * EE + fi * 128)) * TT + (size_t)c * CC;
    const size_t boff = ((size_t)(b * EE + ei * 128)) * TT + (size_t)c * CC;
    gemm_core(g_VT1 + aoff, g_VT2 + aoff, TT, g_KT1 + boff, g_KT2 + boff, TT,
              4, sb, acc);
    EPI_SETUP();
#pragma unroll
    for (int mi = 0; mi < 4; mi++)
#pragma unroll
        for (int h = 0; h < 2; h++) {
            int m = er + mi * 16 + h * 8;
            float* sp = g_SP + ((size_t)(b * NCH + c) * EE + fi * 128 + m) * EE
                             + ei * 128;
#pragma unroll
            for (int nf = 0; nf < 4; nf++) {
                int cc = ec + nf * 8;
                *(float2*)&sp[cc] = make_float2(acc[mi][nf][h * 2 + 0],
                                                acc[mi][nf][h * 2 + 1]);
            }
        }
}

// O = (Q'@S_prev + P'@V) * dinv/1024 -> attn fp16 splits
__global__ __launch_bounds__(256, 2) void qspv_tc()
{
    extern __shared__ char smdyn[];
    uint32_t sb = sm_u32(smdyn) + 1024;
    const int n0 = blockIdx.x * 128, c = blockIdx.y, b = blockIdx.z;
    ACC_DECL();
    const size_t qoff = ((size_t)(b * TT + c * CC)) * EE;
    if (c > 0) {
        const size_t soff = ((size_t)(b * NCH + c) * EE + n0) * EE;
        gemm_core(g_Q1 + qoff, g_Q2 + qoff, EE, g_SC1 + soff, g_SC2 + soff, EE,
                  16, sb, acc);
    }
    const size_t poff = (size_t)(b * NCH + c) * CC * CC;
    const size_t voff = ((size_t)(b * EE + n0)) * TT + (size_t)c * CC;
    gemm_core(g_P1 + poff, g_P2 + poff, CC, g_VT1 + voff, g_VT2 + voff, TT,
              4, sb, acc);
    EPI_SETUP();
#pragma unroll
    for (int mi = 0; mi < 4; mi++)
#pragma unroll
        for (int h = 0; h < 2; h++) {
            int m = er + mi * 16 + h * 8;
            size_t row = (size_t)b * TT + (size_t)c * CC + m;
            float di = g_DI[row] * QDN;
            hf* A1 = g_A1 + row * EE + n0;
            hf* A2 = g_A2 + row * EE + n0;
#pragma unroll
            for (int nf = 0; nf < 4; nf++) {
                int cc = ec + nf * 8;
                float v0 = acc[mi][nf][h * 2 + 0] * di;
                float v1 = acc[mi][nf][h * 2 + 1] * di;
                hf h0, l0, h1, l1;
                h2split(v0, h0, l0);
                h2split(v1, h1, l1);
                *(__half2*)(A1 + cc) = __halves2half2(h0, h1);
                *(__half2*)(A2 + cc) = __halves2half2(l0, l1);
            }
        }
}

// out = A @ o_w^T + o_b (fp32)
__global__ __launch_bounds__(256, 2) void out_tc(
    const float* __restrict__ ob, float* __restrict__ out)
{
    extern __shared__ char smdyn[];
    uint32_t sb = sm_u32(smdyn) + 1024;
    const int b = blockIdx.z, t0 = blockIdx.x * 128, o0 = blockIdx.y * 128;
    ACC_DECL();
    const size_t aoff = ((size_t)(b * TT + t0)) * EE;
    const size_t woff = (size_t)3 * EE * EE + (size_t)o0 * EE;
    gemm_core(g_A1 + aoff, g_A2 + aoff, EE, g_W1 + woff, g_W2 + woff, EE,
              16, sb, acc);
    EPI_SETUP();
#pragma unroll
    for (int mi = 0; mi < 4; mi++)
#pragma unroll
        for (int h = 0; h < 2; h++) {
            int t = t0 + er + mi * 16 + h * 8;
            float* orow = out + ((size_t)b * TT + t) * EE + o0;
#pragma unroll
            for (int nf = 0; nf < 4; nf++) {
                int cc = ec + nf * 8;
                *(float2*)&orow[cc] = make_float2(
                    acc[mi][nf][h * 2 + 0] + ob[o0 + cc],
                    acc[mi][nf][h * 2 + 1] + ob[o0 + cc + 1]);
            }
        }
}

// ===========================================================================
extern "C" void kernel_launch(void* const* d_in, const int* in_sizes, int n_in,
                              void* d_out, int out_size)
{
    (void)in_sizes; (void)n_in; (void)out_size;
    const float* x    = (const float*)d_in[0];
    const float* toep = (const float*)d_in[1];
    const float* q_w  = (const float*)d_in[2];
    const float* q_b  = (const float*)d_in[3];
    const float* k_w  = (const float*)d_in[4];
    const float* k_b  = (const float*)d_in[5];
    const float* v_w  = (const float*)d_in[6];
    const float* v_b  = (const float*)d_in[7];
    const float* o_w  = (const float*)d_in[8];
    const float* o_b  = (const float*)d_in[9];
    float* out = (float*)d_out;

    cudaFuncSetAttribute(proj_tc, cudaFuncAttributeMaxDynamicSharedMemorySize, SMEM_BYTES);
    cudaFuncSetAttribute(p_tc,    cudaFuncAttributeMaxDynamicSharedMemorySize, SMEM_BYTES);
    cudaFuncSetAttribute(ktv_tc,  cudaFuncAttributeMaxDynamicSharedMemorySize, SMEM_BYTES);
    cudaFuncSetAttribute(qspv_tc, cudaFuncAttributeMaxDynamicSharedMemorySize, SMEM_BYTES);
    cudaFuncSetAttribute(out_tc,  cudaFuncAttributeMaxDynamicSharedMemorySize, SMEM_BYTES);

    zero_zs<<<128, 512>>>();
    prep_w<<<4096, 256>>>(q_w, k_w, v_w, o_w);
    trans_x<<<dim3(TT / 32, EE / 32, BB), dim3(32, 8)>>>(x);

    proj_tc<<<dim3(TT / 128, EE / 128, 3 * BB), 256, SMEM_BYTES>>>(q_b, k_b, v_b, toep);

    softmax_split<<<NT, 256>>>();
    z_scan<<<BB, 512>>>();

    p_tc<<<dim3(NCH, BB), 256, SMEM_BYTES>>>();
    ktv_tc<<<dim3(16, NCH, BB), 256, SMEM_BYTES>>>();
    prefix_S<<<2048, 256>>>();
    dinv_kernel<<<NT / 8, 256>>>();
    qspv_tc<<<dim3(EE / 128, NCH, BB), 256, SMEM_BYTES>>>();
    out_tc<<<dim3(TT / 128, EE / 128, BB), 256, SMEM_BYTES>>>(o_b, out);
}

// round 12
// speedup vs baseline: 2.8278x; 1.0442x over previous
#include <cuda_runtime.h>
#include <cuda_fp16.h>
#include <cstdint>
#include <math.h>

// ===========================================================================
// LinearAttentionToeplitz — fp16x2 error-compensated mma.sync pipeline, v5.
// 256-thread CTAs (2 CTAs/SM), 64x32 warp tiles, k-tile 32, 3-stage ring.
// v5: fragment-lifetime reorder, launch fusion (12 -> 7), warp-row softmax,
// p_tc folded into ktv grid.
// ===========================================================================

#define BB 8
#define TT 2048
#define EE 512
#define CC 128
#define NCH 16
#define NT (BB*TT)
#define NTE (NT*EE)
#define EPS_D 1e-3f
#define QSCALE 0.044194173824159216f
#define QUP 1024.0f
#define QDN (1.0f/1024.0f)
#define SPN ((size_t)BB*NCH*EE*EE)
#define STAGE_BYTES 32768              // 4 tiles x [128][32] fp16
#define SMEM_BYTES (1024 + 3*STAGE_BYTES)

typedef __half hf;

// ---------------- device scratch ----------------
__device__ __align__(16) float g_Q[NTE];    // fp32 q (true scale)
__device__ __align__(16) float g_SP[SPN];   // per-chunk S partial [f][e]
__device__ float g_RS[NT];
__device__ float g_DI[NT];
__device__ float g_ZC[BB*NCH*EE];
__device__ float g_ZS[BB*NCH*EE];

__device__ __align__(16) hf g_xT1[NTE], g_xT2[NTE];   // x^T [t][e]
__device__ __align__(16) hf g_Q1[NTE],  g_Q2[NTE];    // 1024*q rows
__device__ __align__(16) hf g_K1[NTE],  g_K2[NTE];    // expk rows
__device__ __align__(16) hf g_KT1[NTE], g_KT2[NTE];   // expk^T [e][t]
__device__ __align__(16) hf g_VT1[NTE], g_VT2[NTE];   // v^T    [f][t]
__device__ __align__(16) hf g_A1[NTE],  g_A2[NTE];    // attn   [t][e]
__device__ __align__(16) hf g_P1[BB*NCH*CC*CC], g_P2[BB*NCH*CC*CC]; // 1024*P
__device__ __align__(16) hf g_SC1[SPN], g_SC2[SPN];   // S prefix [f][e]
__device__ __align__(16) hf g_W1[4*EE*EE], g_W2[4*EE*EE];

// ---------------- helpers ----------------
__device__ __forceinline__ uint32_t sm_u32(const void* p) {
    uint32_t a;
    asm("{ .reg .u64 t; cvta.to.shared.u64 t, %1; cvt.u32.u64 %0, t; }"
        : "=r"(a) : "l"(p));
    return a;
}
__device__ __forceinline__ void h2split(float v, hf& h, hf& l) {
    h = __float2half_rn(v);
    l = __float2half_rn(v - __half2float(h));
}
// swizzle for [row][64B] tiles: 4 segs of 16B, seg' = seg ^ ((row>>1)&3)
__device__ __forceinline__ uint32_t swz(int row, int seg) {
    return (uint32_t)(row * 64 + ((seg ^ ((row >> 1) & 3)) << 4));
}

#define LDSM4(r, addr)                                                         \
    asm volatile("ldmatrix.sync.aligned.m8n8.x4.shared.b16 {%0,%1,%2,%3}, [%4];" \
                 : "=r"((r)[0]), "=r"((r)[1]), "=r"((r)[2]), "=r"((r)[3])      \
                 : "r"(addr))

#define MMA16816(d, a, b)                                                      \
    asm volatile("mma.sync.aligned.m16n8k16.row.col.f32.f16.f16.f32 "          \
                 "{%0,%1,%2,%3}, {%4,%5,%6,%7}, {%8,%9}, {%0,%1,%2,%3};"       \
                 : "+f"((d)[0]), "+f"((d)[1]), "+f"((d)[2]), "+f"((d)[3])      \
                 : "r"((a)[0]), "r"((a)[1]), "r"((a)[2]), "r"((a)[3]),         \
                   "r"((b)[0]), "r"((b)[1]))

// ---------------- cp.async staging: 4 tiles (Ah,Al,Bh,Bl) [128][32] hf ------
__device__ __forceinline__ void ld_stage(
    uint32_t st,
    const hf* __restrict__ A1, const hf* __restrict__ A2, size_t ldA,
    const hf* __restrict__ B1, const hf* __restrict__ B2, size_t ldB,
    int kc, int tid)
{
    const hf* gp[4] = {A1, A2, B1, B2};
    const size_t ldb[4] = {ldA * 2, ldA * 2, ldB * 2, ldB * 2};
#pragma unroll
    for (int t = 0; t < 4; t++) {
        const char* g0 = (const char*)gp[t] + (size_t)kc * 64;
#pragma unroll
        for (int i = 0; i < 2; i++) {
            int c = tid + i * 256;
            int row = c >> 2, seg = c & 3;
            uint32_t d = st + t * 8192u + swz(row, seg);
            const void* s = g0 + (size_t)row * ldb[t] + seg * 16;
            asm volatile("cp.async.cg.shared.global [%0], [%1], 16;"
                         :: "r"(d), "l"(s) : "memory");
        }
    }
    asm volatile("cp.async.commit_group;" ::: "memory");
}

// ---------------- per-ktile compute: 64x32 warp tile, 3 passes --------------
// fragment-lifetime order: load ah/bh/bl -> hh -> load al -> hl -> lh
__device__ __forceinline__ void compute_tile(
    float (&acc)[4][4][4], uint32_t stage, int warpM, int warpN, int lane)
{
    const int l7 = lane & 7;
    const int aSel = lane >> 4;
    const int bSel = (lane >> 3) & 1;
    const int aR = ((lane >> 3) & 1) * 8 + l7;
    const int bR = (lane >> 4) * 8 + l7;
#pragma unroll
    for (int ks = 0; ks < 2; ks++) {
        uint32_t ah[4][4], bh[2][4], bl[2][4];
#pragma unroll
        for (int mi = 0; mi < 4; mi++) {
            int row = warpM + mi * 16 + aR;
            uint32_t off = (uint32_t)(row * 64 +
                (((ks * 2 + aSel) ^ ((row >> 1) & 3)) << 4));
            LDSM4(ah[mi], stage + off);
        }
#pragma unroll
        for (int ni = 0; ni < 2; ni++) {
            int row = warpN + ni * 16 + bR;
            uint32_t off = (uint32_t)(row * 64 +
                (((ks * 2 + bSel) ^ ((row >> 1) & 3)) << 4));
            LDSM4(bh[ni], stage + 16384u + off);
            LDSM4(bl[ni], stage + 24576u + off);
        }
        // pass hh
#pragma unroll
        for (int mi = 0; mi < 4; mi++) {
            MMA16816(acc[mi][0], ah[mi], bh[0] + 0);
            MMA16816(acc[mi][1], ah[mi], bh[0] + 2);
            MMA16816(acc[mi][2], ah[mi], bh[1] + 0);
            MMA16816(acc[mi][3], ah[mi], bh[1] + 2);
        }
        // load al (latency covered by hh pass above)
        uint32_t al[4][4];
#pragma unroll
        for (int mi = 0; mi < 4; mi++) {
            int row = warpM + mi * 16 + aR;
            uint32_t off = (uint32_t)(row * 64 +
                (((ks * 2 + aSel) ^ ((row >> 1) & 3)) << 4));
            LDSM4(al[mi], stage + 8192u + off);
        }
        // pass hl (ah x bl) — bl dies after this
#pragma unroll
        for (int mi = 0; mi < 4; mi++) {
            MMA16816(acc[mi][0], ah[mi], bl[0] + 0);
            MMA16816(acc[mi][1], ah[mi], bl[0] + 2);
            MMA16816(acc[mi][2], ah[mi], bl[1] + 0);
            MMA16816(acc[mi][3], ah[mi], bl[1] + 2);
        }
        // pass lh (al x bh)
#pragma unroll
        for (int mi = 0; mi < 4; mi++) {
            MMA16816(acc[mi][0], al[mi], bh[0] + 0);
            MMA16816(acc[mi][1], al[mi], bh[0] + 2);
            MMA16816(acc[mi][2], al[mi], bh[1] + 0);
            MMA16816(acc[mi][3], al[mi], bh[1] + 2);
        }
    }
}

// ---------------- 3-stage ring GEMM core (accumulating) ---------------------
__device__ void gemm_core(const hf* A1, const hf* A2, size_t ldA,
                          const hf* B1, const hf* B2, size_t ldB,
                          int nK, uint32_t sb, float (&acc)[4][4][4])
{
    const int tid = threadIdx.x;
    const int lane = tid & 31, wid = tid >> 5;
    const int warpM = (wid & 1) * 64, warpN = (wid >> 1) * 32;
    ld_stage(sb, A1, A2, ldA, B1, B2, ldB, 0, tid);
    if (nK > 1) ld_stage(sb + STAGE_BYTES, A1, A2, ldA, B1, B2, ldB, 1, tid);
    for (int kc = 0; kc < nK; kc++) {
        if (kc + 1 < nK) asm volatile("cp.async.wait_group 1;" ::: "memory");
        else             asm volatile("cp.async.wait_group 0;" ::: "memory");
        __syncthreads();
        if (kc + 2 < nK)
            ld_stage(sb + ((kc + 2) % 3) * STAGE_BYTES,
                     A1, A2, ldA, B1, B2, ldB, kc + 2, tid);
        compute_tile(acc, sb + (kc % 3) * STAGE_BYTES, warpM, warpN, lane);
    }
    __syncthreads();
}

#define ACC_DECL()                                                             \
    float acc[4][4][4];                                                        \
    _Pragma("unroll") for (int _i = 0; _i < 4; _i++)                           \
        _Pragma("unroll") for (int _j = 0; _j < 4; _j++)                       \
            _Pragma("unroll") for (int _r = 0; _r < 4; _r++)                   \
                acc[_i][_j][_r] = 0.f;

#define EPI_SETUP()                                                            \
    const int lane = threadIdx.x & 31, wid = threadIdx.x >> 5;                 \
    const int warpM = (wid & 1) * 64, warpN = (wid >> 1) * 32;                 \
    const int er = warpM + (lane >> 2);                                        \
    const int ec = warpN + (lane & 3) * 2;

// ===========================================================================
// fused aux kernels
// ===========================================================================

// prep: bz<8 -> trans_x tile; bz==8 -> weight splits + zero g_ZS
__global__ __launch_bounds__(256) void prep_all(
    const float* __restrict__ x,
    const float* __restrict__ qw, const float* __restrict__ kw,
    const float* __restrict__ vw, const float* __restrict__ ow)
{
    const int tx = threadIdx.x, ty = threadIdx.y;
    if (blockIdx.z < 8) {
        __shared__ float tile[32][33];
        const int b = blockIdx.z, t0 = blockIdx.x * 32, e0 = blockIdx.y * 32;
#pragma unroll
        for (int j = 0; j < 4; j++) {
            int e = e0 + ty + j * 8;
            tile[tx][ty + j * 8] = x[((size_t)(b * EE + e)) * TT + t0 + tx];
        }
        __syncthreads();
#pragma unroll
        for (int j = 0; j < 4; j++) {
            int r = ty + j * 8;
            float v = tile[r][tx];
            size_t o = ((size_t)(b * TT + t0 + r)) * EE + e0 + tx;
            h2split(v, g_xT1[o], g_xT2[o]);
        }
        return;
    }
    const int tid = ty * 32 + tx;
    const int blk = blockIdx.y * 64 + blockIdx.x;   // 0..1023
#pragma unroll
    for (int j = 0; j < 4; j++) {
        int i = blk * 1024 + j * 256 + tid;         // 0..1048575
        int m = i >> 18;
        const float* src = (m == 0) ? qw : (m == 1) ? kw : (m == 2) ? vw : ow;
        float v = src[i & (EE * EE - 1)];
        h2split(v, g_W1[i], g_W2[i]);
    }
    if (blk < 256) g_ZS[blk * 256 + tid] = 0.f;
}

// softmax (warp-per-row, bx<2048) + z_scan (bx>=2048)
__global__ __launch_bounds__(256) void softmax_zscan()
{
    if (blockIdx.x < 2048) {
        int w = blockIdx.x * 8 + (threadIdx.x >> 5);
        int lane = threadIdx.x & 31;
        float* r = g_Q + (size_t)w * EE;
        float4 v[4];
#pragma unroll
        for (int j = 0; j < 4; j++) v[j] = *(float4*)&r[j * 128 + lane * 4];
        float m = -1e30f;
#pragma unroll
        for (int j = 0; j < 4; j++)
            m = fmaxf(m, fmaxf(fmaxf(v[j].x, v[j].y), fmaxf(v[j].z, v[j].w)));
#pragma unroll
        for (int o = 16; o > 0; o >>= 1)
            m = fmaxf(m, __shfl_xor_sync(0xffffffffu, m, o));
        float s = 0.f;
#pragma unroll
        for (int j = 0; j < 4; j++) {
            v[j].x = expf(v[j].x - m); v[j].y = expf(v[j].y - m);
            v[j].z = expf(v[j].z - m); v[j].w = expf(v[j].w - m);
            s += v[j].x + v[j].y + v[j].z + v[j].w;
        }
#pragma unroll
        for (int o = 16; o > 0; o >>= 1)
            s += __shfl_xor_sync(0xffffffffu, s, o);
        float sc = QSCALE / s;
#pragma unroll
        for (int j = 0; j < 4; j++) {
            float q0 = v[j].x * sc, q1 = v[j].y * sc;
            float q2 = v[j].z * sc, q3 = v[j].w * sc;
            int cc = j * 128 + lane * 4;
            *(float4*)&r[cc] = make_float4(q0, q1, q2, q3);
            hf h0, l0, h1, l1, h2, l2, h3, l3;
            h2split(q0 * QUP, h0, l0); h2split(q1 * QUP, h1, l1);
            h2split(q2 * QUP, h2, l2); h2split(q3 * QUP, h3, l3);
            size_t o = (size_t)w * EE + cc;
            *(__half2*)(g_Q1 + o)     = __halves2half2(h0, h1);
            *(__half2*)(g_Q1 + o + 2) = __halves2half2(h2, h3);
            *(__half2*)(g_Q2 + o)     = __halves2half2(l0, l1);
            *(__half2*)(g_Q2 + o + 2) = __halves2half2(l2, l3);
        }
        return;
    }
    int b = blockIdx.x - 2048;
#pragma unroll
    for (int half = 0; half < 2; half++) {
        int e = threadIdx.x + half * 256;
        float run = 0.f;
        for (int c = 0; c < NCH; c++) {
            size_t o = ((size_t)b * NCH + c) * EE + e;
            g_ZC[o] = run;
            run += g_ZS[o];
        }
    }
}

// prefix_S (bx<2048) + dinv (bx>=2048)
__global__ __launch_bounds__(256) void pfx_dinv()
{
    if (blockIdx.x < 2048) {
        int gid = blockIdx.x * 256 + threadIdx.x;
        int b = gid >> 16;
        int p4 = gid & 65535;
        size_t base = ((size_t)b * NCH) * EE * EE + (size_t)p4 * 4;
        float4 run = make_float4(0.f, 0.f, 0.f, 0.f);
        for (int c = 0; c < NCH; c++) {
            size_t o = base + (size_t)c * EE * EE;
            float rv[4] = {run.x, run.y, run.z, run.w};
            hf h[4], l[4];
#pragma unroll
            for (int j = 0; j < 4; j++) h2split(rv[j], h[j], l[j]);
            *(__half2*)(g_SC1 + o)     = __halves2half2(h[0], h[1]);
            *(__half2*)(g_SC1 + o + 2) = __halves2half2(h[2], h[3]);
            *(__half2*)(g_SC2 + o)     = __halves2half2(l[0], l[1]);
            *(__half2*)(g_SC2 + o + 2) = __halves2half2(l[2], l[3]);
            float4 s = *(const float4*)(g_SP + o);
            run.x += s.x; run.y += s.y; run.z += s.z; run.w += s.w;
        }
        return;
    }
    int w = (blockIdx.x - 2048) * 8 + (threadIdx.x >> 5);
    int lane = threadIdx.x & 31;
    int b = w >> 11, t = w & 2047, c = t >> 7;
    const float* q = g_Q + (size_t)w * EE;
    const float* z = g_ZC + ((size_t)b * NCH + c) * EE;
    float s = 0.f;
#pragma unroll
    for (int i = 0; i < 16; i++) s += q[lane + 32 * i] * z[lane + 32 * i];
#pragma unroll
    for (int o = 16; o > 0; o >>= 1) s += __shfl_xor_sync(0xffffffffu, s, o);
    if (lane == 0) g_DI[w] = 1.f / fmaxf(s + g_RS[w], EPS_D);
}

// ===========================================================================
// GEMM kernels (256 threads, 2 CTAs/SM)
// ===========================================================================

// merged projections; fused epilogues (Q raw fp32 / K exp+splits+T+colsum /
// V *toep +T splits)
__global__ __launch_bounds__(256, 2) void proj_tc(
    const float* __restrict__ qb, const float* __restrict__ kb,
    const float* __restrict__ vb, const float* __restrict__ toep)
{
    extern __shared__ char smdyn[];
    uint32_t sb = sm_u32(smdyn) + 1024;
    const int mode = blockIdx.z >> 3, b = blockIdx.z & 7;
    const int t0 = blockIdx.x * 128, o0 = blockIdx.y * 128;
    ACC_DECL();
    const size_t aoff = ((size_t)(b * TT + t0)) * EE;
    const size_t woff = (size_t)mode * EE * EE + (size_t)o0 * EE;
    gemm_core(g_xT1 + aoff, g_xT2 + aoff, EE, g_W1 + woff, g_W2 + woff, EE,
              16, sb, acc);
    EPI_SETUP();
    const float* bias = (mode == 0) ? qb : (mode == 1) ? kb : vb;
    float* smf = (float*)(smdyn + 1024);          // [128 o][132] fp32 stage

    if (mode == 0) {
#pragma unroll
        for (int mi = 0; mi < 4; mi++)
#pragma unroll
            for (int h = 0; h < 2; h++) {
                int t = t0 + er + mi * 16 + h * 8;
                float* orow = g_Q + ((size_t)b * TT + t) * EE + o0;
#pragma unroll
                for (int nf = 0; nf < 4; nf++) {
                    int cc = ec + nf * 8;
                    *(float2*)&orow[cc] = make_float2(
                        acc[mi][nf][h * 2 + 0] + bias[o0 + cc],
                        acc[mi][nf][h * 2 + 1] + bias[o0 + cc + 1]);
                }
            }
        return;
    }

    float csum[4][2] = {{0.f,0.f},{0.f,0.f},{0.f,0.f},{0.f,0.f}};
#pragma unroll
    for (int mi = 0; mi < 4; mi++)
#pragma unroll
        for (int h = 0; h < 2; h++) {
            int m = er + mi * 16 + h * 8;
            int t = t0 + m;
            float tw = (mode == 2) ? toep[t] : 1.f;
            hf* K1r = g_K1 + ((size_t)b * TT + t) * EE + o0;
            hf* K2r = g_K2 + ((size_t)b * TT + t) * EE + o0;
#pragma unroll
            for (int nf = 0; nf < 4; nf++) {
                int cc = ec + nf * 8;
                float v0 = acc[mi][nf][h * 2 + 0] + bias[o0 + cc];
                float v1 = acc[mi][nf][h * 2 + 1] + bias[o0 + cc + 1];
                if (mode == 1) {
                    v0 = expf(v0); v1 = expf(v1);
                    csum[nf][0] += v0; csum[nf][1] += v1;
                    hf h0, l0, h1, l1;
                    h2split(v0, h0, l0);
                    h2split(v1, h1, l1);
                    *(__half2*)(K1r + cc) = __halves2half2(h0, h1);
                    *(__half2*)(K2r + cc) = __halves2half2(l0, l1);
                } else {
                    v0 *= tw; v1 *= tw;
                }
                smf[cc * 132 + m] = v0;
                smf[(cc + 1) * 132 + m] = v1;
            }
        }
    if (mode == 1) {
        const int chunk = t0 >> 7;
        float* zrow = g_ZS + ((size_t)b * NCH + chunk) * EE + o0;
#pragma unroll
        for (int nf = 0; nf < 4; nf++) {
            atomicAdd(&zrow[ec + nf * 8],     csum[nf][0]);
            atomicAdd(&zrow[ec + nf * 8 + 1], csum[nf][1]);
        }
    }
    __syncthreads();
    hf* T1 = (mode == 1) ? g_KT1 : g_VT1;
    hf* T2 = (mode == 1) ? g_KT2 : g_VT2;
#pragma unroll
    for (int i = 0; i < 16; i++) {
        int e = wid * 16 + i;
        float4 vv = *(float4*)&smf[e * 132 + 4 * lane];
        hf h0, l0, h1, l1, h2, l2, h3, l3;
        h2split(vv.x, h0, l0); h2split(vv.y, h1, l1);
        h2split(vv.z, h2, l2); h2split(vv.w, h3, l3);
        size_t o = ((size_t)(b * EE + o0 + e)) * TT + t0 + 4 * lane;
        *(__half2*)(T1 + o)     = __halves2half2(h0, h1);
        *(__half2*)(T1 + o + 2) = __halves2half2(h2, h3);
        *(__half2*)(T2 + o)     = __halves2half2(l0, l1);
        *(__half2*)(T2 + o + 2) = __halves2half2(l2, l3);
    }
}

// fat kernel: bx<16 -> ktv (S partials); bx==16 -> P tile
__global__ __launch_bounds__(256, 2) void pktv_tc()
{
    extern __shared__ char smdyn[];
    uint32_t sb = sm_u32(smdyn) + 1024;
    const int c = blockIdx.y, b = blockIdx.z;
    ACC_DECL();
    if (blockIdx.x < 16) {
        const int fi = blockIdx.x & 3, ei = blockIdx.x >> 2;
        const size_t aoff = ((size_t)(b * EE + fi * 128)) * TT + (size_t)c * CC;
        const size_t boff = ((size_t)(b * EE + ei * 128)) * TT + (size_t)c * CC;
        gemm_core(g_VT1 + aoff, g_VT2 + aoff, TT, g_KT1 + boff, g_KT2 + boff, TT,
                  4, sb, acc);
        EPI_SETUP();
#pragma unroll
        for (int mi = 0; mi < 4; mi++)
#pragma unroll
            for (int h = 0; h < 2; h++) {
                int m = er + mi * 16 + h * 8;
                float* sp = g_SP + ((size_t)(b * NCH + c) * EE + fi * 128 + m) * EE
                                 + ei * 128;
#pragma unroll
                for (int nf = 0; nf < 4; nf++) {
                    int cc = ec + nf * 8;
                    *(float2*)&sp[cc] = make_float2(acc[mi][nf][h * 2 + 0],
                                                    acc[mi][nf][h * 2 + 1]);
                }
            }
        return;
    }
    // ---- P tile ----
    float* srs = (float*)smdyn;
    const int tid = threadIdx.x;
    if (tid < CC) srs[tid] = 0.f;
    const size_t off = ((size_t)(b * TT + c * CC)) * EE;
    gemm_core(g_Q1 + off, g_Q2 + off, EE, g_K1 + off, g_K2 + off, EE,
              16, sb, acc);
    EPI_SETUP();
    hf* P1 = g_P1 + (size_t)(b * NCH + c) * CC * CC;
    hf* P2 = g_P2 + (size_t)(b * NCH + c) * CC * CC;
#pragma unroll
    for (int mi = 0; mi < 4; mi++)
#pragma unroll
        for (int h = 0; h < 2; h++) {
            int m = er + mi * 16 + h * 8;
            float rsum = 0.f;
#pragma unroll
            for (int nf = 0; nf < 4; nf++) {
                int cc = ec + nf * 8;
                float v0 = (cc     <= m) ? acc[mi][nf][h * 2 + 0] : 0.f;
                float v1 = (cc + 1 <= m) ? acc[mi][nf][h * 2 + 1] : 0.f;
                rsum += v0 + v1;
                hf h0, l0, h1, l1;
                h2split(v0, h0, l0);
                h2split(v1, h1, l1);
                *(__half2*)(P1 + (size_t)m * CC + cc) = __halves2half2(h0, h1);
                *(__half2*)(P2 + (size_t)m * CC + cc) = __halves2half2(l0, l1);
            }
            atomicAdd(&srs[m], rsum);
        }
    __syncthreads();
    if (tid < CC) g_RS[(size_t)b * TT + (size_t)c * CC + tid] = srs[tid] * QDN;
}

// O = (Q'@S_prev + P'@V) * dinv/1024 -> attn fp16 splits
__global__ __launch_bounds__(256, 2) void qspv_tc()
{
    extern __shared__ char smdyn[];
    uint32_t sb = sm_u32(smdyn) + 1024;
    const int n0 = blockIdx.x * 128, c = blockIdx.y, b = blockIdx.z;
    ACC_DECL();
    const size_t qoff = ((size_t)(b * TT + c * CC)) * EE;
    if (c > 0) {
        const size_t soff = ((size_t)(b * NCH + c) * EE + n0) * EE;
        gemm_core(g_Q1 + qoff, g_Q2 + qoff, EE, g_SC1 + soff, g_SC2 + soff, EE,
                  16, sb, acc);
    }
    const size_t poff = (size_t)(b * NCH + c) * CC * CC;
    const size_t voff = ((size_t)(b * EE + n0)) * TT + (size_t)c * CC;
    gemm_core(g_P1 + poff, g_P2 + poff, CC, g_VT1 + voff, g_VT2 + voff, TT,
              4, sb, acc);
    EPI_SETUP();
#pragma unroll
    for (int mi = 0; mi < 4; mi++)
#pragma unroll
        for (int h = 0; h < 2; h++) {
            int m = er + mi * 16 + h * 8;
            size_t row = (size_t)b * TT + (size_t)c * CC + m;
            float di = g_DI[row] * QDN;
            hf* A1 = g_A1 + row * EE + n0;
            hf* A2 = g_A2 + row * EE + n0;
#pragma unroll
            for (int nf = 0; nf < 4; nf++) {
                int cc = ec + nf * 8;
                float v0 = acc[mi][nf][h * 2 + 0] * di;
                float v1 = acc[mi][nf][h * 2 + 1] * di;
                hf h0, l0, h1, l1;
                h2split(v0, h0, l0);
                h2split(v1, h1, l1);
                *(__half2*)(A1 + cc) = __halves2half2(h0, h1);
                *(__half2*)(A2 + cc) = __halves2half2(l0, l1);
            }
        }
}

// out = A @ o_w^T + o_b (fp32)
__global__ __launch_bounds__(256, 2) void out_tc(
    const float* __restrict__ ob, float* __restrict__ out)
{
    extern __shared__ char smdyn[];
    uint32_t sb = sm_u32(smdyn) + 1024;
    const int b = blockIdx.z, t0 = blockIdx.x * 128, o0 = blockIdx.y * 128;
    ACC_DECL();
    const size_t aoff = ((size_t)(b * TT + t0)) * EE;
    const size_t woff = (size_t)3 * EE * EE + (size_t)o0 * EE;
    gemm_core(g_A1 + aoff, g_A2 + aoff, EE, g_W1 + woff, g_W2 + woff, EE,
              16, sb, acc);
    EPI_SETUP();
#pragma unroll
    for (int mi = 0; mi < 4; mi++)
#pragma unroll
        for (int h = 0; h < 2; h++) {
            int t = t0 + er + mi * 16 + h * 8;
            float* orow = out + ((size_t)b * TT + t) * EE + o0;
#pragma unroll
            for (int nf = 0; nf < 4; nf++) {
                int cc = ec + nf * 8;
                *(float2*)&orow[cc] = make_float2(
                    acc[mi][nf][h * 2 + 0] + ob[o0 + cc],
                    acc[mi][nf][h * 2 + 1] + ob[o0 + cc + 1]);
            }
        }
}

// ===========================================================================
extern "C" void kernel_launch(void* const* d_in, const int* in_sizes, int n_in,
                              void* d_out, int out_size)
{
    (void)in_sizes; (void)n_in; (void)out_size;
    const float* x    = (const float*)d_in[0];
    const float* toep = (const float*)d_in[1];
    const float* q_w  = (const float*)d_in[2];
    const float* q_b  = (const float*)d_in[3];
    const float* k_w  = (const float*)d_in[4];
    const float* k_b  = (const float*)d_in[5];
    const float* v_w  = (const float*)d_in[6];
    const float* v_b  = (const float*)d_in[7];
    const float* o_w  = (const float*)d_in[8];
    const float* o_b  = (const float*)d_in[9];
    float* out = (float*)d_out;

    cudaFuncSetAttribute(proj_tc, cudaFuncAttributeMaxDynamicSharedMemorySize, SMEM_BYTES);
    cudaFuncSetAttribute(pktv_tc, cudaFuncAttributeMaxDynamicSharedMemorySize, SMEM_BYTES);
    cudaFuncSetAttribute(qspv_tc, cudaFuncAttributeMaxDynamicSharedMemorySize, SMEM_BYTES);
    cudaFuncSetAttribute(out_tc,  cudaFuncAttributeMaxDynamicSharedMemorySize, SMEM_BYTES);

    prep_all<<<dim3(64, 16, 9), dim3(32, 8)>>>(x, q_w, k_w, v_w, o_w);
    proj_tc<<<dim3(TT / 128, EE / 128, 3 * BB), 256, SMEM_BYTES>>>(q_b, k_b, v_b, toep);
    softmax_zscan<<<2048 + BB, 256>>>();
    pktv_tc<<<dim3(17, NCH, BB), 256, SMEM_BYTES>>>();
    pfx_dinv<<<4096, 256>>>();
    qspv_tc<<<dim3(EE / 128, NCH, BB), 256, SMEM_BYTES>>>();
    out_tc<<<dim3(TT / 128, EE / 128, BB), 256, SMEM_BYTES>>>(o_b, out);
}

// round 15
// speedup vs baseline: 2.8569x; 1.0103x over previous
#include <cuda_runtime.h>
#include <cuda_fp16.h>
#include <cstdint>
#include <math.h>

// ===========================================================================
// LinearAttentionToeplitz — fp16x2 error-compensated mma.sync pipeline, v6.
// 256-thread CTAs (2 CTAs/SM), 64x32 warp tiles, k-tile 32, 3-stage ring.
// v6: persistent S-prefix CTAs (S state lives in acc registers across all 16
// chunks; exclusive-prefix splits written per chunk) — g_SP and the prefix_S
// streaming kernel are eliminated (~270 MB DRAM traffic removed).
// ===========================================================================

#define BB 8
#define TT 2048
#define EE 512
#define CC 128
#define NCH 16
#define NT (BB*TT)
#define NTE (NT*EE)
#define EPS_D 1e-3f
#define QSCALE 0.044194173824159216f
#define QUP 1024.0f
#define QDN (1.0f/1024.0f)
#define SPN ((size_t)BB*NCH*EE*EE)
#define STAGE_BYTES 32768              // 4 tiles x [128][32] fp16
#define SMEM_BYTES (1024 + 3*STAGE_BYTES)

typedef __half hf;

// ---------------- device scratch ----------------
__device__ __align__(16) float g_Q[NTE];    // fp32 q (true scale)
__device__ float g_RS[NT];
__device__ float g_DI[NT];
__device__ float g_ZC[BB*NCH*EE];
__device__ float g_ZS[BB*NCH*EE];

__device__ __align__(16) hf g_xT1[NTE], g_xT2[NTE];   // x^T [t][e]
__device__ __align__(16) hf g_Q1[NTE],  g_Q2[NTE];    // 1024*q rows
__device__ __align__(16) hf g_K1[NTE],  g_K2[NTE];    // expk rows
__device__ __align__(16) hf g_KT1[NTE], g_KT2[NTE];   // expk^T [e][t]
__device__ __align__(16) hf g_VT1[NTE], g_VT2[NTE];   // v^T    [f][t]
__device__ __align__(16) hf g_A1[NTE],  g_A2[NTE];    // attn   [t][e]
__device__ __align__(16) hf g_P1[BB*NCH*CC*CC], g_P2[BB*NCH*CC*CC]; // 1024*P
__device__ __align__(16) hf g_SC1[SPN], g_SC2[SPN];   // S exclusive prefix [f][e]
__device__ __align__(16) hf g_W1[4*EE*EE], g_W2[4*EE*EE];

// ---------------- helpers ----------------
__device__ __forceinline__ uint32_t sm_u32(const void* p) {
    uint32_t a;
    asm("{ .reg .u64 t; cvta.to.shared.u64 t, %1; cvt.u32.u64 %0, t; }"
        : "=r"(a) : "l"(p));
    return a;
}
__device__ __forceinline__ void h2split(float v, hf& h, hf& l) {
    h = __float2half_rn(v);
    l = __float2half_rn(v - __half2float(h));
}
// swizzle for [row][64B] tiles: 4 segs of 16B, seg' = seg ^ ((row>>1)&3)
__device__ __forceinline__ uint32_t swz(int row, int seg) {
    return (uint32_t)(row * 64 + ((seg ^ ((row >> 1) & 3)) << 4));
}

#define LDSM4(r, addr)                                                         \
    asm volatile("ldmatrix.sync.aligned.m8n8.x4.shared.b16 {%0,%1,%2,%3}, [%4];" \
                 : "=r"((r)[0]), "=r"((r)[1]), "=r"((r)[2]), "=r"((r)[3])      \
                 : "r"(addr))

#define MMA16816(d, a, b)                                                      \
    asm volatile("mma.sync.aligned.m16n8k16.row.col.f32.f16.f16.f32 "          \
                 "{%0,%1,%2,%3}, {%4,%5,%6,%7}, {%8,%9}, {%0,%1,%2,%3};"       \
                 : "+f"((d)[0]), "+f"((d)[1]), "+f"((d)[2]), "+f"((d)[3])      \
                 : "r"((a)[0]), "r"((a)[1]), "r"((a)[2]), "r"((a)[3]),         \
                   "r"((b)[0]), "r"((b)[1]))

// ---------------- cp.async staging: 4 tiles (Ah,Al,Bh,Bl) [128][32] hf ------
__device__ __forceinline__ void ld_stage(
    uint32_t st,
    const hf* __restrict__ A1, const hf* __restrict__ A2, size_t ldA,
    const hf* __restrict__ B1, const hf* __restrict__ B2, size_t ldB,
    int kc, int tid)
{
    const hf* gp[4] = {A1, A2, B1, B2};
    const size_t ldb[4] = {ldA * 2, ldA * 2, ldB * 2, ldB * 2};
#pragma unroll
    for (int t = 0; t < 4; t++) {
        const char* g0 = (const char*)gp[t] + (size_t)kc * 64;
#pragma unroll
        for (int i = 0; i < 2; i++) {
            int c = tid + i * 256;
            int row = c >> 2, seg = c & 3;
            uint32_t d = st + t * 8192u + swz(row, seg);
            const void* s = g0 + (size_t)row * ldb[t] + seg * 16;
            asm volatile("cp.async.cg.shared.global [%0], [%1], 16;"
                         :: "r"(d), "l"(s) : "memory");
        }
    }
    asm volatile("cp.async.commit_group;" ::: "memory");
}

// ---------------- per-ktile compute: 64x32 warp tile, 3 passes --------------
__device__ __forceinline__ void compute_tile(
    float (&acc)[4][4][4], uint32_t stage, int warpM, int warpN, int lane)
{
    const int l7 = lane & 7;
    const int aSel = lane >> 4;
    const int bSel = (lane >> 3) & 1;
    const int aR = ((lane >> 3) & 1) * 8 + l7;
    const int bR = (lane >> 4) * 8 + l7;
#pragma unroll
    for (int ks = 0; ks < 2; ks++) {
        uint32_t ah[4][4], bh[2][4], bl[2][4];
#pragma unroll
        for (int mi = 0; mi < 4; mi++) {
            int row = warpM + mi * 16 + aR;
            uint32_t off = (uint32_t)(row * 64 +
                (((ks * 2 + aSel) ^ ((row >> 1) & 3)) << 4));
            LDSM4(ah[mi], stage + off);
        }
#pragma unroll
        for (int ni = 0; ni < 2; ni++) {
            int row = warpN + ni * 16 + bR;
            uint32_t off = (uint32_t)(row * 64 +
                (((ks * 2 + bSel) ^ ((row >> 1) & 3)) << 4));
            LDSM4(bh[ni], stage + 16384u + off);
            LDSM4(bl[ni], stage + 24576u + off);
        }
        // pass hh
#pragma unroll
        for (int mi = 0; mi < 4; mi++) {
            MMA16816(acc[mi][0], ah[mi], bh[0] + 0);
            MMA16816(acc[mi][1], ah[mi], bh[0] + 2);
            MMA16816(acc[mi][2], ah[mi], bh[1] + 0);
            MMA16816(acc[mi][3], ah[mi], bh[1] + 2);
        }
        // load al (latency covered by hh pass above)
        uint32_t al[4][4];
#pragma unroll
        for (int mi = 0; mi < 4; mi++) {
            int row = warpM + mi * 16 + aR;
            uint32_t off = (uint32_t)(row * 64 +
                (((ks * 2 + aSel) ^ ((row >> 1) & 3)) << 4));
            LDSM4(al[mi], stage + 8192u + off);
        }
        // pass hl (ah x bl)
#pragma unroll
        for (int mi = 0; mi < 4; mi++) {
            MMA16816(acc[mi][0], ah[mi], bl[0] + 0);
            MMA16816(acc[mi][1], ah[mi], bl[0] + 2);
            MMA16816(acc[mi][2], ah[mi], bl[1] + 0);
            MMA16816(acc[mi][3], ah[mi], bl[1] + 2);
        }
        // pass lh (al x bh)
#pragma unroll
        for (int mi = 0; mi < 4; mi++) {
            MMA16816(acc[mi][0], al[mi], bh[0] + 0);
            MMA16816(acc[mi][1], al[mi], bh[0] + 2);
            MMA16816(acc[mi][2], al[mi], bh[1] + 0);
            MMA16816(acc[mi][3], al[mi], bh[1] + 2);
        }
    }
}

// ---------------- 3-stage ring GEMM core (accumulating) ---------------------
__device__ void gemm_core(const hf* A1, const hf* A2, size_t ldA,
                          const hf* B1, const hf* B2, size_t ldB,
                          int nK, uint32_t sb, float (&acc)[4][4][4])
{
    const int tid = threadIdx.x;
    const int lane = tid & 31, wid = tid >> 5;
    const int warpM = (wid & 1) * 64, warpN = (wid >> 1) * 32;
    ld_stage(sb, A1, A2, ldA, B1, B2, ldB, 0, tid);
    if (nK > 1) ld_stage(sb + STAGE_BYTES, A1, A2, ldA, B1, B2, ldB, 1, tid);
    for (int kc = 0; kc < nK; kc++) {
        if (kc + 1 < nK) asm volatile("cp.async.wait_group 1;" ::: "memory");
        else             asm volatile("cp.async.wait_group 0;" ::: "memory");
        __syncthreads();
        if (kc + 2 < nK)
            ld_stage(sb + ((kc + 2) % 3) * STAGE_BYTES,
                     A1, A2, ldA, B1, B2, ldB, kc + 2, tid);
        compute_tile(acc, sb + (kc % 3) * STAGE_BYTES, warpM, warpN, lane);
    }
    __syncthreads();
}

#define ACC_DECL()                                                             \
    float acc[4][4][4];                                                        \
    _Pragma("unroll") for (int _i = 0; _i < 4; _i++)                           \
        _Pragma("unroll") for (int _j = 0; _j < 4; _j++)                       \
            _Pragma("unroll") for (int _r = 0; _r < 4; _r++)                   \
                acc[_i][_j][_r] = 0.f;

#define EPI_SETUP()                                                            \
    const int lane = threadIdx.x & 31, wid = threadIdx.x >> 5;                 \
    const int warpM = (wid & 1) * 64, warpN = (wid >> 1) * 32;                 \
    const int er = warpM + (lane >> 2);                                        \
    const int ec = warpN + (lane & 3) * 2;

// ===========================================================================
// fused aux kernels
// ===========================================================================

// prep: bz<8 -> trans_x tile; bz==8 -> weight splits + zero g_ZS
__global__ __launch_bounds__(256) void prep_all(
    const float* __restrict__ x,
    const float* __restrict__ qw, const float* __restrict__ kw,
    const float* __restrict__ vw, const float* __restrict__ ow)
{
    const int tx = threadIdx.x, ty = threadIdx.y;
    if (blockIdx.z < 8) {
        __shared__ float tile[32][33];
        const int b = blockIdx.z, t0 = blockIdx.x * 32, e0 = blockIdx.y * 32;
#pragma unroll
        for (int j = 0; j < 4; j++) {
            int e = e0 + ty + j * 8;
            tile[tx][ty + j * 8] = x[((size_t)(b * EE + e)) * TT + t0 + tx];
        }
        __syncthreads();
#pragma unroll
        for (int j = 0; j < 4; j++) {
            int r = ty + j * 8;
            float v = tile[r][tx];
            size_t o = ((size_t)(b * TT + t0 + r)) * EE + e0 + tx;
            h2split(v, g_xT1[o], g_xT2[o]);
        }
        return;
    }
    const int tid = ty * 32 + tx;
    const int blk = blockIdx.y * 64 + blockIdx.x;   // 0..1023
#pragma unroll
    for (int j = 0; j < 4; j++) {
        int i = blk * 1024 + j * 256 + tid;         // 0..1048575
        int m = i >> 18;
        const float* src = (m == 0) ? qw : (m == 1) ? kw : (m == 2) ? vw : ow;
        float v = src[i & (EE * EE - 1)];
        h2split(v, g_W1[i], g_W2[i]);
    }
    if (blk < 256) g_ZS[blk * 256 + tid] = 0.f;
}

// softmax (warp-per-row, bx<2048) + z_scan (bx>=2048)
__global__ __launch_bounds__(256) void softmax_zscan()
{
    if (blockIdx.x < 2048) {
        int w = blockIdx.x * 8 + (threadIdx.x >> 5);
        int lane = threadIdx.x & 31;
        float* r = g_Q + (size_t)w * EE;
        float4 v[4];
#pragma unroll
        for (int j = 0; j < 4; j++) v[j] = *(float4*)&r[j * 128 + lane * 4];
        float m = -1e30f;
#pragma unroll
        for (int j = 0; j < 4; j++)
            m = fmaxf(m, fmaxf(fmaxf(v[j].x, v[j].y), fmaxf(v[j].z, v[j].w)));
#pragma unroll
        for (int o = 16; o > 0; o >>= 1)
            m = fmaxf(m, __shfl_xor_sync(0xffffffffu, m, o));
        float s = 0.f;
#pragma unroll
        for (int j = 0; j < 4; j++) {
            v[j].x = expf(v[j].x - m); v[j].y = expf(v[j].y - m);
            v[j].z = expf(v[j].z - m); v[j].w = expf(v[j].w - m);
            s += v[j].x + v[j].y + v[j].z + v[j].w;
        }
#pragma unroll
        for (int o = 16; o > 0; o >>= 1)
            s += __shfl_xor_sync(0xffffffffu, s, o);
        float sc = QSCALE / s;
#pragma unroll
        for (int j = 0; j < 4; j++) {
            float q0 = v[j].x * sc, q1 = v[j].y * sc;
            float q2 = v[j].z * sc, q3 = v[j].w * sc;
            int cc = j * 128 + lane * 4;
            *(float4*)&r[cc] = make_float4(q0, q1, q2, q3);
            hf h0, l0, h1, l1, h2, l2, h3, l3;
            h2split(q0 * QUP, h0, l0); h2split(q1 * QUP, h1, l1);
            h2split(q2 * QUP, h2, l2); h2split(q3 * QUP, h3, l3);
            size_t o = (size_t)w * EE + cc;
            *(__half2*)(g_Q1 + o)     = __halves2half2(h0, h1);
            *(__half2*)(g_Q1 + o + 2) = __halves2half2(h2, h3);
            *(__half2*)(g_Q2 + o)     = __halves2half2(l0, l1);
            *(__half2*)(g_Q2 + o + 2) = __halves2half2(l2, l3);
        }
        return;
    }
    int b = blockIdx.x - 2048;
#pragma unroll
    for (int half = 0; half < 2; half++) {
        int e = threadIdx.x + half * 256;
        float run = 0.f;
        for (int c = 0; c < NCH; c++) {
            size_t o = ((size_t)b * NCH + c) * EE + e;
            g_ZC[o] = run;
            run += g_ZS[o];
        }
    }
}

// denominator (needs RS from P + ZC)
__global__ __launch_bounds__(256) void dinv_kernel()
{
    int w = blockIdx.x * 8 + (threadIdx.x >> 5);
    int lane = threadIdx.x & 31;
    int b = w >> 11, t = w & 2047, c = t >> 7;
    const float* q = g_Q + (size_t)w * EE;
    const float* z = g_ZC + ((size_t)b * NCH + c) * EE;
    float s = 0.f;
#pragma unroll
    for (int i = 0; i < 16; i++) s += q[lane + 32 * i] * z[lane + 32 * i];
#pragma unroll
    for (int o = 16; o > 0; o >>= 1) s += __shfl_xor_sync(0xffffffffu, s, o);
    if (lane == 0) g_DI[w] = 1.f / fmaxf(s + g_RS[w], EPS_D);
}

// ===========================================================================
// GEMM kernels (256 threads, 2 CTAs/SM)
// ===========================================================================

// merged projections; fused epilogues (Q raw fp32 / K exp+splits+T+colsum /
// V *toep +T splits)
__global__ __launch_bounds__(256, 2) void proj_tc(
    const float* __restrict__ qb, const float* __restrict__ kb,
    const float* __restrict__ vb, const float* __restrict__ toep)
{
    extern __shared__ char smdyn[];
    uint32_t sb = sm_u32(smdyn) + 1024;
    const int mode = blockIdx.z >> 3, b = blockIdx.z & 7;
    const int t0 = blockIdx.x * 128, o0 = blockIdx.y * 128;
    ACC_DECL();
    const size_t aoff = ((size_t)(b * TT + t0)) * EE;
    const size_t woff = (size_t)mode * EE * EE + (size_t)o0 * EE;
    gemm_core(g_xT1 + aoff, g_xT2 + aoff, EE, g_W1 + woff, g_W2 + woff, EE,
              16, sb, acc);
    EPI_SETUP();
    const float* bias = (mode == 0) ? qb : (mode == 1) ? kb : vb;
    float* smf = (float*)(smdyn + 1024);          // [128 o][132] fp32 stage

    if (mode == 0) {
#pragma unroll
        for (int mi = 0; mi < 4; mi++)
#pragma unroll
            for (int h = 0; h < 2; h++) {
                int t = t0 + er + mi * 16 + h * 8;
                float* orow = g_Q + ((size_t)b * TT + t) * EE + o0;
#pragma unroll
                for (int nf = 0; nf < 4; nf++) {
                    int cc = ec + nf * 8;
                    *(float2*)&orow[cc] = make_float2(
                        acc[mi][nf][h * 2 + 0] + bias[o0 + cc],
                        acc[mi][nf][h * 2 + 1] + bias[o0 + cc + 1]);
                }
            }
        return;
    }

    float csum[4][2] = {{0.f,0.f},{0.f,0.f},{0.f,0.f},{0.f,0.f}};
#pragma unroll
    for (int mi = 0; mi < 4; mi++)
#pragma unroll
        for (int h = 0; h < 2; h++) {
            int m = er + mi * 16 + h * 8;
            int t = t0 + m;
            float tw = (mode == 2) ? toep[t] : 1.f;
            hf* K1r = g_K1 + ((size_t)b * TT + t) * EE + o0;
            hf* K2r = g_K2 + ((size_t)b * TT + t) * EE + o0;
#pragma unroll
            for (int nf = 0; nf < 4; nf++) {
                int cc = ec + nf * 8;
                float v0 = acc[mi][nf][h * 2 + 0] + bias[o0 + cc];
                float v1 = acc[mi][nf][h * 2 + 1] + bias[o0 + cc + 1];
                if (mode == 1) {
                    v0 = expf(v0); v1 = expf(v1);
                    csum[nf][0] += v0; csum[nf][1] += v1;
                    hf h0, l0, h1, l1;
                    h2split(v0, h0, l0);
                    h2split(v1, h1, l1);
                    *(__half2*)(K1r + cc) = __halves2half2(h0, h1);
                    *(__half2*)(K2r + cc) = __halves2half2(l0, l1);
                } else {
                    v0 *= tw; v1 *= tw;
                }
                smf[cc * 132 + m] = v0;
                smf[(cc + 1) * 132 + m] = v1;
            }
        }
    if (mode == 1) {
        const int chunk = t0 >> 7;
        float* zrow = g_ZS + ((size_t)b * NCH + chunk) * EE + o0;
#pragma unroll
        for (int nf = 0; nf < 4; nf++) {
            atomicAdd(&zrow[ec + nf * 8],     csum[nf][0]);
            atomicAdd(&zrow[ec + nf * 8 + 1], csum[nf][1]);
        }
    }
    __syncthreads();
    hf* T1 = (mode == 1) ? g_KT1 : g_VT1;
    hf* T2 = (mode == 1) ? g_KT2 : g_VT2;
#pragma unroll
    for (int i = 0; i < 16; i++) {
        int e = wid * 16 + i;
        float4 vv = *(float4*)&smf[e * 132 + 4 * lane];
        hf h0, l0, h1, l1, h2, l2, h3, l3;
        h2split(vv.x, h0, l0); h2split(vv.y, h1, l1);
        h2split(vv.z, h2, l2); h2split(vv.w, h3, l3);
        size_t o = ((size_t)(b * EE + o0 + e)) * TT + t0 + 4 * lane;
        *(__half2*)(T1 + o)     = __halves2half2(h0, h1);
        *(__half2*)(T1 + o + 2) = __halves2half2(h2, h3);
        *(__half2*)(T2 + o)     = __halves2half2(l0, l1);
        *(__half2*)(T2 + o + 2) = __halves2half2(l2, l3);
    }
}

// fat kernel, 1D grid of 256:
//   bid < 128 : persistent S-prefix CTA — owns 128x128 tile (fi,ei) of S for
//               batch b; accumulates K^TV chunks in registers, writes the
//               EXCLUSIVE prefix as fp16 splits before absorbing each chunk.
//   bid >= 128: P tile (chunk c, batch b) — mask(Q'K^T) splits + rowsums.
__global__ __launch_bounds__(256, 2) void pktv_tc()
{
    extern __shared__ char smdyn[];
    uint32_t sb = sm_u32(smdyn) + 1024;
    const int bid = blockIdx.x;
    ACC_DECL();
    if (bid < 128) {
        const int b = bid >> 4, tile = bid & 15;
        const int fi = tile & 3, ei = tile >> 2;
        EPI_SETUP();
        for (int c = 0; c < NCH; c++) {
            if (c > 0) {
                // write exclusive prefix (sum of chunks < c) as splits
                hf* C1 = g_SC1 + ((size_t)(b * NCH + c) * EE) * EE;
                hf* C2 = g_SC2 + ((size_t)(b * NCH + c) * EE) * EE;
#pragma unroll
                for (int mi = 0; mi < 4; mi++)
#pragma unroll
                    for (int h = 0; h < 2; h++) {
                        int m = fi * 128 + er + mi * 16 + h * 8;
                        size_t rofs = (size_t)m * EE + ei * 128;
#pragma unroll
                        for (int nf = 0; nf < 4; nf++) {
                            int cc = ec + nf * 8;
                            float v0 = acc[mi][nf][h * 2 + 0];
                            float v1 = acc[mi][nf][h * 2 + 1];
                            hf h0, l0, h1, l1;
                            h2split(v0, h0, l0);
                            h2split(v1, h1, l1);
                            *(__half2*)(C1 + rofs + cc) = __halves2half2(h0, h1);
                            *(__half2*)(C2 + rofs + cc) = __halves2half2(l0, l1);
                        }
                    }
            }
            if (c < NCH - 1) {   // final inclusive state never consumed
                const size_t aoff = ((size_t)(b * EE + fi * 128)) * TT + (size_t)c * CC;
                const size_t boff = ((size_t)(b * EE + ei * 128)) * TT + (size_t)c * CC;
                gemm_core(g_VT1 + aoff, g_VT2 + aoff, TT,
                          g_KT1 + boff, g_KT2 + boff, TT, 4, sb, acc);
            }
        }
        return;
    }
    // ---- P tile ----
    const int pb = bid - 128;
    const int b = pb >> 4, c = pb & 15;
    float* srs = (float*)smdyn;
    const int tid = threadIdx.x;
    if (tid < CC) srs[tid] = 0.f;
    const size_t off = ((size_t)(b * TT + c * CC)) * EE;
    gemm_core(g_Q1 + off, g_Q2 + off, EE, g_K1 + off, g_K2 + off, EE,
              16, sb, acc);
    EPI_SETUP();
    hf* P1 = g_P1 + (size_t)(b * NCH + c) * CC * CC;
    hf* P2 = g_P2 + (size_t)(b * NCH + c) * CC * CC;
#pragma unroll
    for (int mi = 0; mi < 4; mi++)
#pragma unroll
        for (int h = 0; h < 2; h++) {
            int m = er + mi * 16 + h * 8;
            float rsum = 0.f;
#pragma unroll
            for (int nf = 0; nf < 4; nf++) {
                int cc = ec + nf * 8;
                float v0 = (cc     <= m) ? acc[mi][nf][h * 2 + 0] : 0.f;
                float v1 = (cc + 1 <= m) ? acc[mi][nf][h * 2 + 1] : 0.f;
                rsum += v0 + v1;
                hf h0, l0, h1, l1;
                h2split(v0, h0, l0);
                h2split(v1, h1, l1);
                *(__half2*)(P1 + (size_t)m * CC + cc) = __halves2half2(h0, h1);
                *(__half2*)(P2 + (size_t)m * CC + cc) = __halves2half2(l0, l1);
            }
            atomicAdd(&srs[m], rsum);
        }
    __syncthreads();
    if (tid < CC) g_RS[(size_t)b * TT + (size_t)c * CC + tid] = srs[tid] * QDN;
}

// O = (Q'@S_prev + P'@V) * dinv/1024 -> attn fp16 splits
__global__ __launch_bounds__(256, 2) void qspv_tc()
{
    extern __shared__ char smdyn[];
    uint32_t sb = sm_u32(smdyn) + 1024;
    const int n0 = blockIdx.x * 128, c = blockIdx.y, b = blockIdx.z;
    ACC_DECL();
    const size_t qoff = ((size_t)(b * TT + c * CC)) * EE;
    if (c > 0) {
        const size_t soff = ((size_t)(b * NCH + c) * EE + n0) * EE;
        gemm_core(g_Q1 + qoff, g_Q2 + qoff, EE, g_SC1 + soff, g_SC2 + soff, EE,
                  16, sb, acc);
    }
    const size_t poff = (size_t)(b * NCH + c) * CC * CC;
    const size_t voff = ((size_t)(b * EE + n0)) * TT + (size_t)c * CC;
    gemm_core(g_P1 + poff, g_P2 + poff, CC, g_VT1 + voff, g_VT2 + voff, TT,
              4, sb, acc);
    EPI_SETUP();
#pragma unroll
    for (int mi = 0; mi < 4; mi++)
#pragma unroll
        for (int h = 0; h < 2; h++) {
            int m = er + mi * 16 + h * 8;
            size_t row = (size_t)b * TT + (size_t)c * CC + m;
            float di = g_DI[row] * QDN;
            hf* A1 = g_A1 + row * EE + n0;
            hf* A2 = g_A2 + row * EE + n0;
#pragma unroll
            for (int nf = 0; nf < 4; nf++) {
                int cc = ec + nf * 8;
                float v0 = acc[mi][nf][h * 2 + 0] * di;
                float v1 = acc[mi][nf][h * 2 + 1] * di;
                hf h0, l0, h1, l1;
                h2split(v0, h0, l0);
                h2split(v1, h1, l1);
                *(__half2*)(A1 + cc) = __halves2half2(h0, h1);
                *(__half2*)(A2 + cc) = __halves2half2(l0, l1);
            }
        }
}

// out = A @ o_w^T + o_b (fp32)
__global__ __launch_bounds__(256, 2) void out_tc(
    const float* __restrict__ ob, float* __restrict__ out)
{
    extern __shared__ char smdyn[];
    uint32_t sb = sm_u32(smdyn) + 1024;
    const int b = blockIdx.z, t0 = blockIdx.x * 128, o0 = blockIdx.y * 128;
    ACC_DECL();
    const size_t aoff = ((size_t)(b * TT + t0)) * EE;
    const size_t woff = (size_t)3 * EE * EE + (size_t)o0 * EE;
    gemm_core(g_A1 + aoff, g_A2 + aoff, EE, g_W1 + woff, g_W2 + woff, EE,
              16, sb, acc);
    EPI_SETUP();
#pragma unroll
    for (int mi = 0; mi < 4; mi++)
#pragma unroll
        for (int h = 0; h < 2; h++) {
            int t = t0 + er + mi * 16 + h * 8;
            float* orow = out + ((size_t)b * TT + t) * EE + o0;
#pragma unroll
            for (int nf = 0; nf < 4; nf++) {
                int cc = ec + nf * 8;
                *(float2*)&orow[cc] = make_float2(
                    acc[mi][nf][h * 2 + 0] + ob[o0 + cc],
                    acc[mi][nf][h * 2 + 1] + ob[o0 + cc + 1]);
            }
        }
}

// ===========================================================================
extern "C" void kernel_launch(void* const* d_in, const int* in_sizes, int n_in,
                              void* d_out, int out_size)
{
    (void)in_sizes; (void)n_in; (void)out_size;
    const float* x    = (const float*)d_in[0];
    const float* toep = (const float*)d_in[1];
    const float* q_w  = (const float*)d_in[2];
    const float* q_b  = (const float*)d_in[3];
    const float* k_w  = (const float*)d_in[4];
    const float* k_b  = (const float*)d_in[5];
    const float* v_w  = (const float*)d_in[6];
    const float* v_b  = (const float*)d_in[7];
    const float* o_w  = (const float*)d_in[8];
    const float* o_b  = (const float*)d_in[9];
    float* out = (float*)d_out;

    cudaFuncSetAttribute(proj_tc, cudaFuncAttributeMaxDynamicSharedMemorySize, SMEM_BYTES);
    cudaFuncSetAttribute(pktv_tc, cudaFuncAttributeMaxDynamicSharedMemorySize, SMEM_BYTES);
    cudaFuncSetAttribute(qspv_tc, cudaFuncAttributeMaxDynamicSharedMemorySize, SMEM_BYTES);
    cudaFuncSetAttribute(out_tc,  cudaFuncAttributeMaxDynamicSharedMemorySize, SMEM_BYTES);

    prep_all<<<dim3(64, 16, 9), dim3(32, 8)>>>(x, q_w, k_w, v_w, o_w);
    proj_tc<<<dim3(TT / 128, EE / 128, 3 * BB), 256, SMEM_BYTES>>>(q_b, k_b, v_b, toep);
    softmax_zscan<<<2048 + BB, 256>>>();
    pktv_tc<<<256, 256, SMEM_BYTES>>>();
    dinv_kernel<<<NT / 8, 256>>>();
    qspv_tc<<<dim3(EE / 128, NCH, BB), 256, SMEM_BYTES>>>();
    out_tc<<<dim3(TT / 128, EE / 128, BB), 256, SMEM_BYTES>>>(o_b, out);
}

// round 16
// speedup vs baseline: 2.8794x; 1.0079x over previous
#include <cuda_runtime.h>
#include <cuda_fp16.h>
#include <cstdint>
#include <math.h>

// ===========================================================================
// LinearAttentionToeplitz — fp16x2 error-compensated mma.sync pipeline, v7.
// GEMMs: 256-thread CTAs (2/SM), 64x32 warp tiles, k-tile 32, 3-stage ring.
// v7: S-prefix as a dedicated persistent kernel: 512 threads, 1 CTA/SM
// (197KB smem), 6-stage ring, continuous 60-k-tile stream across chunks
// (t-contiguous VT/KT), exclusive-prefix SC writes at chunk boundaries.
// ===========================================================================

#define BB 8
#define TT 2048
#define EE 512
#define CC 128
#define NCH 16
#define NT (BB*TT)
#define NTE (NT*EE)
#define EPS_D 1e-3f
#define QSCALE 0.044194173824159216f
#define QUP 1024.0f
#define QDN (1.0f/1024.0f)
#define SPN ((size_t)BB*NCH*EE*EE)
#define STAGE_BYTES 32768              // 4 tiles x [128][32] fp16
#define SMEM_BYTES (1024 + 3*STAGE_BYTES)
#define SPF_SMEM   (1024 + 6*STAGE_BYTES)   // 197632: sprefix deep ring

typedef __half hf;

// ---------------- device scratch ----------------
__device__ __align__(16) float g_Q[NTE];    // fp32 q (true scale)
__device__ float g_RS[NT];
__device__ float g_DI[NT];
__device__ float g_ZC[BB*NCH*EE];
__device__ float g_ZS[BB*NCH*EE];

__device__ __align__(16) hf g_xT1[NTE], g_xT2[NTE];   // x^T [t][e]
__device__ __align__(16) hf g_Q1[NTE],  g_Q2[NTE];    // 1024*q rows
__device__ __align__(16) hf g_K1[NTE],  g_K2[NTE];    // expk rows
__device__ __align__(16) hf g_KT1[NTE], g_KT2[NTE];   // expk^T [e][t]
__device__ __align__(16) hf g_VT1[NTE], g_VT2[NTE];   // v^T    [f][t]
__device__ __align__(16) hf g_A1[NTE],  g_A2[NTE];    // attn   [t][e]
__device__ __align__(16) hf g_P1[BB*NCH*CC*CC], g_P2[BB*NCH*CC*CC]; // 1024*P
__device__ __align__(16) hf g_SC1[SPN], g_SC2[SPN];   // S exclusive prefix [f][d]
__device__ __align__(16) hf g_W1[4*EE*EE], g_W2[4*EE*EE];

// ---------------- helpers ----------------
__device__ __forceinline__ uint32_t sm_u32(const void* p) {
    uint32_t a;
    asm("{ .reg .u64 t; cvta.to.shared.u64 t, %1; cvt.u32.u64 %0, t; }"
        : "=r"(a) : "l"(p));
    return a;
}
__device__ __forceinline__ void h2split(float v, hf& h, hf& l) {
    h = __float2half_rn(v);
    l = __float2half_rn(v - __half2float(h));
}
// swizzle for [row][64B] tiles: 4 segs of 16B, seg' = seg ^ ((row>>1)&3)
__device__ __forceinline__ uint32_t swz(int row, int seg) {
    return (uint32_t)(row * 64 + ((seg ^ ((row >> 1) & 3)) << 4));
}

#define LDSM4(r, addr)                                                         \
    asm volatile("ldmatrix.sync.aligned.m8n8.x4.shared.b16 {%0,%1,%2,%3}, [%4];" \
                 : "=r"((r)[0]), "=r"((r)[1]), "=r"((r)[2]), "=r"((r)[3])      \
                 : "r"(addr))

#define MMA16816(d, a, b)                                                      \
    asm volatile("mma.sync.aligned.m16n8k16.row.col.f32.f16.f16.f32 "          \
                 "{%0,%1,%2,%3}, {%4,%5,%6,%7}, {%8,%9}, {%0,%1,%2,%3};"       \
                 : "+f"((d)[0]), "+f"((d)[1]), "+f"((d)[2]), "+f"((d)[3])      \
                 : "r"((a)[0]), "r"((a)[1]), "r"((a)[2]), "r"((a)[3]),         \
                   "r"((b)[0]), "r"((b)[1]))

// ---------------- cp.async staging: 4 tiles (Ah,Al,Bh,Bl) [128][32] hf ------
__device__ __forceinline__ void ld_stage(
    uint32_t st,
    const hf* __restrict__ A1, const hf* __restrict__ A2, size_t ldA,
    const hf* __restrict__ B1, const hf* __restrict__ B2, size_t ldB,
    int kc, int tid)
{
    const hf* gp[4] = {A1, A2, B1, B2};
    const size_t ldb[4] = {ldA * 2, ldA * 2, ldB * 2, ldB * 2};
#pragma unroll
    for (int t = 0; t < 4; t++) {
        const char* g0 = (const char*)gp[t] + (size_t)kc * 64;
#pragma unroll
        for (int i = 0; i < 2; i++) {
            int c = tid + i * 256;
            int row = c >> 2, seg = c & 3;
            uint32_t d = st + t * 8192u + swz(row, seg);
            const void* s = g0 + (size_t)row * ldb[t] + seg * 16;
            asm volatile("cp.async.cg.shared.global [%0], [%1], 16;"
                         :: "r"(d), "l"(s) : "memory");
        }
    }
    asm volatile("cp.async.commit_group;" ::: "memory");
}

// 512-thread variant (one 16B chunk per thread per tile), all lds = TT
__device__ __forceinline__ void ld_stage512(
    uint32_t st,
    const hf* __restrict__ A1, const hf* __restrict__ A2,
    const hf* __restrict__ B1, const hf* __restrict__ B2,
    int kc, int tid)
{
    const hf* gp[4] = {A1, A2, B1, B2};
    const int row = tid >> 2, seg = tid & 3;
    const uint32_t d0 = swz(row, seg);
    const size_t rb = (size_t)row * (TT * 2) + seg * 16 + (size_t)kc * 64;
#pragma unroll
    for (int t = 0; t < 4; t++) {
        asm volatile("cp.async.cg.shared.global [%0], [%1], 16;"
                     :: "r"(st + t * 8192u + d0),
                        "l"((const char*)gp[t] + rb) : "memory");
    }
    asm volatile("cp.async.commit_group;" ::: "memory");
}

// ---------------- per-ktile compute: 64x32 warp tile, 3 passes --------------
__device__ __forceinline__ void compute_tile(
    float (&acc)[4][4][4], uint32_t stage, int warpM, int warpN, int lane)
{
    const int l7 = lane & 7;
    const int aSel = lane >> 4;
    const int bSel = (lane >> 3) & 1;
    const int aR = ((lane >> 3) & 1) * 8 + l7;
    const int bR = (lane >> 4) * 8 + l7;
#pragma unroll
    for (int ks = 0; ks < 2; ks++) {
        uint32_t ah[4][4], bh[2][4], bl[2][4];
#pragma unroll
        for (int mi = 0; mi < 4; mi++) {
            int row = warpM + mi * 16 + aR;
            uint32_t off = (uint32_t)(row * 64 +
                (((ks * 2 + aSel) ^ ((row >> 1) & 3)) << 4));
            LDSM4(ah[mi], stage + off);
        }
#pragma unroll
        for (int ni = 0; ni < 2; ni++) {
            int row = warpN + ni * 16 + bR;
            uint32_t off = (uint32_t)(row * 64 +
                (((ks * 2 + bSel) ^ ((row >> 1) & 3)) << 4));
            LDSM4(bh[ni], stage + 16384u + off);
            LDSM4(bl[ni], stage + 24576u + off);
        }
#pragma unroll
        for (int mi = 0; mi < 4; mi++) {
            MMA16816(acc[mi][0], ah[mi], bh[0] + 0);
            MMA16816(acc[mi][1], ah[mi], bh[0] + 2);
            MMA16816(acc[mi][2], ah[mi], bh[1] + 0);
            MMA16816(acc[mi][3], ah[mi], bh[1] + 2);
        }
        uint32_t al[4][4];
#pragma unroll
        for (int mi = 0; mi < 4; mi++) {
            int row = warpM + mi * 16 + aR;
            uint32_t off = (uint32_t)(row * 64 +
                (((ks * 2 + aSel) ^ ((row >> 1) & 3)) << 4));
            LDSM4(al[mi], stage + 8192u + off);
        }
#pragma unroll
        for (int mi = 0; mi < 4; mi++) {
            MMA16816(acc[mi][0], ah[mi], bl[0] + 0);
            MMA16816(acc[mi][1], ah[mi], bl[0] + 2);
            MMA16816(acc[mi][2], ah[mi], bl[1] + 0);
            MMA16816(acc[mi][3], ah[mi], bl[1] + 2);
        }
#pragma unroll
        for (int mi = 0; mi < 4; mi++) {
            MMA16816(acc[mi][0], al[mi], bh[0] + 0);
            MMA16816(acc[mi][1], al[mi], bh[0] + 2);
            MMA16816(acc[mi][2], al[mi], bh[1] + 0);
            MMA16816(acc[mi][3], al[mi], bh[1] + 2);
        }
    }
}

// 32x32 warp-tile variant for the 512-thread sprefix kernel
__device__ __forceinline__ void compute_tile32(
    float (&acc)[2][4][4], uint32_t stage, int warpM, int warpN, int lane)
{
    const int l7 = lane & 7;
    const int aSel = lane >> 4;
    const int bSel = (lane >> 3) & 1;
    const int aR = ((lane >> 3) & 1) * 8 + l7;
    const int bR = (lane >> 4) * 8 + l7;
#pragma unroll
    for (int ks = 0; ks < 2; ks++) {
        uint32_t ah[2][4], bh[2][4], bl[2][4];
#pragma unroll
        for (int mi = 0; mi < 2; mi++) {
            int row = warpM + mi * 16 + aR;
            uint32_t off = (uint32_t)(row * 64 +
                (((ks * 2 + aSel) ^ ((row >> 1) & 3)) << 4));
            LDSM4(ah[mi], stage + off);
        }
#pragma unroll
        for (int ni = 0; ni < 2; ni++) {
            int row = warpN + ni * 16 + bR;
            uint32_t off = (uint32_t)(row * 64 +
                (((ks * 2 + bSel) ^ ((row >> 1) & 3)) << 4));
            LDSM4(bh[ni], stage + 16384u + off);
            LDSM4(bl[ni], stage + 24576u + off);
        }
#pragma unroll
        for (int mi = 0; mi < 2; mi++) {
            MMA16816(acc[mi][0], ah[mi], bh[0] + 0);
            MMA16816(acc[mi][1], ah[mi], bh[0] + 2);
            MMA16816(acc[mi][2], ah[mi], bh[1] + 0);
            MMA16816(acc[mi][3], ah[mi], bh[1] + 2);
        }
        uint32_t al[2][4];
#pragma unroll
        for (int mi = 0; mi < 2; mi++) {
            int row = warpM + mi * 16 + aR;
            uint32_t off = (uint32_t)(row * 64 +
                (((ks * 2 + aSel) ^ ((row >> 1) & 3)) << 4));
            LDSM4(al[mi], stage + 8192u + off);
        }
#pragma unroll
        for (int mi = 0; mi < 2; mi++) {
            MMA16816(acc[mi][0], ah[mi], bl[0] + 0);
            MMA16816(acc[mi][1], ah[mi], bl[0] + 2);
            MMA16816(acc[mi][2], ah[mi], bl[1] + 0);
            MMA16816(acc[mi][3], ah[mi], bl[1] + 2);
        }
#pragma unroll
        for (int mi = 0; mi < 2; mi++) {
            MMA16816(acc[mi][0], al[mi], bh[0] + 0);
            MMA16816(acc[mi][1], al[mi], bh[0] + 2);
            MMA16816(acc[mi][2], al[mi], bh[1] + 0);
            MMA16816(acc[mi][3], al[mi], bh[1] + 2);
        }
    }
}

// ---------------- 3-stage ring GEMM core (accumulating) ---------------------
__device__ void gemm_core(const hf* A1, const hf* A2, size_t ldA,
                          const hf* B1, const hf* B2, size_t ldB,
                          int nK, uint32_t sb, float (&acc)[4][4][4])
{
    const int tid = threadIdx.x;
    const int lane = tid & 31, wid = tid >> 5;
    const int warpM = (wid & 1) * 64, warpN = (wid >> 1) * 32;
    ld_stage(sb, A1, A2, ldA, B1, B2, ldB, 0, tid);
    if (nK > 1) ld_stage(sb + STAGE_BYTES, A1, A2, ldA, B1, B2, ldB, 1, tid);
    for (int kc = 0; kc < nK; kc++) {
        if (kc + 1 < nK) asm volatile("cp.async.wait_group 1;" ::: "memory");
        else             asm volatile("cp.async.wait_group 0;" ::: "memory");
        __syncthreads();
        if (kc + 2 < nK)
            ld_stage(sb + ((kc + 2) % 3) * STAGE_BYTES,
                     A1, A2, ldA, B1, B2, ldB, kc + 2, tid);
        compute_tile(acc, sb + (kc % 3) * STAGE_BYTES, warpM, warpN, lane);
    }
    __syncthreads();
}

#define ACC_DECL()                                                             \
    float acc[4][4][4];                                                        \
    _Pragma("unroll") for (int _i = 0; _i < 4; _i++)                           \
        _Pragma("unroll") for (int _j = 0; _j < 4; _j++)                       \
            _Pragma("unroll") for (int _r = 0; _r < 4; _r++)                   \
                acc[_i][_j][_r] = 0.f;

#define EPI_SETUP()                                                            \
    const int lane = threadIdx.x & 31, wid = threadIdx.x >> 5;                 \
    const int warpM = (wid & 1) * 64, warpN = (wid >> 1) * 32;                 \
    const int er = warpM + (lane >> 2);                                        \
    const int ec = warpN + (lane & 3) * 2;

// ===========================================================================
// fused aux kernels
// ===========================================================================

__global__ __launch_bounds__(256) void prep_all(
    const float* __restrict__ x,
    const float* __restrict__ qw, const float* __restrict__ kw,
    const float* __restrict__ vw, const float* __restrict__ ow)
{
    const int tx = threadIdx.x, ty = threadIdx.y;
    if (blockIdx.z < 8) {
        __shared__ float tile[32][33];
        const int b = blockIdx.z, t0 = blockIdx.x * 32, e0 = blockIdx.y * 32;
#pragma unroll
        for (int j = 0; j < 4; j++) {
            int e = e0 + ty + j * 8;
            tile[tx][ty + j * 8] = x[((size_t)(b * EE + e)) * TT + t0 + tx];
        }
        __syncthreads();
#pragma unroll
        for (int j = 0; j < 4; j++) {
            int r = ty + j * 8;
            float v = tile[r][tx];
            size_t o = ((size_t)(b * TT + t0 + r)) * EE + e0 + tx;
            h2split(v, g_xT1[o], g_xT2[o]);
        }
        return;
    }
    const int tid = ty * 32 + tx;
    const int blk = blockIdx.y * 64 + blockIdx.x;   // 0..1023
#pragma unroll
    for (int j = 0; j < 4; j++) {
        int i = blk * 1024 + j * 256 + tid;
        int m = i >> 18;
        const float* src = (m == 0) ? qw : (m == 1) ? kw : (m == 2) ? vw : ow;
        float v = src[i & (EE * EE - 1)];
        h2split(v, g_W1[i], g_W2[i]);
    }
    if (blk < 256) g_ZS[blk * 256 + tid] = 0.f;
}

__global__ __launch_bounds__(256) void softmax_zscan()
{
    if (blockIdx.x < 2048) {
        int w = blockIdx.x * 8 + (threadIdx.x >> 5);
        int lane = threadIdx.x & 31;
        float* r = g_Q + (size_t)w * EE;
        float4 v[4];
#pragma unroll
        for (int j = 0; j < 4; j++) v[j] = *(float4*)&r[j * 128 + lane * 4];
        float m = -1e30f;
#pragma unroll
        for (int j = 0; j < 4; j++)
            m = fmaxf(m, fmaxf(fmaxf(v[j].x, v[j].y), fmaxf(v[j].z, v[j].w)));
#pragma unroll
        for (int o = 16; o > 0; o >>= 1)
            m = fmaxf(m, __shfl_xor_sync(0xffffffffu, m, o));
        float s = 0.f;
#pragma unroll
        for (int j = 0; j < 4; j++) {
            v[j].x = expf(v[j].x - m); v[j].y = expf(v[j].y - m);
            v[j].z = expf(v[j].z - m); v[j].w = expf(v[j].w - m);
            s += v[j].x + v[j].y + v[j].z + v[j].w;
        }
#pragma unroll
        for (int o = 16; o > 0; o >>= 1)
            s += __shfl_xor_sync(0xffffffffu, s, o);
        float sc = QSCALE / s;
#pragma unroll
        for (int j = 0; j < 4; j++) {
            float q0 = v[j].x * sc, q1 = v[j].y * sc;
            float q2 = v[j].z * sc, q3 = v[j].w * sc;
            int cc = j * 128 + lane * 4;
            *(float4*)&r[cc] = make_float4(q0, q1, q2, q3);
            hf h0, l0, h1, l1, h2, l2, h3, l3;
            h2split(q0 * QUP, h0, l0); h2split(q1 * QUP, h1, l1);
            h2split(q2 * QUP, h2, l2); h2split(q3 * QUP, h3, l3);
            size_t o = (size_t)w * EE + cc;
            *(__half2*)(g_Q1 + o)     = __halves2half2(h0, h1);
            *(__half2*)(g_Q1 + o + 2) = __halves2half2(h2, h3);
            *(__half2*)(g_Q2 + o)     = __halves2half2(l0, l1);
            *(__half2*)(g_Q2 + o + 2) = __halves2half2(l2, l3);
        }
        return;
    }
    int b = blockIdx.x - 2048;
#pragma unroll
    for (int half = 0; half < 2; half++) {
        int e = threadIdx.x + half * 256;
        float run = 0.f;
        for (int c = 0; c < NCH; c++) {
            size_t o = ((size_t)b * NCH + c) * EE + e;
            g_ZC[o] = run;
            run += g_ZS[o];
        }
    }
}

__global__ __launch_bounds__(256) void dinv_kernel()
{
    int w = blockIdx.x * 8 + (threadIdx.x >> 5);
    int lane = threadIdx.x & 31;
    int b = w >> 11, t = w & 2047, c = t >> 7;
    const float* q = g_Q + (size_t)w * EE;
    const float* z = g_ZC + ((size_t)b * NCH + c) * EE;
    float s = 0.f;
#pragma unroll
    for (int i = 0; i < 16; i++) s += q[lane + 32 * i] * z[lane + 32 * i];
#pragma unroll
    for (int o = 16; o > 0; o >>= 1) s += __shfl_xor_sync(0xffffffffu, s, o);
    if (lane == 0) g_DI[w] = 1.f / fmaxf(s + g_RS[w], EPS_D);
}

// ===========================================================================
// GEMM kernels
// ===========================================================================

// merged projections; fused epilogues (Q raw fp32 / K exp+splits+T+colsum /
// V *toep +T splits)
__global__ __launch_bounds__(256, 2) void proj_tc(
    const float* __restrict__ qb, const float* __restrict__ kb,
    const float* __restrict__ vb, const float* __restrict__ toep)
{
    extern __shared__ char smdyn[];
    uint32_t sb = sm_u32(smdyn) + 1024;
    const int mode = blockIdx.z >> 3, b = blockIdx.z & 7;
    const int t0 = blockIdx.x * 128, o0 = blockIdx.y * 128;
    ACC_DECL();
    const size_t aoff = ((size_t)(b * TT + t0)) * EE;
    const size_t woff = (size_t)mode * EE * EE + (size_t)o0 * EE;
    gemm_core(g_xT1 + aoff, g_xT2 + aoff, EE, g_W1 + woff, g_W2 + woff, EE,
              16, sb, acc);
    EPI_SETUP();
    const float* bias = (mode == 0) ? qb : (mode == 1) ? kb : vb;
    float* smf = (float*)(smdyn + 1024);          // [128 o][132] fp32 stage

    if (mode == 0) {
#pragma unroll
        for (int mi = 0; mi < 4; mi++)
#pragma unroll
            for (int h = 0; h < 2; h++) {
                int t = t0 + er + mi * 16 + h * 8;
                float* orow = g_Q + ((size_t)b * TT + t) * EE + o0;
#pragma unroll
                for (int nf = 0; nf < 4; nf++) {
                    int cc = ec + nf * 8;
                    *(float2*)&orow[cc] = make_float2(
                        acc[mi][nf][h * 2 + 0] + bias[o0 + cc],
                        acc[mi][nf][h * 2 + 1] + bias[o0 + cc + 1]);
                }
            }
        return;
    }

    float csum[4][2] = {{0.f,0.f},{0.f,0.f},{0.f,0.f},{0.f,0.f}};
#pragma unroll
    for (int mi = 0; mi < 4; mi++)
#pragma unroll
        for (int h = 0; h < 2; h++) {
            int m = er + mi * 16 + h * 8;
            int t = t0 + m;
            float tw = (mode == 2) ? toep[t] : 1.f;
            hf* K1r = g_K1 + ((size_t)b * TT + t) * EE + o0;
            hf* K2r = g_K2 + ((size_t)b * TT + t) * EE + o0;
#pragma unroll
            for (int nf = 0; nf < 4; nf++) {
                int cc = ec + nf * 8;
                float v0 = acc[mi][nf][h * 2 + 0] + bias[o0 + cc];
                float v1 = acc[mi][nf][h * 2 + 1] + bias[o0 + cc + 1];
                if (mode == 1) {
                    v0 = expf(v0); v1 = expf(v1);
                    csum[nf][0] += v0; csum[nf][1] += v1;
                    hf h0, l0, h1, l1;
                    h2split(v0, h0, l0);
                    h2split(v1, h1, l1);
                    *(__half2*)(K1r + cc) = __halves2half2(h0, h1);
                    *(__half2*)(K2r + cc) = __halves2half2(l0, l1);
                } else {
                    v0 *= tw; v1 *= tw;
                }
                smf[cc * 132 + m] = v0;
                smf[(cc + 1) * 132 + m] = v1;
            }
        }
    if (mode == 1) {
        const int chunk = t0 >> 7;
        float* zrow = g_ZS + ((size_t)b * NCH + chunk) * EE + o0;
#pragma unroll
        for (int nf = 0; nf < 4; nf++) {
            atomicAdd(&zrow[ec + nf * 8],     csum[nf][0]);
            atomicAdd(&zrow[ec + nf * 8 + 1], csum[nf][1]);
        }
    }
    __syncthreads();
    hf* T1 = (mode == 1) ? g_KT1 : g_VT1;
    hf* T2 = (mode == 1) ? g_KT2 : g_VT2;
#pragma unroll
    for (int i = 0; i < 16; i++) {
        int e = wid * 16 + i;
        float4 vv = *(float4*)&smf[e * 132 + 4 * lane];
        hf h0, l0, h1, l1, h2, l2, h3, l3;
        h2split(vv.x, h0, l0); h2split(vv.y, h1, l1);
        h2split(vv.z, h2, l2); h2split(vv.w, h3, l3);
        size_t o = ((size_t)(b * EE + o0 + e)) * TT + t0 + 4 * lane;
        *(__half2*)(T1 + o)     = __halves2half2(h0, h1);
        *(__half2*)(T1 + o + 2) = __halves2half2(h2, h3);
        *(__half2*)(T2 + o)     = __halves2half2(l0, l1);
        *(__half2*)(T2 + o + 2) = __halves2half2(l2, l3);
    }
}

// ---------------------------------------------------------------------------
// S-prefix: 128 CTAs, 512 threads, 1 CTA/SM (197KB smem), 6-stage ring,
// continuous 60-k-tile stream (chunks 0..14 are t-contiguous in VT/KT).
// acc holds the running S tile; exclusive prefix written at chunk boundaries.
// ---------------------------------------------------------------------------
__global__ __launch_bounds__(512, 1) void sprefix_tc()
{
    extern __shared__ char smdyn[];
    uint32_t sb = sm_u32(smdyn) + 1024;
    const int bid = blockIdx.x;            // 0..127
    const int b = bid >> 4, tile = bid & 15;
    const int fi = tile & 3, ei = tile >> 2;
    const int tid = threadIdx.x;
    const int lane = tid & 31, wid = tid >> 5;
    const int warpM = (wid & 3) * 32, warpN = (wid >> 2) * 32;
    const int er = warpM + (lane >> 2);
    const int ec = warpN + (lane & 3) * 2;

    float acc[2][4][4];
#pragma unroll
    for (int i = 0; i < 2; i++)
#pragma unroll
        for (int j = 0; j < 4; j++)
#pragma unroll
            for (int r = 0; r < 4; r++) acc[i][j][r] = 0.f;

    const hf* A1 = g_VT1 + ((size_t)(b * EE + fi * 128)) * TT;
    const hf* A2 = g_VT2 + ((size_t)(b * EE + fi * 128)) * TT;
    const hf* B1 = g_KT1 + ((size_t)(b * EE + ei * 128)) * TT;
    const hf* B2 = g_KT2 + ((size_t)(b * EE + ei * 128)) * TT;

    const int KT = 60;                     // 15 chunks x 4 k-tiles
#pragma unroll
    for (int i = 0; i < 5; i++)
        ld_stage512(sb + i * STAGE_BYTES, A1, A2, B1, B2, i, tid);

    for (int kt = 0; kt < KT; kt++) {
        asm volatile("cp.async.wait_group 4;" ::: "memory");
        __syncthreads();
        if (kt + 5 < KT)
            ld_stage512(sb + ((kt + 5) % 6) * STAGE_BYTES, A1, A2, B1, B2,
                        kt + 5, tid);
        else
            asm volatile("cp.async.commit_group;" ::: "memory");
        compute_tile32(acc, sb + (kt % 6) * STAGE_BYTES, warpM, warpN, lane);
        if ((kt & 3) == 3) {
            // acc = sum of chunks 0..(kt>>2) -> exclusive prefix for chunk+1
            const int cn = (kt >> 2) + 1;
            hf* C1 = g_SC1 + ((size_t)(b * NCH + cn) * EE) * EE;
            hf* C2 = g_SC2 + ((size_t)(b * NCH + cn) * EE) * EE;
#pragma unroll
            for (int mi = 0; mi < 2; mi++)
#pragma unroll
                for (int h = 0; h < 2; h++) {
                    int m = fi * 128 + er + mi * 16 + h * 8;
                    size_t rofs = (size_t)m * EE + ei * 128;
#pragma unroll
                    for (int nf = 0; nf < 4; nf++) {
                        int cc = ec + nf * 8;
                        hf h0, l0, h1, l1;
                        h2split(acc[mi][nf][h * 2 + 0], h0, l0);
                        h2split(acc[mi][nf][h * 2 + 1], h1, l1);
                        *(__half2*)(C1 + rofs + cc) = __halves2half2(h0, h1);
                        *(__half2*)(C2 + rofs + cc) = __halves2half2(l0, l1);
                    }
                }
        }
    }
}

// P' = mask(Q' K^T): fp16 splits + true rowsums
__global__ __launch_bounds__(256, 2) void p_tc()
{
    extern __shared__ char smdyn[];
    uint32_t sb = sm_u32(smdyn) + 1024;
    float* srs = (float*)smdyn;
    const int c = blockIdx.x, b = blockIdx.y;
    const int tid = threadIdx.x;
    if (tid < CC) srs[tid] = 0.f;
    ACC_DECL();
    const size_t off = ((size_t)(b * TT + c * CC)) * EE;
    gemm_core(g_Q1 + off, g_Q2 + off, EE, g_K1 + off, g_K2 + off, EE,
              16, sb, acc);
    EPI_SETUP();
    hf* P1 = g_P1 + (size_t)(b * NCH + c) * CC * CC;
    hf* P2 = g_P2 + (size_t)(b * NCH + c) * CC * CC;
#pragma unroll
    for (int mi = 0; mi < 4; mi++)
#pragma unroll
        for (int h = 0; h < 2; h++) {
            int m = er + mi * 16 + h * 8;
            float rsum = 0.f;
#pragma unroll
            for (int nf = 0; nf < 4; nf++) {
                int cc = ec + nf * 8;
                float v0 = (cc     <= m) ? acc[mi][nf][h * 2 + 0] : 0.f;
                float v1 = (cc + 1 <= m) ? acc[mi][nf][h * 2 + 1] : 0.f;
                rsum += v0 + v1;
                hf h0, l0, h1, l1;
                h2split(v0, h0, l0);
                h2split(v1, h1, l1);
                *(__half2*)(P1 + (size_t)m * CC + cc) = __halves2half2(h0, h1);
                *(__half2*)(P2 + (size_t)m * CC + cc) = __halves2half2(l0, l1);
            }
            atomicAdd(&srs[m], rsum);
        }
    __syncthreads();
    if (tid < CC) g_RS[(size_t)b * TT + (size_t)c * CC + tid] = srs[tid] * QDN;
}

// O = (Q'@S_prev + P'@V) * dinv/1024 -> attn fp16 splits
__global__ __launch_bounds__(256, 2) void qspv_tc()
{
    extern __shared__ char smdyn[];
    uint32_t sb = sm_u32(smdyn) + 1024;
    const int n0 = blockIdx.x * 128, c = blockIdx.y, b = blockIdx.z;
    ACC_DECL();
    const size_t qoff = ((size_t)(b * TT + c * CC)) * EE;
    if (c > 0) {
        const size_t soff = ((size_t)(b * NCH + c) * EE + n0) * EE;
        gemm_core(g_Q1 + qoff, g_Q2 + qoff, EE, g_SC1 + soff, g_SC2 + soff, EE,
                  16, sb, acc);
    }
    const size_t poff = (size_t)(b * NCH + c) * CC * CC;
    const size_t voff = ((size_t)(b * EE + n0)) * TT + (size_t)c * CC;
    gemm_core(g_P1 + poff, g_P2 + poff, CC, g_VT1 + voff, g_VT2 + voff, TT,
              4, sb, acc);
    EPI_SETUP();
#pragma unroll
    for (int mi = 0; mi < 4; mi++)
#pragma unroll
        for (int h = 0; h < 2; h++) {
            int m = er + mi * 16 + h * 8;
            size_t row = (size_t)b * TT + (size_t)c * CC + m;
            float di = g_DI[row] * QDN;
            hf* A1 = g_A1 + row * EE + n0;
            hf* A2 = g_A2 + row * EE + n0;
#pragma unroll
            for (int nf = 0; nf < 4; nf++) {
                int cc = ec + nf * 8;
                float v0 = acc[mi][nf][h * 2 + 0] * di;
                float v1 = acc[mi][nf][h * 2 + 1] * di;
                hf h0, l0, h1, l1;
                h2split(v0, h0, l0);
                h2split(v1, h1, l1);
                *(__half2*)(A1 + cc) = __halves2half2(h0, h1);
                *(__half2*)(A2 + cc) = __halves2half2(l0, l1);
            }
        }
}

// out = A @ o_w^T + o_b (fp32)
__global__ __launch_bounds__(256, 2) void out_tc(
    const float* __restrict__ ob, float* __restrict__ out)
{
    extern __shared__ char smdyn[];
    uint32_t sb = sm_u32(smdyn) + 1024;
    const int b = blockIdx.z, t0 = blockIdx.x * 128, o0 = blockIdx.y * 128;
    ACC_DECL();
    const size_t aoff = ((size_t)(b * TT + t0)) * EE;
    const size_t woff = (size_t)3 * EE * EE + (size_t)o0 * EE;
    gemm_core(g_A1 + aoff, g_A2 + aoff, EE, g_W1 + woff, g_W2 + woff, EE,
              16, sb, acc);
    EPI_SETUP();
#pragma unroll
    for (int mi = 0; mi < 4; mi++)
#pragma unroll
        for (int h = 0; h < 2; h++) {
            int t = t0 + er + mi * 16 + h * 8;
            float* orow = out + ((size_t)b * TT + t) * EE + o0;
#pragma unroll
            for (int nf = 0; nf < 4; nf++) {
                int cc = ec + nf * 8;
                *(float2*)&orow[cc] = make_float2(
                    acc[mi][nf][h * 2 + 0] + ob[o0 + cc],
                    acc[mi][nf][h * 2 + 1] + ob[o0 + cc + 1]);
            }
        }
}

// ===========================================================================
extern "C" void kernel_launch(void* const* d_in, const int* in_sizes, int n_in,
                              void* d_out, int out_size)
{
    (void)in_sizes; (void)n_in; (void)out_size;
    const float* x    = (const float*)d_in[0];
    const float* toep = (const float*)d_in[1];
    const float* q_w  = (const float*)d_in[2];
    const float* q_b  = (const float*)d_in[3];
    const float* k_w  = (const float*)d_in[4];
    const float* k_b  = (const float*)d_in[5];
    const float* v_w  = (const float*)d_in[6];
    const float* v_b  = (const float*)d_in[7];
    const float* o_w  = (const float*)d_in[8];
    const float* o_b  = (const float*)d_in[9];
    float* out = (float*)d_out;

    cudaFuncSetAttribute(proj_tc,    cudaFuncAttributeMaxDynamicSharedMemorySize, SMEM_BYTES);
    cudaFuncSetAttribute(sprefix_tc, cudaFuncAttributeMaxDynamicSharedMemorySize, SPF_SMEM);
    cudaFuncSetAttribute(p_tc,       cudaFuncAttributeMaxDynamicSharedMemorySize, SMEM_BYTES);
    cudaFuncSetAttribute(qspv_tc,    cudaFuncAttributeMaxDynamicSharedMemorySize, SMEM_BYTES);
    cudaFuncSetAttribute(out_tc,     cudaFuncAttributeMaxDynamicSharedMemorySize, SMEM_BYTES);

    prep_all<<<dim3(64, 16, 9), dim3(32, 8)>>>(x, q_w, k_w, v_w, o_w);
    proj_tc<<<dim3(TT / 128, EE / 128, 3 * BB), 256, SMEM_BYTES>>>(q_b, k_b, v_b, toep);
    sprefix_tc<<<128, 512, SPF_SMEM>>>();
    softmax_zscan<<<2048 + BB, 256>>>();
    p_tc<<<dim3(NCH, BB), 256, SMEM_BYTES>>>();
    dinv_kernel<<<NT / 8, 256>>>();
    qspv_tc<<<dim3(EE / 128, NCH, BB), 256, SMEM_BYTES>>>();
    out_tc<<<dim3(TT / 128, EE / 128, BB), 256, SMEM_BYTES>>>(o_b, out);
}